// round 4
// baseline (speedup 1.0000x reference)
#include <cuda_runtime.h>
#include <math.h>
#include <float.h>
#include <stdint.h>

// ---------------- problem constants ----------------
#define CB   4
#define CT   16
#define CS   256
#define CN   4096
#define CC   1152
#define CNH  16
#define CHD  72
#define CYL  120
#define NROW 16384
#define CC2  (CC * CC)

// ---------------- scratch (device globals) ----------------
__device__ float g_t6[CB * 6 * CC];
__device__ float g_xm[(size_t)NROW * CC];
__device__ float g_qkv[(size_t)NROW * 3 * CC];
__device__ float g_att[(size_t)NROW * CC];
__device__ float g_h[(size_t)NROW * 4 * CC];
__device__ float g_sc[67108864UL];
__device__ float g_kv[CB * CYL * 2 * CC];
__device__ float g_w[20 * CC2];                 // tf32-rounded weights
__device__ float g_yr[CB * CYL * CC];           // tf32-rounded y

// ---------------- helpers ----------------
__device__ __forceinline__ float gelu_tanh(float x) {
    float x3 = x * x * x;
    return 0.5f * x * (1.f + tanhf(0.7978845608028654f * (x + 0.044715f * x3)));
}
__device__ __forceinline__ uint32_t f2tf(float f) {
    uint32_t u;
    asm("cvt.rna.tf32.f32 %0, %1;" : "=r"(u) : "f"(f));
    return u;
}
__device__ __forceinline__ float rndtf(float f) { return __uint_as_float(f2tf(f)); }

__device__ __forceinline__ void cp_async16(void* smem, const void* gmem) {
    uint32_t s = (uint32_t)__cvta_generic_to_shared(smem);
    asm volatile("cp.async.cg.shared.global [%0], [%1], 16;\n" :: "r"(s), "l"(gmem));
}
__device__ __forceinline__ void cp_async16z(void* smem, const void* gmem, int sz) {
    uint32_t s = (uint32_t)__cvta_generic_to_shared(smem);
    asm volatile("cp.async.cg.shared.global [%0], [%1], 16, %2;\n" :: "r"(s), "l"(gmem), "r"(sz));
}
__device__ __forceinline__ void cp_commit() { asm volatile("cp.async.commit_group;\n"); }
template <int Nk>
__device__ __forceinline__ void cp_wait() { asm volatile("cp.async.wait_group %0;\n" :: "n"(Nk)); }

#define MMA_TF32(acc, af, bf)                                                     \
    asm volatile(                                                                 \
        "mma.sync.aligned.m16n8k8.row.col.f32.tf32.tf32.f32 "                     \
        "{%0,%1,%2,%3}, {%4,%5,%6,%7}, {%8,%9}, {%0,%1,%2,%3};\n"                 \
        : "+f"(acc[0]), "+f"(acc[1]), "+f"(acc[2]), "+f"(acc[3])                  \
        : "r"(af[0]), "r"(af[1]), "r"(af[2]), "r"(af[3]), "r"(bf[0]), "r"(bf[1]))

// ---------------- elementwise round ----------------
__global__ void k_round(const float* __restrict__ a, float* __restrict__ o, int n) {
    int i = blockIdx.x * blockDim.x + threadIdx.x;
    if (i < n) o[i] = rndtf(a[i]);
}

// ---------------- modulation ----------------
__global__ void k_mod(const float* __restrict__ t, const float* __restrict__ sst,
                      float* __restrict__ t6) {
    int i = blockIdx.x * blockDim.x + threadIdx.x;
    if (i < CB * 6 * CC) t6[i] = sst[i % (6 * CC)] + t[i];
}

// ---------------- LayerNorm + modulate (tf32-rounded output) ----------------
__global__ void k_ln_mod(const float* __restrict__ X, const float* __restrict__ t6,
                         float* __restrict__ out, int shiftIdx, int scaleIdx) {
    int r = blockIdx.x;
    int b = r >> 12;
    const float* xr = X + (size_t)r * CC;
    const float* sh = t6 + (size_t)(b * 6 + shiftIdx) * CC;
    const float* scl = t6 + (size_t)(b * 6 + scaleIdx) * CC;

    float v[4];
    float s = 0.f, sq = 0.f;
#pragma unroll
    for (int i = 0; i < 4; i++) {
        int c = threadIdx.x + i * 288;
        v[i] = xr[c];
        s += v[i];
        sq += v[i] * v[i];
    }
    __shared__ float s1[9], s2[9], bc[2];
    int lane = threadIdx.x & 31, wid = threadIdx.x >> 5;
#pragma unroll
    for (int off = 16; off > 0; off >>= 1) {
        s += __shfl_xor_sync(0xffffffffu, s, off);
        sq += __shfl_xor_sync(0xffffffffu, sq, off);
    }
    if (lane == 0) { s1[wid] = s; s2[wid] = sq; }
    __syncthreads();
    if (threadIdx.x == 0) {
        float ts = 0.f, tq = 0.f;
        for (int w = 0; w < 9; w++) { ts += s1[w]; tq += s2[w]; }
        float mean = ts * (1.f / CC);
        float var = tq * (1.f / CC) - mean * mean;
        bc[0] = mean;
        bc[1] = rsqrtf(var + 1e-6f);
    }
    __syncthreads();
    float mean = bc[0], rstd = bc[1];
    float* orow = out + (size_t)r * CC;
#pragma unroll
    for (int i = 0; i < 4; i++) {
        int c = threadIdx.x + i * 288;
        orow[c] = rndtf((v[i] - mean) * rstd * (1.f + scl[c]) + sh[c]);
    }
}

#define TBK 16
#define ASTR 20

// ---------------- big TF32 GEMM: 256x128 tile, 3-stage, 64x64 warp tiles ------
// OP: 0 = plain store, 1 = round store, 2 = gelu+round store,
//     3 = residual: Cmat[r][c] += gate[c] * (acc + bias[c])   (gate=1 if gi<0)
#define TBM2 256
#define TBN2 128
#define ASZ2 (TBM2 * ASTR)
#define BSZ2 (TBN2 * ASTR)

template <int OP>
__global__ __launch_bounds__(256, 1) void k_tgemm2(const float* __restrict__ A,
                                                   const float* __restrict__ W,
                                                   const float* __restrict__ bias,
                                                   float* __restrict__ Cmat,
                                                   int M, int Nn, int K,
                                                   const float* __restrict__ t6, int gi) {
    extern __shared__ float sm[];
    float* As = sm;                 // 3 stages of 256x20
    float* Bs = sm + 3 * ASZ2;      // 3 stages of 128x20

    const int tid = threadIdx.x;
    const int m0 = blockIdx.y * TBM2, n0 = blockIdx.x * TBN2;
    const int wid = tid >> 5, lane = tid & 31;
    const int wr = wid & 3, wc = wid >> 2;       // 4 x 2 warps
    const int warp_m = wr * 64, warp_n = wc * 64;
    const int qr = lane >> 2, qc = lane & 3;

    float acc[4][8][4];
#pragma unroll
    for (int mi = 0; mi < 4; mi++)
#pragma unroll
        for (int ni = 0; ni < 8; ni++)
#pragma unroll
            for (int c = 0; c < 4; c++) acc[mi][ni][c] = 0.f;

    auto load_tile = [&](int stg, int kbase) {
        float* as = As + stg * ASZ2;
        float* bs = Bs + stg * BSZ2;
#pragma unroll
        for (int i = 0; i < 4; i++) {
            int ch = tid + i * 256;
            int m = ch >> 2;
            int k4 = (ch & 3) * 4;
            cp_async16(&as[m * ASTR + k4], A + (size_t)(m0 + m) * K + kbase + k4);
        }
#pragma unroll
        for (int i = 0; i < 2; i++) {
            int ch = tid + i * 256;
            int m = ch >> 2;
            int k4 = (ch & 3) * 4;
            cp_async16(&bs[m * ASTR + k4], W + (size_t)(n0 + m) * K + kbase + k4);
        }
    };

    const int KT = K >> 4;
    load_tile(0, 0);
    cp_commit();
    load_tile(1, TBK);
    cp_commit();

    for (int kt = 0; kt < KT; ++kt) {
        cp_wait<1>();
        __syncthreads();
        int cur = kt % 3;
        if (kt + 2 < KT) load_tile((kt + 2) % 3, (kt + 2) << 4);
        cp_commit();   // empty group at tail keeps the count uniform

        const float* as = As + cur * ASZ2;
        const float* bs = Bs + cur * BSZ2;
#pragma unroll
        for (int kk = 0; kk < TBK; kk += 8) {
            uint32_t af[4][4], bf[8][2];
#pragma unroll
            for (int mi = 0; mi < 4; mi++) {
                const float* base = &as[(warp_m + mi * 16 + qr) * ASTR + kk + qc];
                af[mi][0] = __float_as_uint(base[0]);
                af[mi][1] = __float_as_uint(base[8 * ASTR]);
                af[mi][2] = __float_as_uint(base[4]);
                af[mi][3] = __float_as_uint(base[8 * ASTR + 4]);
            }
#pragma unroll
            for (int ni = 0; ni < 8; ni++) {
                const float* base = &bs[(warp_n + ni * 8 + qr) * ASTR + kk + qc];
                bf[ni][0] = __float_as_uint(base[0]);
                bf[ni][1] = __float_as_uint(base[4]);
            }
#pragma unroll
            for (int mi = 0; mi < 4; mi++)
#pragma unroll
                for (int ni = 0; ni < 8; ni++) MMA_TF32(acc[mi][ni], af[mi], bf[ni]);
        }
        __syncthreads();
    }

    const int b = m0 >> 12;  // batch (M rows are batch-major, 4096/batch)
    const float* gate = (OP == 3 && gi >= 0) ? t6 + (size_t)(b * 6 + gi) * CC : nullptr;

#pragma unroll
    for (int mi = 0; mi < 4; mi++) {
        int r0 = m0 + warp_m + mi * 16 + qr;
        int r1 = r0 + 8;
#pragma unroll
        for (int ni = 0; ni < 8; ni++) {
            int c0 = n0 + warp_n + ni * 8 + qc * 2;
            float b0 = bias[c0], b1 = bias[c0 + 1];
            float v[4] = {acc[mi][ni][0] + b0, acc[mi][ni][1] + b1,
                          acc[mi][ni][2] + b0, acc[mi][ni][3] + b1};
            if (OP == 2) {
#pragma unroll
                for (int c = 0; c < 4; c++) v[c] = gelu_tanh(v[c]);
            }
            if (OP == 1 || OP == 2) {
#pragma unroll
                for (int c = 0; c < 4; c++) v[c] = rndtf(v[c]);
            }
            if (OP == 3) {
                float g0 = gate ? gate[c0] : 1.f;
                float g1 = gate ? gate[c0 + 1] : 1.f;
                float* row0 = Cmat + (size_t)r0 * Nn;
                float* row1 = Cmat + (size_t)r1 * Nn;
                row0[c0] += g0 * v[0];
                row0[c0 + 1] += g1 * v[1];
                row1[c0] += g0 * v[2];
                row1[c0 + 1] += g1 * v[3];
            } else {
                Cmat[(size_t)r0 * Nn + c0] = v[0];
                Cmat[(size_t)r0 * Nn + c0 + 1] = v[1];
                Cmat[(size_t)r1 * Nn + c0] = v[2];
                Cmat[(size_t)r1 * Nn + c0 + 1] = v[3];
            }
        }
    }
}

// ---------------- small TF32 GEMM (kv_c only): 128x128, 2-stage ----------------
#define TBM 128
#define TBN 128

template <int OP>
__global__ __launch_bounds__(256) void k_tgemm(const float* __restrict__ A,
                                               const float* __restrict__ W,
                                               const float* __restrict__ bias,
                                               float* __restrict__ Cmat,
                                               int M, int Nn, int K) {
    __shared__ float As[2][TBM * ASTR];
    __shared__ float Bs[2][TBN * ASTR];

    const int tid = threadIdx.x;
    const int m0 = blockIdx.y * TBM, n0 = blockIdx.x * TBN;
    const int wid = tid >> 5, lane = tid & 31;
    const int wr = wid >> 2, wc = wid & 3;
    const int warp_m = wr * 64, warp_n = wc * 32;
    const int qr = lane >> 2, qc = lane & 3;

    float acc[4][4][4];
#pragma unroll
    for (int mi = 0; mi < 4; mi++)
#pragma unroll
        for (int ni = 0; ni < 4; ni++)
#pragma unroll
            for (int c = 0; c < 4; c++) acc[mi][ni][c] = 0.f;

    auto load_tile = [&](int stg, int kbase) {
#pragma unroll
        for (int i = 0; i < 2; i++) {
            int ch = tid + i * 256;
            int m = ch >> 2;
            int k4 = (ch & 3) * 4;
            int gm = m0 + m; if (gm >= M) gm = M - 1;
            cp_async16(&As[stg][m * ASTR + k4], A + (size_t)gm * K + kbase + k4);
            cp_async16(&Bs[stg][m * ASTR + k4], W + (size_t)(n0 + m) * K + kbase + k4);
        }
    };

    const int KT = K >> 4;
    load_tile(0, 0);
    cp_commit();

    for (int kt = 0; kt < KT; ++kt) {
        int cur = kt & 1;
        if (kt + 1 < KT) {
            load_tile(1 - cur, (kt + 1) << 4);
            cp_commit();
            cp_wait<1>();
        } else {
            cp_wait<0>();
        }
        __syncthreads();

#pragma unroll
        for (int kk = 0; kk < TBK; kk += 8) {
            uint32_t af[4][4], bf[4][2];
#pragma unroll
            for (int mi = 0; mi < 4; mi++) {
                const float* base = &As[cur][(warp_m + mi * 16 + qr) * ASTR + kk + qc];
                af[mi][0] = __float_as_uint(base[0]);
                af[mi][1] = __float_as_uint(base[8 * ASTR]);
                af[mi][2] = __float_as_uint(base[4]);
                af[mi][3] = __float_as_uint(base[8 * ASTR + 4]);
            }
#pragma unroll
            for (int ni = 0; ni < 4; ni++) {
                const float* base = &Bs[cur][(warp_n + ni * 8 + qr) * ASTR + kk + qc];
                bf[ni][0] = __float_as_uint(base[0]);
                bf[ni][1] = __float_as_uint(base[4]);
            }
#pragma unroll
            for (int mi = 0; mi < 4; mi++)
#pragma unroll
                for (int ni = 0; ni < 4; ni++) MMA_TF32(acc[mi][ni], af[mi], bf[ni]);
        }
        __syncthreads();
    }

#pragma unroll
    for (int mi = 0; mi < 4; mi++) {
        int r0 = m0 + warp_m + mi * 16 + qr;
        int r1 = r0 + 8;
#pragma unroll
        for (int ni = 0; ni < 4; ni++) {
            int c0 = n0 + warp_n + ni * 8 + qc * 2;
            float b0 = bias[c0], b1 = bias[c0 + 1];
            float v[4] = {acc[mi][ni][0] + b0, acc[mi][ni][1] + b1,
                          acc[mi][ni][2] + b0, acc[mi][ni][3] + b1};
            if (OP >= 1) {
#pragma unroll
                for (int c = 0; c < 4; c++) v[c] = rndtf(v[c]);
            }
            if (r0 < M) {
                Cmat[(size_t)r0 * Nn + c0] = v[0];
                Cmat[(size_t)r0 * Nn + c0 + 1] = v[1];
            }
            if (r1 < M) {
                Cmat[(size_t)r1 * Nn + c0] = v[2];
                Cmat[(size_t)r1 * Nn + c0 + 1] = v[3];
            }
        }
    }
}

// ---------------- MMA scores: out[z,i,j] = scale * Q_i . K_j  (d = 72) -------
__global__ __launch_bounds__(256) void k_scores_mma(const float* __restrict__ Q,
                                                    const float* __restrict__ Kd,
                                                    float* __restrict__ out,
                                                    int heads, int Sq, int Sk,
                                                    int qRS, int kRS, long qBS, long kBS,
                                                    float scale) {
    __shared__ float As[2][TBM * ASTR];
    __shared__ float Bs[2][TBN * ASTR];

    const int tid = threadIdx.x;
    int z = blockIdx.z;
    int b = z / heads, h = z - b * heads;
    const float* qb = Q + (long)b * qBS + h * CHD;
    const float* kb = Kd + (long)b * kBS + h * CHD;
    const int i0 = blockIdx.y * TBM, j0 = blockIdx.x * TBN;
    const int wid = tid >> 5, lane = tid & 31;
    const int wr = wid >> 2, wc = wid & 3;
    const int warp_m = wr * 64, warp_n = wc * 32;
    const int qr = lane >> 2, qc = lane & 3;

    float acc[4][4][4];
#pragma unroll
    for (int mi = 0; mi < 4; mi++)
#pragma unroll
        for (int ni = 0; ni < 4; ni++)
#pragma unroll
            for (int c = 0; c < 4; c++) acc[mi][ni][c] = 0.f;

    auto load_tile = [&](int stg, int kbase) {
#pragma unroll
        for (int i = 0; i < 2; i++) {
            int ch = tid + i * 256;
            int m = ch >> 2;
            int k4 = (ch & 3) * 4;
            int sz = (kbase + k4 + 4 <= CHD) ? 16 : 0;
            int gq = i0 + m; if (gq >= Sq) gq = Sq - 1;
            int gk = j0 + m; if (gk >= Sk) gk = Sk - 1;
            cp_async16z(&As[stg][m * ASTR + k4], qb + (long)gq * qRS + kbase + k4, sz);
            cp_async16z(&Bs[stg][m * ASTR + k4], kb + (long)gk * kRS + kbase + k4, sz);
        }
    };

    const int KT = 5;
    load_tile(0, 0);
    cp_commit();

    for (int kt = 0; kt < KT; ++kt) {
        int cur = kt & 1;
        if (kt + 1 < KT) {
            load_tile(1 - cur, (kt + 1) << 4);
            cp_commit();
            cp_wait<1>();
        } else {
            cp_wait<0>();
        }
        __syncthreads();

#pragma unroll
        for (int kk = 0; kk < TBK; kk += 8) {
            uint32_t af[4][4], bf[4][2];
#pragma unroll
            for (int mi = 0; mi < 4; mi++) {
                const float* base = &As[cur][(warp_m + mi * 16 + qr) * ASTR + kk + qc];
                af[mi][0] = __float_as_uint(base[0]);
                af[mi][1] = __float_as_uint(base[8 * ASTR]);
                af[mi][2] = __float_as_uint(base[4]);
                af[mi][3] = __float_as_uint(base[8 * ASTR + 4]);
            }
#pragma unroll
            for (int ni = 0; ni < 4; ni++) {
                const float* base = &Bs[cur][(warp_n + ni * 8 + qr) * ASTR + kk + qc];
                bf[ni][0] = __float_as_uint(base[0]);
                bf[ni][1] = __float_as_uint(base[4]);
            }
#pragma unroll
            for (int mi = 0; mi < 4; mi++)
#pragma unroll
                for (int ni = 0; ni < 4; ni++) MMA_TF32(acc[mi][ni], af[mi], bf[ni]);
        }
        __syncthreads();
    }

    float* ob = out + (long)z * Sq * Sk;
#pragma unroll
    for (int mi = 0; mi < 4; mi++) {
        int r0 = i0 + warp_m + mi * 16 + qr;
        int r1 = r0 + 8;
#pragma unroll
        for (int ni = 0; ni < 4; ni++) {
            int c0 = j0 + warp_n + ni * 8 + qc * 2;
            if (c0 < Sk) {
                if (r0 < Sq) ob[(long)r0 * Sk + c0] = acc[mi][ni][0] * scale;
                if (r1 < Sq) ob[(long)r1 * Sk + c0] = acc[mi][ni][2] * scale;
            }
            if (c0 + 1 < Sk) {
                if (r0 < Sq) ob[(long)r0 * Sk + c0 + 1] = acc[mi][ni][1] * scale;
                if (r1 < Sq) ob[(long)r1 * Sk + c0 + 1] = acc[mi][ni][3] * scale;
            }
        }
    }
}

// ---------------- MMA attn@V: O[z,i,d] = sum_j P[z,i,j] V[z,j,d]  (d = 72) ----
#define VSTR 72
__global__ __launch_bounds__(256) void k_av_mma(const float* __restrict__ P,
                                                const float* __restrict__ V,
                                                float* __restrict__ O,
                                                int heads, int Sq, int Sk,
                                                int vRS, long vBS, int oRS, long oBS) {
    __shared__ float As[2][TBM * ASTR];
    __shared__ float Bs[2][16 * VSTR];

    const int tid = threadIdx.x;
    int z = blockIdx.y;
    int b = z / heads, h = z - b * heads;
    const float* Pb = P + (long)z * Sq * Sk;
    const float* Vb = V + (long)b * vBS + h * CHD;
    float* Ob = O + (long)b * oBS + h * CHD;
    const int i0 = blockIdx.x * TBM;
    const int wid = tid >> 5, lane = tid & 31;
    const int warp_m = wid * 16;
    const int qr = lane >> 2, qc = lane & 3;

    float acc[9][4];
#pragma unroll
    for (int nt = 0; nt < 9; nt++)
#pragma unroll
        for (int c = 0; c < 4; c++) acc[nt][c] = 0.f;

    auto load_tile = [&](int stg, int kb) {
#pragma unroll
        for (int i = 0; i < 2; i++) {
            int ch = tid + i * 256;
            int m = ch >> 2;
            int k4 = (ch & 3) * 4;
            int sz = (kb + k4 + 4 <= Sk) ? 16 : 0;
            int gi = i0 + m; if (gi >= Sq) gi = Sq - 1;
            cp_async16z(&As[stg][m * ASTR + k4], Pb + (long)gi * Sk + kb + k4, sz);
        }
#pragma unroll
        for (int i = 0; i < 2; i++) {
            int ch = tid + i * 256;
            if (ch < 288) {
                int r = ch / 18;
                int c4 = (ch - r * 18) * 4;
                int sz = (kb + r < Sk) ? 16 : 0;
                cp_async16z(&Bs[stg][r * VSTR + c4], Vb + (long)(kb + r) * vRS + c4, sz);
            }
        }
    };

    const int KT = (Sk + 15) >> 4;
    load_tile(0, 0);
    cp_commit();

    for (int kt = 0; kt < KT; ++kt) {
        int cur = kt & 1;
        if (kt + 1 < KT) {
            load_tile(1 - cur, (kt + 1) << 4);
            cp_commit();
            cp_wait<1>();
        } else {
            cp_wait<0>();
        }
        __syncthreads();

#pragma unroll
        for (int kk = 0; kk < 16; kk += 8) {
            uint32_t af[4];
            const float* abase = &As[cur][(warp_m + qr) * ASTR + kk + qc];
            af[0] = __float_as_uint(abase[0]);
            af[1] = __float_as_uint(abase[8 * ASTR]);
            af[2] = __float_as_uint(abase[4]);
            af[3] = __float_as_uint(abase[8 * ASTR + 4]);
#pragma unroll
            for (int nt = 0; nt < 9; nt++) {
                uint32_t bf[2];
                bf[0] = __float_as_uint(Bs[cur][(kk + qc) * VSTR + nt * 8 + qr]);
                bf[1] = __float_as_uint(Bs[cur][(kk + qc + 4) * VSTR + nt * 8 + qr]);
                MMA_TF32(acc[nt], af, bf);
            }
        }
        __syncthreads();
    }

    int r0 = i0 + warp_m + qr;
    int r1 = r0 + 8;
#pragma unroll
    for (int nt = 0; nt < 9; nt++) {
        int c0 = nt * 8 + qc * 2;
        if (r0 < Sq) {
            Ob[(long)r0 * oRS + c0] = rndtf(acc[nt][0]);
            Ob[(long)r0 * oRS + c0 + 1] = rndtf(acc[nt][1]);
        }
        if (r1 < Sq) {
            Ob[(long)r1 * oRS + c0] = rndtf(acc[nt][2]);
            Ob[(long)r1 * oRS + c0 + 1] = rndtf(acc[nt][3]);
        }
    }
}

// ---------------- SIMT scores (temporal only, tiny) ----------------
__global__ void k_scores(const float* __restrict__ Q, const float* __restrict__ Kd,
                         float* __restrict__ out, int heads, int Sq, int Sk,
                         int qRS, int kRS, long qBS, long kBS, float scale) {
    __shared__ float qs[32][73];
    __shared__ float ks[32][73];
    int z = blockIdx.z;
    int b = z / heads, h = z - b * heads;
    const float* qb = Q + (long)b * qBS + h * CHD;
    const float* kb = Kd + (long)b * kBS + h * CHD;
    int i0 = blockIdx.y * 32, j0 = blockIdx.x * 32;
    int tid = threadIdx.x;

    for (int idx = tid; idx < 32 * CHD; idx += 256) {
        int r = idx / CHD, d = idx - r * CHD;
        int i = i0 + r;
        qs[r][d] = (i < Sq) ? qb[(long)i * qRS + d] : 0.f;
        int j = j0 + r;
        ks[r][d] = (j < Sk) ? kb[(long)j * kRS + d] : 0.f;
    }
    __syncthreads();

    int il = tid >> 3;
    int jq = (tid & 7) * 4;
    float acc[4] = {0.f, 0.f, 0.f, 0.f};
#pragma unroll 8
    for (int d = 0; d < CHD; d++) {
        float qv = qs[il][d];
#pragma unroll
        for (int jj = 0; jj < 4; jj++) acc[jj] = fmaf(qv, ks[jq + jj][d], acc[jj]);
    }
    int i = i0 + il;
    if (i < Sq) {
        float* orow = out + (long)z * Sq * Sk + (long)i * Sk;
#pragma unroll
        for (int jj = 0; jj < 4; jj++) {
            int j = j0 + jq + jj;
            if (j < Sk) orow[j] = acc[jj] * scale;
        }
    }
}

// ---------------- softmax (tf32-rounded output) ----------------
__global__ void k_softmax(float* __restrict__ sc, int L, int Sq, int causal) {
    long row = blockIdx.x;
    float* p = sc + row * (long)L;
    int i = (int)(row % Sq);
    int tid = threadIdx.x;
    int j0 = tid, j1 = tid + 128;

    float a0 = -FLT_MAX, a1 = -FLT_MAX;
    if (j0 < L) { a0 = p[j0]; if (causal && j0 > i) a0 = -FLT_MAX; }
    if (j1 < L) { a1 = p[j1]; if (causal && j1 > i) a1 = -FLT_MAX; }

    __shared__ float red[4];
    float m = fmaxf(a0, a1);
#pragma unroll
    for (int off = 16; off > 0; off >>= 1) m = fmaxf(m, __shfl_xor_sync(0xffffffffu, m, off));
    if ((tid & 31) == 0) red[tid >> 5] = m;
    __syncthreads();
    m = fmaxf(fmaxf(red[0], red[1]), fmaxf(red[2], red[3]));
    __syncthreads();

    float e0 = (j0 < L) ? expf(a0 - m) : 0.f;
    float e1 = (j1 < L) ? expf(a1 - m) : 0.f;
    float s = e0 + e1;
#pragma unroll
    for (int off = 16; off > 0; off >>= 1) s += __shfl_xor_sync(0xffffffffu, s, off);
    if ((tid & 31) == 0) red[tid >> 5] = s;
    __syncthreads();
    s = red[0] + red[1] + red[2] + red[3];
    float inv = 1.f / s;
    if (j0 < L) p[j0] = rndtf(e0 * inv);
    if (j1 < L) p[j1] = rndtf(e1 * inv);
}

// ---------------- SIMT attn@V (temporal only; rounded output) ----------------
__global__ void k_av(const float* __restrict__ Asc, const float* __restrict__ V,
                     float* __restrict__ O, int heads, int Sq, int Sk,
                     int vRS, long vBS, int oRS, long oBS) {
    __shared__ float vs[32][73];
    __shared__ float as[8][32];
    int z = blockIdx.y;
    int b = z / heads, h = z - b * heads;
    const float* Ab = Asc + (long)z * Sq * Sk;
    const float* Vb = V + (long)b * vBS + h * CHD;
    float* Ob = O + (long)b * oBS + h * CHD;

    int d = threadIdx.x, ii = threadIdx.y;
    int i = blockIdx.x * 8 + ii;
    int tid = ii * 72 + d;
    float acc = 0.f;

    for (int jt = 0; jt < Sk; jt += 32) {
        for (int idx = tid; idx < 32 * CHD; idx += 576) {
            int r = idx / CHD, dd = idx - r * CHD;
            int j = jt + r;
            vs[r][dd] = (j < Sk) ? Vb[(long)j * vRS + dd] : 0.f;
        }
        if (tid < 256) {
            int r = tid >> 5, jj = tid & 31;
            int ig = blockIdx.x * 8 + r;
            int j = jt + jj;
            as[r][jj] = (ig < Sq && j < Sk) ? Ab[(long)ig * Sk + j] : 0.f;
        }
        __syncthreads();
#pragma unroll
        for (int jj = 0; jj < 32; jj++) acc = fmaf(as[ii][jj], vs[jj][d], acc);
        __syncthreads();
    }
    if (i < Sq) Ob[(long)i * oRS + d] = rndtf(acc);
}

// ---------------- build temporal input (rounded) ----------------
__global__ void k_xt_build(const float* __restrict__ X, const float* __restrict__ tpe,
                           float* __restrict__ out) {
    int r = blockIdx.x;
    int t = r & 15;
    int bs = r >> 4;
    int s = bs & 255;
    int b = bs >> 8;
    const float* xr = X + ((size_t)b * CN + t * CS + s) * CC;
    const float* tp = tpe + (size_t)t * CC;
    float* orow = out + (size_t)r * CC;
#pragma unroll
    for (int i = 0; i < 4; i++) {
        int c = threadIdx.x + i * 288;
        orow[c] = rndtf(xr[c] + tp[c]);
    }
}

// ---------------- temporal residual scatter + rounded copy of X ----------------
__global__ void k_resadd_t(float* __restrict__ X, const float* __restrict__ src,
                           const float* __restrict__ t6, int gi,
                           float* __restrict__ xr_out) {
    int r = blockIdx.x;
    int b = r >> 12;
    int n = r & 4095;
    int t = n >> 8;
    int s = n & 255;
    long srow = ((long)(b * CS + s) * CT + t) * CC;
    float* xr = X + (size_t)r * CC;
    const float* sr = src + srow;
    const float* gr = t6 + (size_t)(b * 6 + gi) * CC;
    float* orow = xr_out + (size_t)r * CC;
#pragma unroll
    for (int i = 0; i < 4; i++) {
        int c = threadIdx.x + i * 288;
        float v = xr[c] + gr[c] * sr[c];
        xr[c] = v;
        orow[c] = rndtf(v);
    }
}

// =======================================================================
extern "C" void kernel_launch(void* const* d_in, const int* in_sizes, int n_in,
                              void* d_out, int out_size) {
    const float* x      = (const float*)d_in[0];
    const float* y      = (const float*)d_in[1];
    const float* t      = (const float*)d_in[2];
    const float* tpe    = (const float*)d_in[3];
    const float* sst    = (const float*)d_in[4];
    const float* qkv_s_w = (const float*)d_in[5];
    const float* qkv_s_b = (const float*)d_in[6];
    const float* proj_s_w = (const float*)d_in[7];
    const float* proj_s_b = (const float*)d_in[8];
    const float* qkv_t_w = (const float*)d_in[9];
    const float* qkv_t_b = (const float*)d_in[10];
    const float* proj_t_w = (const float*)d_in[11];
    const float* proj_t_b = (const float*)d_in[12];
    const float* q_c_w  = (const float*)d_in[13];
    const float* q_c_b  = (const float*)d_in[14];
    const float* kv_c_w = (const float*)d_in[15];
    const float* kv_c_b = (const float*)d_in[16];
    const float* proj_c_w = (const float*)d_in[17];
    const float* proj_c_b = (const float*)d_in[18];
    const float* fc1_w  = (const float*)d_in[19];
    const float* fc1_b  = (const float*)d_in[20];
    const float* fc2_w  = (const float*)d_in[21];
    const float* fc2_b  = (const float*)d_in[22];
    float* X = (float*)d_out;

    float *p_t6, *p_xm, *p_qkv, *p_att, *p_h, *p_sc, *p_kv, *p_w, *p_yr;
    cudaGetSymbolAddress((void**)&p_t6, g_t6);
    cudaGetSymbolAddress((void**)&p_xm, g_xm);
    cudaGetSymbolAddress((void**)&p_qkv, g_qkv);
    cudaGetSymbolAddress((void**)&p_att, g_att);
    cudaGetSymbolAddress((void**)&p_h, g_h);
    cudaGetSymbolAddress((void**)&p_sc, g_sc);
    cudaGetSymbolAddress((void**)&p_kv, g_kv);
    cudaGetSymbolAddress((void**)&p_w, g_w);
    cudaGetSymbolAddress((void**)&p_yr, g_yr);

    const float scale = 0.11785113019775793f;  // 1/sqrt(72)
    const int SMEM2 = (3 * (TBM2 + TBN2) * ASTR) * (int)sizeof(float);  // 92160

    static int attr_set = 0;
    if (!attr_set) {
        cudaFuncSetAttribute((const void*)k_tgemm2<0>, cudaFuncAttributeMaxDynamicSharedMemorySize, SMEM2);
        cudaFuncSetAttribute((const void*)k_tgemm2<1>, cudaFuncAttributeMaxDynamicSharedMemorySize, SMEM2);
        cudaFuncSetAttribute((const void*)k_tgemm2<2>, cudaFuncAttributeMaxDynamicSharedMemorySize, SMEM2);
        cudaFuncSetAttribute((const void*)k_tgemm2<3>, cudaFuncAttributeMaxDynamicSharedMemorySize, SMEM2);
        attr_set = 1;
    }

    // rounded weight copies
    float* w_qkv_s = p_w + (size_t)0 * CC2;
    float* w_proj_s = p_w + (size_t)3 * CC2;
    float* w_qkv_t = p_w + (size_t)4 * CC2;
    float* w_proj_t = p_w + (size_t)7 * CC2;
    float* w_q_c   = p_w + (size_t)8 * CC2;
    float* w_kv_c  = p_w + (size_t)9 * CC2;
    float* w_proj_c = p_w + (size_t)11 * CC2;
    float* w_fc1   = p_w + (size_t)12 * CC2;
    float* w_fc2   = p_w + (size_t)16 * CC2;

    auto rnd = [&](const float* src, float* dst, size_t n) {
        k_round<<<(int)((n + 255) / 256), 256>>>(src, dst, (int)n);
    };
    rnd(qkv_s_w, w_qkv_s, (size_t)3 * CC2);
    rnd(proj_s_w, w_proj_s, CC2);
    rnd(qkv_t_w, w_qkv_t, (size_t)3 * CC2);
    rnd(proj_t_w, w_proj_t, CC2);
    rnd(q_c_w, w_q_c, CC2);
    rnd(kv_c_w, w_kv_c, (size_t)2 * CC2);
    rnd(proj_c_w, w_proj_c, CC2);
    rnd(fc1_w, w_fc1, (size_t)4 * CC2);
    rnd(fc2_w, w_fc2, (size_t)4 * CC2);
    rnd(y, p_yr, (size_t)CB * CYL * CC);

    cudaMemcpyAsync(X, x, (size_t)NROW * CC * sizeof(float), cudaMemcpyDeviceToDevice);
    k_mod<<<(CB * 6 * CC + 255) / 256, 256>>>(t, sst, p_t6);

#define G2(OP, A, W, B, C, Nn, K, gi) \
    k_tgemm2<OP><<<dim3((Nn) / TBN2, NROW / TBM2), 256, SMEM2>>>(A, W, B, C, NROW, Nn, K, p_t6, gi)

    // ---- spatial attention ----
    k_ln_mod<<<NROW, 288>>>(X, p_t6, p_xm, 0, 1);
    G2(1, p_xm, w_qkv_s, qkv_s_b, p_qkv, 3 * CC, CC, 0);
    k_scores_mma<<<dim3(2, 2, CB * CT * CNH), 256>>>(p_qkv, p_qkv + CC, p_sc, CNH, CS, CS,
                                                     3 * CC, 3 * CC,
                                                     (long)CS * 3 * CC, (long)CS * 3 * CC, scale);
    k_softmax<<<CB * CT * CNH * CS, 128>>>(p_sc, CS, CS, 0);
    k_av_mma<<<dim3(2, CB * CT * CNH), 256>>>(p_sc, p_qkv + 2 * CC, p_att, CNH, CS, CS,
                                              3 * CC, (long)CS * 3 * CC, CC, (long)CS * CC);
    G2(3, p_att, w_proj_s, proj_s_b, X, CC, CC, 2);   // fused X += gate_msa * proj

    // ---- temporal attention (causal) ----
    k_xt_build<<<NROW, 288>>>(X, tpe, p_xm);
    G2(1, p_xm, w_qkv_t, qkv_t_b, p_qkv, 3 * CC, CC, 0);
    k_scores<<<dim3(1, 1, CB * CS * CNH), 256>>>(p_qkv, p_qkv + CC, p_sc, CNH, CT, CT,
                                                 3 * CC, 3 * CC,
                                                 (long)CT * 3 * CC, (long)CT * 3 * CC, scale);
    k_softmax<<<CB * CS * CNH * CT, 128>>>(p_sc, CT, CT, 1);
    k_av<<<dim3(CT / 8, CB * CS * CNH), dim3(72, 8)>>>(p_sc, p_qkv + 2 * CC, p_att, CNH, CT, CT,
                                                       3 * CC, (long)CT * 3 * CC,
                                                       CC, (long)CT * CC);
    G2(0, p_att, w_proj_t, proj_t_b, p_xm, CC, CC, 0);
    k_resadd_t<<<NROW, 288>>>(X, p_xm, p_t6, 2, p_h);  // p_h = rounded X copy

    // ---- cross attention ----
    G2(1, p_h, w_q_c, q_c_b, p_qkv, CC, CC, 0);
    k_tgemm<1><<<dim3(2 * CC / TBN, (CB * CYL + TBM - 1) / TBM), 256>>>(
        p_yr, w_kv_c, kv_c_b, p_kv, CB * CYL, 2 * CC, CC);
    k_scores_mma<<<dim3(1, CN / TBM, CB * CNH), 256>>>(p_qkv, p_kv, p_sc, CNH, CN, CYL,
                                                       CC, 2 * CC,
                                                       (long)CN * CC, (long)CYL * 2 * CC, scale);
    k_softmax<<<CB * CNH * CN, 128>>>(p_sc, CYL, CN, 0);
    k_av_mma<<<dim3(CN / TBM, CB * CNH), 256>>>(p_sc, p_kv + CC, p_att, CNH, CN, CYL,
                                                2 * CC, (long)CYL * 2 * CC, CC, (long)CN * CC);
    G2(3, p_att, w_proj_c, proj_c_b, X, CC, CC, -1);  // fused X += proj (gate=1)

    // ---- MLP ----
    k_ln_mod<<<NROW, 288>>>(X, p_t6, p_xm, 3, 4);
    G2(2, p_xm, w_fc1, fc1_b, p_h, 4 * CC, CC, 0);
    G2(3, p_h, w_fc2, fc2_b, X, CC, 4 * CC, 5);       // fused X += gate_mlp * fc2
}

// round 5
// speedup vs baseline: 1.0926x; 1.0926x over previous
#include <cuda_runtime.h>
#include <math.h>
#include <float.h>
#include <stdint.h>

// ---------------- problem constants ----------------
#define CB   4
#define CT   16
#define CS   256
#define CN   4096
#define CC   1152
#define CNH  16
#define CHD  72
#define CYL  120
#define NROW 16384
#define CC2  (CC * CC)

// ---------------- scratch (device globals) ----------------
__device__ float g_t6[CB * 6 * CC];
__device__ float g_xm[(size_t)NROW * CC];
__device__ float g_qkv[(size_t)NROW * 3 * CC];
__device__ float g_att[(size_t)NROW * CC];
__device__ float g_h[(size_t)NROW * 4 * CC];
__device__ float g_sc[67108864UL];
__device__ float g_kv[CB * CYL * 2 * CC];
__device__ float g_w[20 * CC2];                 // tf32-rounded weights
__device__ float g_yr[CB * CYL * CC];           // tf32-rounded y

// ---------------- helpers ----------------
__device__ __forceinline__ float gelu_tanh(float x) {
    float x3 = x * x * x;
    return 0.5f * x * (1.f + tanhf(0.7978845608028654f * (x + 0.044715f * x3)));
}
__device__ __forceinline__ uint32_t f2tf(float f) {
    uint32_t u;
    asm("cvt.rna.tf32.f32 %0, %1;" : "=r"(u) : "f"(f));
    return u;
}
__device__ __forceinline__ float rndtf(float f) { return __uint_as_float(f2tf(f)); }

__device__ __forceinline__ void cp_async16(void* smem, const void* gmem) {
    uint32_t s = (uint32_t)__cvta_generic_to_shared(smem);
    asm volatile("cp.async.cg.shared.global [%0], [%1], 16;\n" :: "r"(s), "l"(gmem));
}
__device__ __forceinline__ void cp_async16z(void* smem, const void* gmem, int sz) {
    uint32_t s = (uint32_t)__cvta_generic_to_shared(smem);
    asm volatile("cp.async.cg.shared.global [%0], [%1], 16, %2;\n" :: "r"(s), "l"(gmem), "r"(sz));
}
__device__ __forceinline__ void cp_commit() { asm volatile("cp.async.commit_group;\n"); }
template <int Nk>
__device__ __forceinline__ void cp_wait() { asm volatile("cp.async.wait_group %0;\n" :: "n"(Nk)); }

#define MMA_TF32(acc, af, bf)                                                     \
    asm volatile(                                                                 \
        "mma.sync.aligned.m16n8k8.row.col.f32.tf32.tf32.f32 "                     \
        "{%0,%1,%2,%3}, {%4,%5,%6,%7}, {%8,%9}, {%0,%1,%2,%3};\n"                 \
        : "+f"(acc[0]), "+f"(acc[1]), "+f"(acc[2]), "+f"(acc[3])                  \
        : "r"(af[0]), "r"(af[1]), "r"(af[2]), "r"(af[3]), "r"(bf[0]), "r"(bf[1]))

// ---------------- elementwise round ----------------
__global__ void k_round(const float* __restrict__ a, float* __restrict__ o, int n) {
    int i = blockIdx.x * blockDim.x + threadIdx.x;
    if (i < n) o[i] = rndtf(a[i]);
}

// ---------------- modulation ----------------
__global__ void k_mod(const float* __restrict__ t, const float* __restrict__ sst,
                      float* __restrict__ t6) {
    int i = blockIdx.x * blockDim.x + threadIdx.x;
    if (i < CB * 6 * CC) t6[i] = sst[i % (6 * CC)] + t[i];
}

// ---------------- LayerNorm + modulate (tf32-rounded output) ----------------
__global__ void k_ln_mod(const float* __restrict__ X, const float* __restrict__ t6,
                         float* __restrict__ out, int shiftIdx, int scaleIdx) {
    int r = blockIdx.x;
    int b = r >> 12;
    const float* xr = X + (size_t)r * CC;
    const float* sh = t6 + (size_t)(b * 6 + shiftIdx) * CC;
    const float* scl = t6 + (size_t)(b * 6 + scaleIdx) * CC;

    float v[4];
    float s = 0.f, sq = 0.f;
#pragma unroll
    for (int i = 0; i < 4; i++) {
        int c = threadIdx.x + i * 288;
        v[i] = xr[c];
        s += v[i];
        sq += v[i] * v[i];
    }
    __shared__ float s1[9], s2[9], bc[2];
    int lane = threadIdx.x & 31, wid = threadIdx.x >> 5;
#pragma unroll
    for (int off = 16; off > 0; off >>= 1) {
        s += __shfl_xor_sync(0xffffffffu, s, off);
        sq += __shfl_xor_sync(0xffffffffu, sq, off);
    }
    if (lane == 0) { s1[wid] = s; s2[wid] = sq; }
    __syncthreads();
    if (threadIdx.x == 0) {
        float ts = 0.f, tq = 0.f;
        for (int w = 0; w < 9; w++) { ts += s1[w]; tq += s2[w]; }
        float mean = ts * (1.f / CC);
        float var = tq * (1.f / CC) - mean * mean;
        bc[0] = mean;
        bc[1] = rsqrtf(var + 1e-6f);
    }
    __syncthreads();
    float mean = bc[0], rstd = bc[1];
    float* orow = out + (size_t)r * CC;
#pragma unroll
    for (int i = 0; i < 4; i++) {
        int c = threadIdx.x + i * 288;
        orow[c] = rndtf((v[i] - mean) * rstd * (1.f + scl[c]) + sh[c]);
    }
}

#define TBK 16
#define ASTR 20
#define TBM 128
#define TBN 128
#define STG 4
#define TSZ (TBM * ASTR)   // floats per stage per operand (2560)

// ---------------- unified TF32 GEMM: C[M,N] = A[M,K] @ W[N,K]^T + bias -------
// 128x128x16 tile, 4-stage cp.async pipeline, 64x32 warp tiles.
// OP: 0 = plain, 1 = round, 2 = gelu+round, 3 = C = resid + gate*(acc+bias)
template <int OP>
__global__ __launch_bounds__(256) void k_tgemm(const float* __restrict__ A,
                                               const float* __restrict__ W,
                                               const float* __restrict__ bias,
                                               float* __restrict__ Cmat,
                                               const float* __restrict__ resid,
                                               const float* __restrict__ t6, int gi,
                                               int M, int Nn, int K) {
    extern __shared__ float sm[];
    float* As = sm;                // STG stages of 128x20
    float* Bs = sm + STG * TSZ;

    const int tid = threadIdx.x;
    const int m0 = blockIdx.y * TBM, n0 = blockIdx.x * TBN;
    const int wid = tid >> 5, lane = tid & 31;
    const int wr = wid >> 2, wc = wid & 3;
    const int warp_m = wr * 64, warp_n = wc * 32;
    const int qr = lane >> 2, qc = lane & 3;

    float acc[4][4][4];
#pragma unroll
    for (int mi = 0; mi < 4; mi++)
#pragma unroll
        for (int ni = 0; ni < 4; ni++)
#pragma unroll
            for (int c = 0; c < 4; c++) acc[mi][ni][c] = 0.f;

    auto load_tile = [&](int stg, int kbase) {
        float* as = As + stg * TSZ;
        float* bs = Bs + stg * TSZ;
#pragma unroll
        for (int i = 0; i < 2; i++) {
            int ch = tid + i * 256;
            int m = ch >> 2;
            int k4 = (ch & 3) * 4;
            int gm = m0 + m; if (gm >= M) gm = M - 1;
            cp_async16(&as[m * ASTR + k4], A + (size_t)gm * K + kbase + k4);
            cp_async16(&bs[m * ASTR + k4], W + (size_t)(n0 + m) * K + kbase + k4);
        }
    };

    const int KT = K >> 4;
    load_tile(0, 0); cp_commit();
    load_tile(1, 16); cp_commit();
    load_tile(2, 32); cp_commit();

    for (int kt = 0; kt < KT; ++kt) {
        cp_wait<STG - 2>();
        __syncthreads();
        if (kt + STG - 1 < KT) load_tile((kt + STG - 1) % STG, (kt + STG - 1) << 4);
        cp_commit();

        const float* as = As + (kt % STG) * TSZ;
        const float* bs = Bs + (kt % STG) * TSZ;
#pragma unroll
        for (int kk = 0; kk < TBK; kk += 8) {
            uint32_t af[4][4], bf[4][2];
#pragma unroll
            for (int mi = 0; mi < 4; mi++) {
                const float* base = &as[(warp_m + mi * 16 + qr) * ASTR + kk + qc];
                af[mi][0] = __float_as_uint(base[0]);
                af[mi][1] = __float_as_uint(base[8 * ASTR]);
                af[mi][2] = __float_as_uint(base[4]);
                af[mi][3] = __float_as_uint(base[8 * ASTR + 4]);
            }
#pragma unroll
            for (int ni = 0; ni < 4; ni++) {
                const float* base = &bs[(warp_n + ni * 8 + qr) * ASTR + kk + qc];
                bf[ni][0] = __float_as_uint(base[0]);
                bf[ni][1] = __float_as_uint(base[4]);
            }
#pragma unroll
            for (int mi = 0; mi < 4; mi++)
#pragma unroll
                for (int ni = 0; ni < 4; ni++) MMA_TF32(acc[mi][ni], af[mi], bf[ni]);
        }
        __syncthreads();
    }

    const int b = m0 >> 12;
    const float* gate = (OP == 3 && gi >= 0) ? t6 + (size_t)(b * 6 + gi) * CC : nullptr;

#pragma unroll
    for (int mi = 0; mi < 4; mi++) {
        int r0 = m0 + warp_m + mi * 16 + qr;
        int r1 = r0 + 8;
#pragma unroll
        for (int ni = 0; ni < 4; ni++) {
            int c0 = n0 + warp_n + ni * 8 + qc * 2;
            float b0 = bias[c0], b1 = bias[c0 + 1];
            float v[4] = {acc[mi][ni][0] + b0, acc[mi][ni][1] + b1,
                          acc[mi][ni][2] + b0, acc[mi][ni][3] + b1};
            if (OP == 2) {
#pragma unroll
                for (int c = 0; c < 4; c++) v[c] = gelu_tanh(v[c]);
            }
            if (OP == 1 || OP == 2) {
#pragma unroll
                for (int c = 0; c < 4; c++) v[c] = rndtf(v[c]);
            }
            if (OP == 3) {
                float g0 = gate ? gate[c0] : 1.f;
                float g1 = gate ? gate[c0 + 1] : 1.f;
                if (r0 < M) {
                    const float* rr = resid + (size_t)r0 * Nn;
                    float* cw = Cmat + (size_t)r0 * Nn;
                    cw[c0] = rr[c0] + g0 * v[0];
                    cw[c0 + 1] = rr[c0 + 1] + g1 * v[1];
                }
                if (r1 < M) {
                    const float* rr = resid + (size_t)r1 * Nn;
                    float* cw = Cmat + (size_t)r1 * Nn;
                    cw[c0] = rr[c0] + g0 * v[2];
                    cw[c0 + 1] = rr[c0 + 1] + g1 * v[3];
                }
            } else {
                if (r0 < M) {
                    Cmat[(size_t)r0 * Nn + c0] = v[0];
                    Cmat[(size_t)r0 * Nn + c0 + 1] = v[1];
                }
                if (r1 < M) {
                    Cmat[(size_t)r1 * Nn + c0] = v[2];
                    Cmat[(size_t)r1 * Nn + c0 + 1] = v[3];
                }
            }
        }
    }
}

// ---------------- MMA scores (+ optional fused softmax when one CTA owns rows)
// DOSM = 1 requires gridDim.x == 1 and Sk <= TBN.
template <int DOSM>
__global__ __launch_bounds__(256) void k_scores_mma(const float* __restrict__ Q,
                                                    const float* __restrict__ Kd,
                                                    float* __restrict__ out,
                                                    int heads, int Sq, int Sk,
                                                    int qRS, int kRS, long qBS, long kBS,
                                                    float scale) {
    __shared__ float As[2][TBM * ASTR];
    __shared__ float Bs[2][TBN * ASTR];
    __shared__ float red[128][4];

    const int tid = threadIdx.x;
    int z = blockIdx.z;
    int b = z / heads, h = z - b * heads;
    const float* qb = Q + (long)b * qBS + h * CHD;
    const float* kb = Kd + (long)b * kBS + h * CHD;
    const int i0 = blockIdx.y * TBM, j0 = blockIdx.x * TBN;
    const int wid = tid >> 5, lane = tid & 31;
    const int wr = wid >> 2, wc = wid & 3;
    const int warp_m = wr * 64, warp_n = wc * 32;
    const int qr = lane >> 2, qc = lane & 3;

    float acc[4][4][4];
#pragma unroll
    for (int mi = 0; mi < 4; mi++)
#pragma unroll
        for (int ni = 0; ni < 4; ni++)
#pragma unroll
            for (int c = 0; c < 4; c++) acc[mi][ni][c] = 0.f;

    auto load_tile = [&](int stg, int kbase) {
#pragma unroll
        for (int i = 0; i < 2; i++) {
            int ch = tid + i * 256;
            int m = ch >> 2;
            int k4 = (ch & 3) * 4;
            int sz = (kbase + k4 + 4 <= CHD) ? 16 : 0;
            int gq = i0 + m; if (gq >= Sq) gq = Sq - 1;
            int gk = j0 + m; if (gk >= Sk) gk = Sk - 1;
            cp_async16z(&As[stg][m * ASTR + k4], qb + (long)gq * qRS + kbase + k4, sz);
            cp_async16z(&Bs[stg][m * ASTR + k4], kb + (long)gk * kRS + kbase + k4, sz);
        }
    };

    const int KT = 5;
    load_tile(0, 0);
    cp_commit();

    for (int kt = 0; kt < KT; ++kt) {
        int cur = kt & 1;
        if (kt + 1 < KT) {
            load_tile(1 - cur, (kt + 1) << 4);
            cp_commit();
            cp_wait<1>();
        } else {
            cp_wait<0>();
        }
        __syncthreads();

#pragma unroll
        for (int kk = 0; kk < TBK; kk += 8) {
            uint32_t af[4][4], bf[4][2];
#pragma unroll
            for (int mi = 0; mi < 4; mi++) {
                const float* base = &As[cur][(warp_m + mi * 16 + qr) * ASTR + kk + qc];
                af[mi][0] = __float_as_uint(base[0]);
                af[mi][1] = __float_as_uint(base[8 * ASTR]);
                af[mi][2] = __float_as_uint(base[4]);
                af[mi][3] = __float_as_uint(base[8 * ASTR + 4]);
            }
#pragma unroll
            for (int ni = 0; ni < 4; ni++) {
                const float* base = &Bs[cur][(warp_n + ni * 8 + qr) * ASTR + kk + qc];
                bf[ni][0] = __float_as_uint(base[0]);
                bf[ni][1] = __float_as_uint(base[4]);
            }
#pragma unroll
            for (int mi = 0; mi < 4; mi++)
#pragma unroll
                for (int ni = 0; ni < 4; ni++) MMA_TF32(acc[mi][ni], af[mi], bf[ni]);
        }
        __syncthreads();
    }

    float* ob = out + (long)z * Sq * Sk;

    if (DOSM == 0) {
#pragma unroll
        for (int mi = 0; mi < 4; mi++) {
            int r0 = i0 + warp_m + mi * 16 + qr;
            int r1 = r0 + 8;
#pragma unroll
            for (int ni = 0; ni < 4; ni++) {
                int c0 = j0 + warp_n + ni * 8 + qc * 2;
                if (c0 < Sk) {
                    if (r0 < Sq) ob[(long)r0 * Sk + c0] = acc[mi][ni][0] * scale;
                    if (r1 < Sq) ob[(long)r1 * Sk + c0] = acc[mi][ni][2] * scale;
                }
                if (c0 + 1 < Sk) {
                    if (r0 < Sq) ob[(long)r0 * Sk + c0 + 1] = acc[mi][ni][1] * scale;
                    if (r1 < Sq) ob[(long)r1 * Sk + c0 + 1] = acc[mi][ni][3] * scale;
                }
            }
        }
        return;
    }

    // ---- fused row softmax (grid.x == 1, Sk <= 128, Sq % 128 == 0) ----
    // scale in place
#pragma unroll
    for (int mi = 0; mi < 4; mi++)
#pragma unroll
        for (int ni = 0; ni < 4; ni++)
#pragma unroll
            for (int c = 0; c < 4; c++) acc[mi][ni][c] *= scale;

    float mrow[4][2], srow[4][2];
    // --- max ---
#pragma unroll
    for (int mi = 0; mi < 4; mi++)
#pragma unroll
        for (int hf = 0; hf < 2; hf++) {
            float m = -FLT_MAX;
#pragma unroll
            for (int ni = 0; ni < 4; ni++) {
                int c0 = warp_n + ni * 8 + qc * 2;
                if (c0 < Sk) m = fmaxf(m, acc[mi][ni][hf * 2]);
                if (c0 + 1 < Sk) m = fmaxf(m, acc[mi][ni][hf * 2 + 1]);
            }
            m = fmaxf(m, __shfl_xor_sync(0xffffffffu, m, 1));
            m = fmaxf(m, __shfl_xor_sync(0xffffffffu, m, 2));
            if (qc == 0) red[warp_m + mi * 16 + qr + hf * 8][wc] = m;
            mrow[mi][hf] = m;
        }
    __syncthreads();
#pragma unroll
    for (int mi = 0; mi < 4; mi++)
#pragma unroll
        for (int hf = 0; hf < 2; hf++) {
            int rl = warp_m + mi * 16 + qr + hf * 8;
            float m = fmaxf(fmaxf(red[rl][0], red[rl][1]), fmaxf(red[rl][2], red[rl][3]));
            mrow[mi][hf] = m;
        }
    __syncthreads();
    // --- exp + sum ---
#pragma unroll
    for (int mi = 0; mi < 4; mi++)
#pragma unroll
        for (int hf = 0; hf < 2; hf++) {
            float s = 0.f;
#pragma unroll
            for (int ni = 0; ni < 4; ni++) {
                int c0 = warp_n + ni * 8 + qc * 2;
                float e0 = (c0 < Sk) ? expf(acc[mi][ni][hf * 2] - mrow[mi][hf]) : 0.f;
                float e1 = (c0 + 1 < Sk) ? expf(acc[mi][ni][hf * 2 + 1] - mrow[mi][hf]) : 0.f;
                acc[mi][ni][hf * 2] = e0;
                acc[mi][ni][hf * 2 + 1] = e1;
                s += e0 + e1;
            }
            s += __shfl_xor_sync(0xffffffffu, s, 1);
            s += __shfl_xor_sync(0xffffffffu, s, 2);
            if (qc == 0) red[warp_m + mi * 16 + qr + hf * 8][wc] = s;
            srow[mi][hf] = s;
        }
    __syncthreads();
#pragma unroll
    for (int mi = 0; mi < 4; mi++)
#pragma unroll
        for (int hf = 0; hf < 2; hf++) {
            int rl = warp_m + mi * 16 + qr + hf * 8;
            float s = red[rl][0] + red[rl][1] + red[rl][2] + red[rl][3];
            srow[mi][hf] = 1.f / s;
        }
    // --- store normalized P (rounded) ---
#pragma unroll
    for (int mi = 0; mi < 4; mi++) {
        int r0 = i0 + warp_m + mi * 16 + qr;
        int r1 = r0 + 8;
#pragma unroll
        for (int ni = 0; ni < 4; ni++) {
            int c0 = warp_n + ni * 8 + qc * 2;
            if (c0 < Sk) {
                ob[(long)r0 * Sk + c0] = rndtf(acc[mi][ni][0] * srow[mi][0]);
                ob[(long)r1 * Sk + c0] = rndtf(acc[mi][ni][2] * srow[mi][1]);
            }
            if (c0 + 1 < Sk) {
                ob[(long)r0 * Sk + c0 + 1] = rndtf(acc[mi][ni][1] * srow[mi][0]);
                ob[(long)r1 * Sk + c0 + 1] = rndtf(acc[mi][ni][3] * srow[mi][1]);
            }
        }
    }
}

// ---------------- MMA attn@V: O[z,i,d] = sum_j P[z,i,j] V[z,j,d]  (d = 72) ----
#define VSTR 72
__global__ __launch_bounds__(256) void k_av_mma(const float* __restrict__ P,
                                                const float* __restrict__ V,
                                                float* __restrict__ O,
                                                int heads, int Sq, int Sk,
                                                int vRS, long vBS, int oRS, long oBS) {
    __shared__ float As[2][TBM * ASTR];
    __shared__ float Bs[2][16 * VSTR];

    const int tid = threadIdx.x;
    int z = blockIdx.y;
    int b = z / heads, h = z - b * heads;
    const float* Pb = P + (long)z * Sq * Sk;
    const float* Vb = V + (long)b * vBS + h * CHD;
    float* Ob = O + (long)b * oBS + h * CHD;
    const int i0 = blockIdx.x * TBM;
    const int wid = tid >> 5, lane = tid & 31;
    const int warp_m = wid * 16;
    const int qr = lane >> 2, qc = lane & 3;

    float acc[9][4];
#pragma unroll
    for (int nt = 0; nt < 9; nt++)
#pragma unroll
        for (int c = 0; c < 4; c++) acc[nt][c] = 0.f;

    auto load_tile = [&](int stg, int kb) {
#pragma unroll
        for (int i = 0; i < 2; i++) {
            int ch = tid + i * 256;
            int m = ch >> 2;
            int k4 = (ch & 3) * 4;
            int sz = (kb + k4 + 4 <= Sk) ? 16 : 0;
            int gi = i0 + m; if (gi >= Sq) gi = Sq - 1;
            cp_async16z(&As[stg][m * ASTR + k4], Pb + (long)gi * Sk + kb + k4, sz);
        }
#pragma unroll
        for (int i = 0; i < 2; i++) {
            int ch = tid + i * 256;
            if (ch < 288) {
                int r = ch / 18;
                int c4 = (ch - r * 18) * 4;
                int sz = (kb + r < Sk) ? 16 : 0;
                cp_async16z(&Bs[stg][r * VSTR + c4], Vb + (long)(kb + r) * vRS + c4, sz);
            }
        }
    };

    const int KT = (Sk + 15) >> 4;
    load_tile(0, 0);
    cp_commit();

    for (int kt = 0; kt < KT; ++kt) {
        int cur = kt & 1;
        if (kt + 1 < KT) {
            load_tile(1 - cur, (kt + 1) << 4);
            cp_commit();
            cp_wait<1>();
        } else {
            cp_wait<0>();
        }
        __syncthreads();

#pragma unroll
        for (int kk = 0; kk < 16; kk += 8) {
            uint32_t af[4];
            const float* abase = &As[cur][(warp_m + qr) * ASTR + kk + qc];
            af[0] = __float_as_uint(abase[0]);
            af[1] = __float_as_uint(abase[8 * ASTR]);
            af[2] = __float_as_uint(abase[4]);
            af[3] = __float_as_uint(abase[8 * ASTR + 4]);
#pragma unroll
            for (int nt = 0; nt < 9; nt++) {
                uint32_t bf[2];
                bf[0] = __float_as_uint(Bs[cur][(kk + qc) * VSTR + nt * 8 + qr]);
                bf[1] = __float_as_uint(Bs[cur][(kk + qc + 4) * VSTR + nt * 8 + qr]);
                MMA_TF32(acc[nt], af, bf);
            }
        }
        __syncthreads();
    }

    int r0 = i0 + warp_m + qr;
    int r1 = r0 + 8;
#pragma unroll
    for (int nt = 0; nt < 9; nt++) {
        int c0 = nt * 8 + qc * 2;
        if (r0 < Sq) {
            Ob[(long)r0 * oRS + c0] = rndtf(acc[nt][0]);
            Ob[(long)r0 * oRS + c0 + 1] = rndtf(acc[nt][1]);
        }
        if (r1 < Sq) {
            Ob[(long)r1 * oRS + c0] = rndtf(acc[nt][2]);
            Ob[(long)r1 * oRS + c0 + 1] = rndtf(acc[nt][3]);
        }
    }
}

// ---------------- softmax (spatial, tf32-rounded output) ----------------
__global__ void k_softmax(float* __restrict__ sc, int L, int Sq, int causal) {
    long row = blockIdx.x;
    float* p = sc + row * (long)L;
    int i = (int)(row % Sq);
    int tid = threadIdx.x;
    int j0 = tid, j1 = tid + 128;

    float a0 = -FLT_MAX, a1 = -FLT_MAX;
    if (j0 < L) { a0 = p[j0]; if (causal && j0 > i) a0 = -FLT_MAX; }
    if (j1 < L) { a1 = p[j1]; if (causal && j1 > i) a1 = -FLT_MAX; }

    __shared__ float red[4];
    float m = fmaxf(a0, a1);
#pragma unroll
    for (int off = 16; off > 0; off >>= 1) m = fmaxf(m, __shfl_xor_sync(0xffffffffu, m, off));
    if ((tid & 31) == 0) red[tid >> 5] = m;
    __syncthreads();
    m = fmaxf(fmaxf(red[0], red[1]), fmaxf(red[2], red[3]));
    __syncthreads();

    float e0 = (j0 < L) ? expf(a0 - m) : 0.f;
    float e1 = (j1 < L) ? expf(a1 - m) : 0.f;
    float s = e0 + e1;
#pragma unroll
    for (int off = 16; off > 0; off >>= 1) s += __shfl_xor_sync(0xffffffffu, s, off);
    if ((tid & 31) == 0) red[tid >> 5] = s;
    __syncthreads();
    s = red[0] + red[1] + red[2] + red[3];
    float inv = 1.f / s;
    if (j0 < L) p[j0] = rndtf(e0 * inv);
    if (j1 < L) p[j1] = rndtf(e1 * inv);
}

// ---------------- fused temporal attention (T=16, causal) ----------------
// grid (CNH, CB*CS), block 128. qkv rows are temporal-order: (bs*CT + t).
__global__ __launch_bounds__(128) void k_attn_t(const float* __restrict__ qkv,
                                                float* __restrict__ O, float scale) {
    __shared__ float q[16][72], k[16][72], v[16][72], p[16][17];
    int h = blockIdx.x;
    int bs = blockIdx.y;
    const float* base = qkv + (size_t)bs * CT * 3 * CC + h * CHD;
    int tid = threadIdx.x;

    for (int idx = tid; idx < 16 * 72; idx += 128) {
        int t = idx / 72, d = idx - t * 72;
        const float* row = base + (size_t)t * 3 * CC;
        q[t][d] = row[d];
        k[t][d] = row[CC + d];
        v[t][d] = row[2 * CC + d];
    }
    __syncthreads();

    // scores (all 256; mask later)
    for (int e = tid; e < 256; e += 128) {
        int i = e >> 4, j = e & 15;
        float acc = 0.f;
#pragma unroll 8
        for (int d = 0; d < 72; d++) acc += q[i][d] * k[j][d];
        p[i][j] = acc * scale;
    }
    __syncthreads();

    // causal softmax, one thread per row
    if (tid < 16) {
        int i = tid;
        float m = -FLT_MAX;
        for (int j = 0; j <= i; j++) m = fmaxf(m, p[i][j]);
        float s = 0.f;
        for (int j = 0; j <= i; j++) { float e = expf(p[i][j] - m); p[i][j] = e; s += e; }
        float inv = 1.f / s;
        for (int j = 0; j <= i; j++) p[i][j] *= inv;
        for (int j = i + 1; j < 16; j++) p[i][j] = 0.f;
    }
    __syncthreads();

    // AV + store (rounded, temporal-order rows)
    for (int e = tid; e < 16 * 72; e += 128) {
        int t = e / 72, d = e - t * 72;
        float acc = 0.f;
#pragma unroll
        for (int j = 0; j < 16; j++) acc += p[t][j] * v[j][d];
        O[((size_t)bs * CT + t) * CC + h * CHD + d] = rndtf(acc);
    }
}

// ---------------- build temporal input (rounded) ----------------
__global__ void k_xt_build(const float* __restrict__ X, const float* __restrict__ tpe,
                           float* __restrict__ out) {
    int r = blockIdx.x;
    int t = r & 15;
    int bs = r >> 4;
    int s = bs & 255;
    int b = bs >> 8;
    const float* xr = X + ((size_t)b * CN + t * CS + s) * CC;
    const float* tp = tpe + (size_t)t * CC;
    float* orow = out + (size_t)r * CC;
#pragma unroll
    for (int i = 0; i < 4; i++) {
        int c = threadIdx.x + i * 288;
        orow[c] = rndtf(xr[c] + tp[c]);
    }
}

// ---------------- temporal residual scatter + rounded copy of X ----------------
__global__ void k_resadd_t(float* __restrict__ X, const float* __restrict__ src,
                           const float* __restrict__ t6, int gi,
                           float* __restrict__ xr_out) {
    int r = blockIdx.x;
    int b = r >> 12;
    int n = r & 4095;
    int t = n >> 8;
    int s = n & 255;
    long srow = ((long)(b * CS + s) * CT + t) * CC;
    float* xr = X + (size_t)r * CC;
    const float* sr = src + srow;
    const float* gr = t6 + (size_t)(b * 6 + gi) * CC;
    float* orow = xr_out + (size_t)r * CC;
#pragma unroll
    for (int i = 0; i < 4; i++) {
        int c = threadIdx.x + i * 288;
        float v = xr[c] + gr[c] * sr[c];
        xr[c] = v;
        orow[c] = rndtf(v);
    }
}

// =======================================================================
extern "C" void kernel_launch(void* const* d_in, const int* in_sizes, int n_in,
                              void* d_out, int out_size) {
    const float* x      = (const float*)d_in[0];
    const float* y      = (const float*)d_in[1];
    const float* t      = (const float*)d_in[2];
    const float* tpe    = (const float*)d_in[3];
    const float* sst    = (const float*)d_in[4];
    const float* qkv_s_w = (const float*)d_in[5];
    const float* qkv_s_b = (const float*)d_in[6];
    const float* proj_s_w = (const float*)d_in[7];
    const float* proj_s_b = (const float*)d_in[8];
    const float* qkv_t_w = (const float*)d_in[9];
    const float* qkv_t_b = (const float*)d_in[10];
    const float* proj_t_w = (const float*)d_in[11];
    const float* proj_t_b = (const float*)d_in[12];
    const float* q_c_w  = (const float*)d_in[13];
    const float* q_c_b  = (const float*)d_in[14];
    const float* kv_c_w = (const float*)d_in[15];
    const float* kv_c_b = (const float*)d_in[16];
    const float* proj_c_w = (const float*)d_in[17];
    const float* proj_c_b = (const float*)d_in[18];
    const float* fc1_w  = (const float*)d_in[19];
    const float* fc1_b  = (const float*)d_in[20];
    const float* fc2_w  = (const float*)d_in[21];
    const float* fc2_b  = (const float*)d_in[22];
    float* X = (float*)d_out;

    float *p_t6, *p_xm, *p_qkv, *p_att, *p_h, *p_sc, *p_kv, *p_w, *p_yr;
    cudaGetSymbolAddress((void**)&p_t6, g_t6);
    cudaGetSymbolAddress((void**)&p_xm, g_xm);
    cudaGetSymbolAddress((void**)&p_qkv, g_qkv);
    cudaGetSymbolAddress((void**)&p_att, g_att);
    cudaGetSymbolAddress((void**)&p_h, g_h);
    cudaGetSymbolAddress((void**)&p_sc, g_sc);
    cudaGetSymbolAddress((void**)&p_kv, g_kv);
    cudaGetSymbolAddress((void**)&p_w, g_w);
    cudaGetSymbolAddress((void**)&p_yr, g_yr);

    const float scale = 0.11785113019775793f;  // 1/sqrt(72)
    const int SMEMG = STG * 2 * TSZ * (int)sizeof(float);  // 81920

    static int attr_set = 0;
    if (!attr_set) {
        cudaFuncSetAttribute((const void*)k_tgemm<0>, cudaFuncAttributeMaxDynamicSharedMemorySize, SMEMG);
        cudaFuncSetAttribute((const void*)k_tgemm<1>, cudaFuncAttributeMaxDynamicSharedMemorySize, SMEMG);
        cudaFuncSetAttribute((const void*)k_tgemm<2>, cudaFuncAttributeMaxDynamicSharedMemorySize, SMEMG);
        cudaFuncSetAttribute((const void*)k_tgemm<3>, cudaFuncAttributeMaxDynamicSharedMemorySize, SMEMG);
        attr_set = 1;
    }

    // rounded weight copies
    float* w_qkv_s = p_w + (size_t)0 * CC2;
    float* w_proj_s = p_w + (size_t)3 * CC2;
    float* w_qkv_t = p_w + (size_t)4 * CC2;
    float* w_proj_t = p_w + (size_t)7 * CC2;
    float* w_q_c   = p_w + (size_t)8 * CC2;
    float* w_kv_c  = p_w + (size_t)9 * CC2;
    float* w_proj_c = p_w + (size_t)11 * CC2;
    float* w_fc1   = p_w + (size_t)12 * CC2;
    float* w_fc2   = p_w + (size_t)16 * CC2;

    auto rnd = [&](const float* src, float* dst, size_t n) {
        k_round<<<(int)((n + 255) / 256), 256>>>(src, dst, (int)n);
    };
    rnd(qkv_s_w, w_qkv_s, (size_t)3 * CC2);
    rnd(proj_s_w, w_proj_s, CC2);
    rnd(qkv_t_w, w_qkv_t, (size_t)3 * CC2);
    rnd(proj_t_w, w_proj_t, CC2);
    rnd(q_c_w, w_q_c, CC2);
    rnd(kv_c_w, w_kv_c, (size_t)2 * CC2);
    rnd(proj_c_w, w_proj_c, CC2);
    rnd(fc1_w, w_fc1, (size_t)4 * CC2);
    rnd(fc2_w, w_fc2, (size_t)4 * CC2);
    rnd(y, p_yr, (size_t)CB * CYL * CC);

    k_mod<<<(CB * 6 * CC + 255) / 256, 256>>>(t, sst, p_t6);

#define G(OP, A, W, B, C, R, gi, M, Nn, K) \
    k_tgemm<OP><<<dim3((Nn) / TBN, ((M) + TBM - 1) / TBM), 256, SMEMG>>>(A, W, B, C, R, p_t6, gi, M, Nn, K)

    // ---- spatial attention ----
    k_ln_mod<<<NROW, 288>>>(x, p_t6, p_xm, 0, 1);              // LN reads input x directly
    G(1, p_xm, w_qkv_s, qkv_s_b, p_qkv, nullptr, 0, NROW, 3 * CC, CC);
    k_scores_mma<0><<<dim3(2, 2, CB * CT * CNH), 256>>>(p_qkv, p_qkv + CC, p_sc, CNH, CS, CS,
                                                        3 * CC, 3 * CC,
                                                        (long)CS * 3 * CC, (long)CS * 3 * CC, scale);
    k_softmax<<<CB * CT * CNH * CS, 128>>>(p_sc, CS, CS, 0);
    k_av_mma<<<dim3(2, CB * CT * CNH), 256>>>(p_sc, p_qkv + 2 * CC, p_att, CNH, CS, CS,
                                              3 * CC, (long)CS * 3 * CC, CC, (long)CS * CC);
    G(3, p_att, w_proj_s, proj_s_b, X, x, 2, NROW, CC, CC);    // X = x + gate_msa * proj

    // ---- temporal attention (causal, fused) ----
    k_xt_build<<<NROW, 288>>>(X, tpe, p_xm);
    G(1, p_xm, w_qkv_t, qkv_t_b, p_qkv, nullptr, 0, NROW, 3 * CC, CC);
    k_attn_t<<<dim3(CNH, CB * CS), 128>>>(p_qkv, p_att, scale);
    G(0, p_att, w_proj_t, proj_t_b, p_xm, nullptr, 0, NROW, CC, CC);
    k_resadd_t<<<NROW, 288>>>(X, p_xm, p_t6, 2, p_h);          // p_h = rounded X copy

    // ---- cross attention ----
    G(1, p_h, w_q_c, q_c_b, p_qkv, nullptr, 0, NROW, CC, CC);
    G(1, p_yr, w_kv_c, kv_c_b, p_kv, nullptr, 0, CB * CYL, 2 * CC, CC);
    k_scores_mma<1><<<dim3(1, CN / TBM, CB * CNH), 256>>>(p_qkv, p_kv, p_sc, CNH, CN, CYL,
                                                          CC, 2 * CC,
                                                          (long)CN * CC, (long)CYL * 2 * CC, scale);
    k_av_mma<<<dim3(CN / TBM, CB * CNH), 256>>>(p_sc, p_kv + CC, p_att, CNH, CN, CYL,
                                                2 * CC, (long)CYL * 2 * CC, CC, (long)CN * CC);
    G(3, p_att, w_proj_c, proj_c_b, X, X, -1, NROW, CC, CC);   // X += proj (gate=1)

    // ---- MLP ----
    k_ln_mod<<<NROW, 288>>>(X, p_t6, p_xm, 3, 4);
    G(2, p_xm, w_fc1, fc1_b, p_h, nullptr, 0, NROW, 4 * CC, CC);
    G(3, p_h, w_fc2, fc2_b, X, X, 5, NROW, CC, 4 * CC);        // X += gate_mlp * fc2
}

// round 7
// speedup vs baseline: 1.8602x; 1.7025x over previous
#include <cuda_runtime.h>
#include <cuda_fp16.h>
#include <math.h>
#include <float.h>
#include <stdint.h>

// ---------------- problem constants ----------------
#define CB   4
#define CT   16
#define CS   256
#define CN   4096
#define CC   1152
#define CNH  16
#define CHD  72
#define CYL  120
#define NROW 16384
#define CC2  (CC * CC)

// ---------------- scratch (device globals) ----------------
__device__ float g_t6[CB * 6 * CC];
__device__ float g_xm[(size_t)NROW * CC];
__device__ float g_qkv[(size_t)NROW * 3 * CC];
__device__ float g_att[(size_t)NROW * CC];
__device__ float g_h[(size_t)NROW * 4 * CC];
__device__ float g_sc[67108864UL];
__device__ float g_kv[CB * CYL * 2 * CC];
__device__ float g_w[20 * CC2];                 // half weights (aliased)
__device__ float g_yr[CB * CYL * CC];           // half y (aliased)

// ---------------- helpers ----------------
__device__ __forceinline__ float gelu_tanh(float x) {
    float x3 = x * x * x;
    return 0.5f * x * (1.f + tanhf(0.7978845608028654f * (x + 0.044715f * x3)));
}
__device__ __forceinline__ uint32_t f2tf(float f) {
    uint32_t u;
    asm("cvt.rna.tf32.f32 %0, %1;" : "=r"(u) : "f"(f));
    return u;
}
__device__ __forceinline__ float rndtf(float f) { return __uint_as_float(f2tf(f)); }

__device__ __forceinline__ void cp_async16(void* smem, const void* gmem) {
    uint32_t s = (uint32_t)__cvta_generic_to_shared(smem);
    asm volatile("cp.async.cg.shared.global [%0], [%1], 16;\n" :: "r"(s), "l"(gmem));
}
__device__ __forceinline__ void cp_async16z(void* smem, const void* gmem, int sz) {
    uint32_t s = (uint32_t)__cvta_generic_to_shared(smem);
    asm volatile("cp.async.cg.shared.global [%0], [%1], 16, %2;\n" :: "r"(s), "l"(gmem), "r"(sz));
}
__device__ __forceinline__ void cp_commit() { asm volatile("cp.async.commit_group;\n"); }
template <int Nk>
__device__ __forceinline__ void cp_wait() { asm volatile("cp.async.wait_group %0;\n" :: "n"(Nk)); }

#define MMA_TF32(acc, af, bf)                                                     \
    asm volatile(                                                                 \
        "mma.sync.aligned.m16n8k8.row.col.f32.tf32.tf32.f32 "                     \
        "{%0,%1,%2,%3}, {%4,%5,%6,%7}, {%8,%9}, {%0,%1,%2,%3};\n"                 \
        : "+f"(acc[0]), "+f"(acc[1]), "+f"(acc[2]), "+f"(acc[3])                  \
        : "r"(af[0]), "r"(af[1]), "r"(af[2]), "r"(af[3]), "r"(bf[0]), "r"(bf[1]))

#define MMA_F16(acc, af, bf)                                                      \
    asm volatile(                                                                 \
        "mma.sync.aligned.m16n8k16.row.col.f32.f16.f16.f32 "                      \
        "{%0,%1,%2,%3}, {%4,%5,%6,%7}, {%8,%9}, {%0,%1,%2,%3};\n"                 \
        : "+f"(acc[0]), "+f"(acc[1]), "+f"(acc[2]), "+f"(acc[3])                  \
        : "r"(af[0]), "r"(af[1]), "r"(af[2]), "r"(af[3]), "r"(bf[0]), "r"(bf[1]))

// ---------------- elementwise: fp32 -> half ----------------
__global__ void k_round_h(const float* __restrict__ a, __half* __restrict__ o, int n) {
    int i = blockIdx.x * blockDim.x + threadIdx.x;
    if (i < n) o[i] = __float2half_rn(a[i]);
}

// ---------------- modulation ----------------
__global__ void k_mod(const float* __restrict__ t, const float* __restrict__ sst,
                      float* __restrict__ t6) {
    int i = blockIdx.x * blockDim.x + threadIdx.x;
    if (i < CB * 6 * CC) t6[i] = sst[i % (6 * CC)] + t[i];
}

// ---------------- LayerNorm + modulate (half output) ----------------
__global__ void k_ln_mod(const float* __restrict__ X, const float* __restrict__ t6,
                         __half* __restrict__ out, int shiftIdx, int scaleIdx) {
    int r = blockIdx.x;
    int b = r >> 12;
    const float* xr = X + (size_t)r * CC;
    const float* sh = t6 + (size_t)(b * 6 + shiftIdx) * CC;
    const float* scl = t6 + (size_t)(b * 6 + scaleIdx) * CC;

    float v[4];
    float s = 0.f, sq = 0.f;
#pragma unroll
    for (int i = 0; i < 4; i++) {
        int c = threadIdx.x + i * 288;
        v[i] = xr[c];
        s += v[i];
        sq += v[i] * v[i];
    }
    __shared__ float s1[9], s2[9], bc[2];
    int lane = threadIdx.x & 31, wid = threadIdx.x >> 5;
#pragma unroll
    for (int off = 16; off > 0; off >>= 1) {
        s += __shfl_xor_sync(0xffffffffu, s, off);
        sq += __shfl_xor_sync(0xffffffffu, sq, off);
    }
    if (lane == 0) { s1[wid] = s; s2[wid] = sq; }
    __syncthreads();
    if (threadIdx.x == 0) {
        float ts = 0.f, tq = 0.f;
        for (int w = 0; w < 9; w++) { ts += s1[w]; tq += s2[w]; }
        float mean = ts * (1.f / CC);
        float var = tq * (1.f / CC) - mean * mean;
        bc[0] = mean;
        bc[1] = rsqrtf(var + 1e-6f);
    }
    __syncthreads();
    float mean = bc[0], rstd = bc[1];
    __half* orow = out + (size_t)r * CC;
#pragma unroll
    for (int i = 0; i < 4; i++) {
        int c = threadIdx.x + i * 288;
        orow[c] = __float2half_rn((v[i] - mean) * rstd * (1.f + scl[c]) + sh[c]);
    }
}

// ================= fp16 dense GEMM =================
// C[M,N] = A[M,K]h @ W[N,K]h^T + bias; fp32 accum, m16n8k16.
// 128x128x32 tile, 4-stage cp.async, 64x32 warp tiles.
// OP: 0 = half store, 1 = fp32 rounded-tf32 store, 2 = gelu+half store,
//     3 = fp32 residual: C = resid + gate*(acc+bias)
#define HTBK 32
#define HSTR 40                       // halves per row (80 B, conflict-free)
#define HTSZ (128 * HSTR)             // halves per stage per operand
#define HSTG 4
#define HSMEM (HSTG * 2 * HTSZ * 2)   // bytes = 81920

template <int OP>
__global__ __launch_bounds__(256) void k_hgemm(const __half* __restrict__ A,
                                               const __half* __restrict__ W,
                                               const float* __restrict__ bias,
                                               void* __restrict__ Cout,
                                               const float* __restrict__ resid,
                                               const float* __restrict__ t6, int gi,
                                               int M, int Nn, int K) {
    extern __shared__ __half smh[];
    __half* As = smh;
    __half* Bs = smh + HSTG * HTSZ;

    const int tid = threadIdx.x;
    const int m0 = blockIdx.y * 128, n0 = blockIdx.x * 128;
    const int wid = tid >> 5, lane = tid & 31;
    const int wr = wid >> 2, wc = wid & 3;
    const int warp_m = wr * 64, warp_n = wc * 32;
    const int qr = lane >> 2, qc = lane & 3;

    float acc[4][4][4];
#pragma unroll
    for (int mi = 0; mi < 4; mi++)
#pragma unroll
        for (int ni = 0; ni < 4; ni++)
#pragma unroll
            for (int c = 0; c < 4; c++) acc[mi][ni][c] = 0.f;

    auto load_tile = [&](int stg, int kb) {
        __half* as = As + stg * HTSZ;
        __half* bs = Bs + stg * HTSZ;
#pragma unroll
        for (int i = 0; i < 2; i++) {
            int ch = tid + i * 256;          // 0..511
            int m = ch >> 2;
            int c8 = (ch & 3) * 8;           // half offset
            int gm = m0 + m; if (gm >= M) gm = M - 1;
            cp_async16(&as[m * HSTR + c8], A + (size_t)gm * K + kb + c8);
            cp_async16(&bs[m * HSTR + c8], W + (size_t)(n0 + m) * K + kb + c8);
        }
    };

    const int KT = K >> 5;
    load_tile(0, 0); cp_commit();
    load_tile(1, 32); cp_commit();
    load_tile(2, 64); cp_commit();

    for (int kt = 0; kt < KT; ++kt) {
        cp_wait<HSTG - 2>();
        __syncthreads();
        if (kt + HSTG - 1 < KT) load_tile((kt + HSTG - 1) % HSTG, (kt + HSTG - 1) << 5);
        cp_commit();

        const __half* as = As + (kt % HSTG) * HTSZ;
        const __half* bs = Bs + (kt % HSTG) * HTSZ;
#pragma unroll
        for (int kk = 0; kk < HTBK; kk += 16) {
            uint32_t af[4][4], bf[4][2];
#pragma unroll
            for (int mi = 0; mi < 4; mi++) {
                const __half* base = &as[(warp_m + mi * 16 + qr) * HSTR + kk + 2 * qc];
                af[mi][0] = *(const uint32_t*)(base);
                af[mi][1] = *(const uint32_t*)(base + 8 * HSTR);
                af[mi][2] = *(const uint32_t*)(base + 8);
                af[mi][3] = *(const uint32_t*)(base + 8 * HSTR + 8);
            }
#pragma unroll
            for (int ni = 0; ni < 4; ni++) {
                const __half* bb = &bs[(warp_n + ni * 8 + qr) * HSTR + kk + 2 * qc];
                bf[ni][0] = *(const uint32_t*)(bb);
                bf[ni][1] = *(const uint32_t*)(bb + 8);
            }
#pragma unroll
            for (int mi = 0; mi < 4; mi++)
#pragma unroll
                for (int ni = 0; ni < 4; ni++) MMA_F16(acc[mi][ni], af[mi], bf[ni]);
        }
        __syncthreads();
    }

    const int b = m0 >> 12;
    const float* gate = (OP == 3 && gi >= 0) ? t6 + (size_t)(b * 6 + gi) * CC : nullptr;

#pragma unroll
    for (int mi = 0; mi < 4; mi++) {
        int r0 = m0 + warp_m + mi * 16 + qr;
        int r1 = r0 + 8;
#pragma unroll
        for (int ni = 0; ni < 4; ni++) {
            int c0 = n0 + warp_n + ni * 8 + qc * 2;
            float b0 = bias[c0], b1 = bias[c0 + 1];
            float v[4] = {acc[mi][ni][0] + b0, acc[mi][ni][1] + b1,
                          acc[mi][ni][2] + b0, acc[mi][ni][3] + b1};
            if (OP == 2) {
#pragma unroll
                for (int c = 0; c < 4; c++) v[c] = gelu_tanh(v[c]);
            }
            if (OP == 0 || OP == 2) {
                __half* C = (__half*)Cout;
                if (r0 < M)
                    *(__half2*)(C + (size_t)r0 * Nn + c0) =
                        __halves2half2(__float2half_rn(v[0]), __float2half_rn(v[1]));
                if (r1 < M)
                    *(__half2*)(C + (size_t)r1 * Nn + c0) =
                        __halves2half2(__float2half_rn(v[2]), __float2half_rn(v[3]));
            } else if (OP == 1) {
                float* C = (float*)Cout;
                if (r0 < M) {
                    C[(size_t)r0 * Nn + c0] = rndtf(v[0]);
                    C[(size_t)r0 * Nn + c0 + 1] = rndtf(v[1]);
                }
                if (r1 < M) {
                    C[(size_t)r1 * Nn + c0] = rndtf(v[2]);
                    C[(size_t)r1 * Nn + c0 + 1] = rndtf(v[3]);
                }
            } else {  // OP == 3
                float* C = (float*)Cout;
                float g0 = gate ? gate[c0] : 1.f;
                float g1 = gate ? gate[c0 + 1] : 1.f;
                if (r0 < M) {
                    const float* rr = resid + (size_t)r0 * Nn;
                    float* cw = C + (size_t)r0 * Nn;
                    cw[c0] = rr[c0] + g0 * v[0];
                    cw[c0 + 1] = rr[c0 + 1] + g1 * v[1];
                }
                if (r1 < M) {
                    const float* rr = resid + (size_t)r1 * Nn;
                    float* cw = C + (size_t)r1 * Nn;
                    cw[c0] = rr[c0] + g0 * v[2];
                    cw[c0 + 1] = rr[c0 + 1] + g1 * v[3];
                }
            }
        }
    }
}

// ================= tf32 attention kernels (unchanged numerics) =================
#define TBK 16
#define ASTR 20
#define TBM 128
#define TBN 128

// ---------------- MMA scores (+ optional fused softmax) ----------------
template <int DOSM>
__global__ __launch_bounds__(256) void k_scores_mma(const float* __restrict__ Q,
                                                    const float* __restrict__ Kd,
                                                    float* __restrict__ out,
                                                    int heads, int Sq, int Sk,
                                                    int qRS, int kRS, long qBS, long kBS,
                                                    float scale) {
    __shared__ float As[2][TBM * ASTR];
    __shared__ float Bs[2][TBN * ASTR];
    __shared__ float red[128][4];

    const int tid = threadIdx.x;
    int z = blockIdx.z;
    int b = z / heads, h = z - b * heads;
    const float* qb = Q + (long)b * qBS + h * CHD;
    const float* kb = Kd + (long)b * kBS + h * CHD;
    const int i0 = blockIdx.y * TBM, j0 = blockIdx.x * TBN;
    const int wid = tid >> 5, lane = tid & 31;
    const int wr = wid >> 2, wc = wid & 3;
    const int warp_m = wr * 64, warp_n = wc * 32;
    const int qr = lane >> 2, qc = lane & 3;

    float acc[4][4][4];
#pragma unroll
    for (int mi = 0; mi < 4; mi++)
#pragma unroll
        for (int ni = 0; ni < 4; ni++)
#pragma unroll
            for (int c = 0; c < 4; c++) acc[mi][ni][c] = 0.f;

    auto load_tile = [&](int stg, int kbase) {
#pragma unroll
        for (int i = 0; i < 2; i++) {
            int ch = tid + i * 256;
            int m = ch >> 2;
            int k4 = (ch & 3) * 4;
            int sz = (kbase + k4 + 4 <= CHD) ? 16 : 0;
            int gq = i0 + m; if (gq >= Sq) gq = Sq - 1;
            int gk = j0 + m; if (gk >= Sk) gk = Sk - 1;
            cp_async16z(&As[stg][m * ASTR + k4], qb + (long)gq * qRS + kbase + k4, sz);
            cp_async16z(&Bs[stg][m * ASTR + k4], kb + (long)gk * kRS + kbase + k4, sz);
        }
    };

    const int KT = 5;
    load_tile(0, 0);
    cp_commit();

    for (int kt = 0; kt < KT; ++kt) {
        int cur = kt & 1;
        if (kt + 1 < KT) {
            load_tile(1 - cur, (kt + 1) << 4);
            cp_commit();
            cp_wait<1>();
        } else {
            cp_wait<0>();
        }
        __syncthreads();

#pragma unroll
        for (int kk = 0; kk < TBK; kk += 8) {
            uint32_t af[4][4], bf[4][2];
#pragma unroll
            for (int mi = 0; mi < 4; mi++) {
                const float* base = &As[cur][(warp_m + mi * 16 + qr) * ASTR + kk + qc];
                af[mi][0] = __float_as_uint(base[0]);
                af[mi][1] = __float_as_uint(base[8 * ASTR]);
                af[mi][2] = __float_as_uint(base[4]);
                af[mi][3] = __float_as_uint(base[8 * ASTR + 4]);
            }
#pragma unroll
            for (int ni = 0; ni < 4; ni++) {
                const float* base = &Bs[cur][(warp_n + ni * 8 + qr) * ASTR + kk + qc];
                bf[ni][0] = __float_as_uint(base[0]);
                bf[ni][1] = __float_as_uint(base[4]);
            }
#pragma unroll
            for (int mi = 0; mi < 4; mi++)
#pragma unroll
                for (int ni = 0; ni < 4; ni++) MMA_TF32(acc[mi][ni], af[mi], bf[ni]);
        }
        __syncthreads();
    }

    float* ob = out + (long)z * Sq * Sk;

    if (DOSM == 0) {
#pragma unroll
        for (int mi = 0; mi < 4; mi++) {
            int r0 = i0 + warp_m + mi * 16 + qr;
            int r1 = r0 + 8;
#pragma unroll
            for (int ni = 0; ni < 4; ni++) {
                int c0 = j0 + warp_n + ni * 8 + qc * 2;
                if (c0 < Sk) {
                    if (r0 < Sq) ob[(long)r0 * Sk + c0] = acc[mi][ni][0] * scale;
                    if (r1 < Sq) ob[(long)r1 * Sk + c0] = acc[mi][ni][2] * scale;
                }
                if (c0 + 1 < Sk) {
                    if (r0 < Sq) ob[(long)r0 * Sk + c0 + 1] = acc[mi][ni][1] * scale;
                    if (r1 < Sq) ob[(long)r1 * Sk + c0 + 1] = acc[mi][ni][3] * scale;
                }
            }
        }
        return;
    }

    // ---- fused row softmax (grid.x == 1, Sk <= 128) ----
#pragma unroll
    for (int mi = 0; mi < 4; mi++)
#pragma unroll
        for (int ni = 0; ni < 4; ni++)
#pragma unroll
            for (int c = 0; c < 4; c++) acc[mi][ni][c] *= scale;

    float mrow[4][2], srow[4][2];
#pragma unroll
    for (int mi = 0; mi < 4; mi++)
#pragma unroll
        for (int hf = 0; hf < 2; hf++) {
            float m = -FLT_MAX;
#pragma unroll
            for (int ni = 0; ni < 4; ni++) {
                int c0 = warp_n + ni * 8 + qc * 2;
                if (c0 < Sk) m = fmaxf(m, acc[mi][ni][hf * 2]);
                if (c0 + 1 < Sk) m = fmaxf(m, acc[mi][ni][hf * 2 + 1]);
            }
            m = fmaxf(m, __shfl_xor_sync(0xffffffffu, m, 1));
            m = fmaxf(m, __shfl_xor_sync(0xffffffffu, m, 2));
            if (qc == 0) red[warp_m + mi * 16 + qr + hf * 8][wc] = m;
            mrow[mi][hf] = m;
        }
    __syncthreads();
#pragma unroll
    for (int mi = 0; mi < 4; mi++)
#pragma unroll
        for (int hf = 0; hf < 2; hf++) {
            int rl = warp_m + mi * 16 + qr + hf * 8;
            mrow[mi][hf] = fmaxf(fmaxf(red[rl][0], red[rl][1]), fmaxf(red[rl][2], red[rl][3]));
        }
    __syncthreads();
#pragma unroll
    for (int mi = 0; mi < 4; mi++)
#pragma unroll
        for (int hf = 0; hf < 2; hf++) {
            float s = 0.f;
#pragma unroll
            for (int ni = 0; ni < 4; ni++) {
                int c0 = warp_n + ni * 8 + qc * 2;
                float e0 = (c0 < Sk) ? expf(acc[mi][ni][hf * 2] - mrow[mi][hf]) : 0.f;
                float e1 = (c0 + 1 < Sk) ? expf(acc[mi][ni][hf * 2 + 1] - mrow[mi][hf]) : 0.f;
                acc[mi][ni][hf * 2] = e0;
                acc[mi][ni][hf * 2 + 1] = e1;
                s += e0 + e1;
            }
            s += __shfl_xor_sync(0xffffffffu, s, 1);
            s += __shfl_xor_sync(0xffffffffu, s, 2);
            if (qc == 0) red[warp_m + mi * 16 + qr + hf * 8][wc] = s;
        }
    __syncthreads();
#pragma unroll
    for (int mi = 0; mi < 4; mi++)
#pragma unroll
        for (int hf = 0; hf < 2; hf++) {
            int rl = warp_m + mi * 16 + qr + hf * 8;
            srow[mi][hf] = 1.f / (red[rl][0] + red[rl][1] + red[rl][2] + red[rl][3]);
        }
#pragma unroll
    for (int mi = 0; mi < 4; mi++) {
        int r0 = i0 + warp_m + mi * 16 + qr;
        int r1 = r0 + 8;
#pragma unroll
        for (int ni = 0; ni < 4; ni++) {
            int c0 = warp_n + ni * 8 + qc * 2;
            if (c0 < Sk) {
                ob[(long)r0 * Sk + c0] = rndtf(acc[mi][ni][0] * srow[mi][0]);
                ob[(long)r1 * Sk + c0] = rndtf(acc[mi][ni][2] * srow[mi][1]);
            }
            if (c0 + 1 < Sk) {
                ob[(long)r0 * Sk + c0 + 1] = rndtf(acc[mi][ni][1] * srow[mi][0]);
                ob[(long)r1 * Sk + c0 + 1] = rndtf(acc[mi][ni][3] * srow[mi][1]);
            }
        }
    }
}

// ---------------- MMA attn@V (tf32, half output) ----------------
#define VSTR 72
__global__ __launch_bounds__(256) void k_av_mma(const float* __restrict__ P,
                                                const float* __restrict__ V,
                                                __half* __restrict__ O,
                                                int heads, int Sq, int Sk,
                                                int vRS, long vBS, int oRS, long oBS) {
    __shared__ float As[2][TBM * ASTR];
    __shared__ float Bs[2][16 * VSTR];

    const int tid = threadIdx.x;
    int z = blockIdx.y;
    int b = z / heads, h = z - b * heads;
    const float* Pb = P + (long)z * Sq * Sk;
    const float* Vb = V + (long)b * vBS + h * CHD;
    __half* Ob = O + (long)b * oBS + h * CHD;
    const int i0 = blockIdx.x * TBM;
    const int wid = tid >> 5, lane = tid & 31;
    const int warp_m = wid * 16;
    const int qr = lane >> 2, qc = lane & 3;

    float acc[9][4];
#pragma unroll
    for (int nt = 0; nt < 9; nt++)
#pragma unroll
        for (int c = 0; c < 4; c++) acc[nt][c] = 0.f;

    auto load_tile = [&](int stg, int kb) {
#pragma unroll
        for (int i = 0; i < 2; i++) {
            int ch = tid + i * 256;
            int m = ch >> 2;
            int k4 = (ch & 3) * 4;
            int sz = (kb + k4 + 4 <= Sk) ? 16 : 0;
            int gi = i0 + m; if (gi >= Sq) gi = Sq - 1;
            cp_async16z(&As[stg][m * ASTR + k4], Pb + (long)gi * Sk + kb + k4, sz);
        }
#pragma unroll
        for (int i = 0; i < 2; i++) {
            int ch = tid + i * 256;
            if (ch < 288) {
                int r = ch / 18;
                int c4 = (ch - r * 18) * 4;
                int sz = (kb + r < Sk) ? 16 : 0;
                cp_async16z(&Bs[stg][r * VSTR + c4], Vb + (long)(kb + r) * vRS + c4, sz);
            }
        }
    };

    const int KT = (Sk + 15) >> 4;
    load_tile(0, 0);
    cp_commit();

    for (int kt = 0; kt < KT; ++kt) {
        int cur = kt & 1;
        if (kt + 1 < KT) {
            load_tile(1 - cur, (kt + 1) << 4);
            cp_commit();
            cp_wait<1>();
        } else {
            cp_wait<0>();
        }
        __syncthreads();

#pragma unroll
        for (int kk = 0; kk < 16; kk += 8) {
            uint32_t af[4];
            const float* abase = &As[cur][(warp_m + qr) * ASTR + kk + qc];
            af[0] = __float_as_uint(abase[0]);
            af[1] = __float_as_uint(abase[8 * ASTR]);
            af[2] = __float_as_uint(abase[4]);
            af[3] = __float_as_uint(abase[8 * ASTR + 4]);
#pragma unroll
            for (int nt = 0; nt < 9; nt++) {
                uint32_t bf[2];
                bf[0] = __float_as_uint(Bs[cur][(kk + qc) * VSTR + nt * 8 + qr]);
                bf[1] = __float_as_uint(Bs[cur][(kk + qc + 4) * VSTR + nt * 8 + qr]);
                MMA_TF32(acc[nt], af, bf);
            }
        }
        __syncthreads();
    }

    int r0 = i0 + warp_m + qr;
    int r1 = r0 + 8;
#pragma unroll
    for (int nt = 0; nt < 9; nt++) {
        int c0 = nt * 8 + qc * 2;
        if (r0 < Sq)
            *(__half2*)(Ob + (long)r0 * oRS + c0) =
                __halves2half2(__float2half_rn(acc[nt][0]), __float2half_rn(acc[nt][1]));
        if (r1 < Sq)
            *(__half2*)(Ob + (long)r1 * oRS + c0) =
                __halves2half2(__float2half_rn(acc[nt][2]), __float2half_rn(acc[nt][3]));
    }
}

// ---------------- softmax (spatial, tf32-rounded output) ----------------
__global__ void k_softmax(float* __restrict__ sc, int L, int Sq, int causal) {
    long row = blockIdx.x;
    float* p = sc + row * (long)L;
    int i = (int)(row % Sq);
    int tid = threadIdx.x;
    int j0 = tid, j1 = tid + 128;

    float a0 = -FLT_MAX, a1 = -FLT_MAX;
    if (j0 < L) { a0 = p[j0]; if (causal && j0 > i) a0 = -FLT_MAX; }
    if (j1 < L) { a1 = p[j1]; if (causal && j1 > i) a1 = -FLT_MAX; }

    __shared__ float red[4];
    float m = fmaxf(a0, a1);
#pragma unroll
    for (int off = 16; off > 0; off >>= 1) m = fmaxf(m, __shfl_xor_sync(0xffffffffu, m, off));
    if ((tid & 31) == 0) red[tid >> 5] = m;
    __syncthreads();
    m = fmaxf(fmaxf(red[0], red[1]), fmaxf(red[2], red[3]));
    __syncthreads();

    float e0 = (j0 < L) ? expf(a0 - m) : 0.f;
    float e1 = (j1 < L) ? expf(a1 - m) : 0.f;
    float s = e0 + e1;
#pragma unroll
    for (int off = 16; off > 0; off >>= 1) s += __shfl_xor_sync(0xffffffffu, s, off);
    if ((tid & 31) == 0) red[tid >> 5] = s;
    __syncthreads();
    s = red[0] + red[1] + red[2] + red[3];
    float inv = 1.f / s;
    if (j0 < L) p[j0] = rndtf(e0 * inv);
    if (j1 < L) p[j1] = rndtf(e1 * inv);
}

// ---------------- fused temporal attention (T=16, causal; half in/out) -------
__global__ __launch_bounds__(128) void k_attn_t(const __half* __restrict__ qkv,
                                                __half* __restrict__ O, float scale) {
    __shared__ float q[16][72], k[16][72], v[16][72], p[16][17];
    int h = blockIdx.x;
    int bs = blockIdx.y;
    const __half* base = qkv + (size_t)bs * CT * 3 * CC + h * CHD;
    int tid = threadIdx.x;

    for (int idx = tid; idx < 16 * 72; idx += 128) {
        int t = idx / 72, d = idx - t * 72;
        const __half* row = base + (size_t)t * 3 * CC;
        q[t][d] = __half2float(row[d]);
        k[t][d] = __half2float(row[CC + d]);
        v[t][d] = __half2float(row[2 * CC + d]);
    }
    __syncthreads();

    for (int e = tid; e < 256; e += 128) {
        int i = e >> 4, j = e & 15;
        float acc = 0.f;
#pragma unroll 8
        for (int d = 0; d < 72; d++) acc += q[i][d] * k[j][d];
        p[i][j] = acc * scale;
    }
    __syncthreads();

    if (tid < 16) {
        int i = tid;
        float m = -FLT_MAX;
        for (int j = 0; j <= i; j++) m = fmaxf(m, p[i][j]);
        float s = 0.f;
        for (int j = 0; j <= i; j++) { float e = expf(p[i][j] - m); p[i][j] = e; s += e; }
        float inv = 1.f / s;
        for (int j = 0; j <= i; j++) p[i][j] *= inv;
        for (int j = i + 1; j < 16; j++) p[i][j] = 0.f;
    }
    __syncthreads();

    for (int e = tid; e < 16 * 72; e += 128) {
        int t = e / 72, d = e - t * 72;
        float acc = 0.f;
#pragma unroll
        for (int j = 0; j < 16; j++) acc += p[t][j] * v[j][d];
        O[((size_t)bs * CT + t) * CC + h * CHD + d] = __float2half_rn(acc);
    }
}

// ---------------- build temporal input (half out) ----------------
__global__ void k_xt_build(const float* __restrict__ X, const float* __restrict__ tpe,
                           __half* __restrict__ out) {
    int r = blockIdx.x;
    int t = r & 15;
    int bs = r >> 4;
    int s = bs & 255;
    int b = bs >> 8;
    const float* xr = X + ((size_t)b * CN + t * CS + s) * CC;
    const float* tp = tpe + (size_t)t * CC;
    __half* orow = out + (size_t)r * CC;
#pragma unroll
    for (int i = 0; i < 4; i++) {
        int c = threadIdx.x + i * 288;
        orow[c] = __float2half_rn(xr[c] + tp[c]);
    }
}

// ---------------- temporal residual scatter + half copy of X ----------------
__global__ void k_resadd_t(float* __restrict__ X, const __half* __restrict__ src,
                           const float* __restrict__ t6, int gi,
                           __half* __restrict__ xr_out) {
    int r = blockIdx.x;
    int b = r >> 12;
    int n = r & 4095;
    int t = n >> 8;
    int s = n & 255;
    long srow = ((long)(b * CS + s) * CT + t) * CC;
    float* xr = X + (size_t)r * CC;
    const __half* sr = src + srow;
    const float* gr = t6 + (size_t)(b * 6 + gi) * CC;
    __half* orow = xr_out + (size_t)r * CC;
#pragma unroll
    for (int i = 0; i < 4; i++) {
        int c = threadIdx.x + i * 288;
        float v = xr[c] + gr[c] * __half2float(sr[c]);
        xr[c] = v;
        orow[c] = __float2half_rn(v);
    }
}

// =======================================================================
extern "C" void kernel_launch(void* const* d_in, const int* in_sizes, int n_in,
                              void* d_out, int out_size) {
    const float* x      = (const float*)d_in[0];
    const float* y      = (const float*)d_in[1];
    const float* t      = (const float*)d_in[2];
    const float* tpe    = (const float*)d_in[3];
    const float* sst    = (const float*)d_in[4];
    const float* qkv_s_w = (const float*)d_in[5];
    const float* qkv_s_b = (const float*)d_in[6];
    const float* proj_s_w = (const float*)d_in[7];
    const float* proj_s_b = (const float*)d_in[8];
    const float* qkv_t_w = (const float*)d_in[9];
    const float* qkv_t_b = (const float*)d_in[10];
    const float* proj_t_w = (const float*)d_in[11];
    const float* proj_t_b = (const float*)d_in[12];
    const float* q_c_w  = (const float*)d_in[13];
    const float* q_c_b  = (const float*)d_in[14];
    const float* kv_c_w = (const float*)d_in[15];
    const float* kv_c_b = (const float*)d_in[16];
    const float* proj_c_w = (const float*)d_in[17];
    const float* proj_c_b = (const float*)d_in[18];
    const float* fc1_w  = (const float*)d_in[19];
    const float* fc1_b  = (const float*)d_in[20];
    const float* fc2_w  = (const float*)d_in[21];
    const float* fc2_b  = (const float*)d_in[22];
    float* X = (float*)d_out;

    float *p_t6, *p_xm, *p_qkv, *p_att, *p_h, *p_sc, *p_kv, *p_w, *p_yr;
    cudaGetSymbolAddress((void**)&p_t6, g_t6);
    cudaGetSymbolAddress((void**)&p_xm, g_xm);
    cudaGetSymbolAddress((void**)&p_qkv, g_qkv);
    cudaGetSymbolAddress((void**)&p_att, g_att);
    cudaGetSymbolAddress((void**)&p_h, g_h);
    cudaGetSymbolAddress((void**)&p_sc, g_sc);
    cudaGetSymbolAddress((void**)&p_kv, g_kv);
    cudaGetSymbolAddress((void**)&p_w, g_w);
    cudaGetSymbolAddress((void**)&p_yr, g_yr);

    // half-typed aliases
    __half* h_xm  = (__half*)p_xm;
    __half* h_qkv = (__half*)p_qkv;   // temporal phase only
    __half* h_att = (__half*)p_att;
    __half* h_h   = (__half*)p_h;
    __half* h_w   = (__half*)p_w;
    __half* h_yr  = (__half*)p_yr;

    const float scale = 0.11785113019775793f;  // 1/sqrt(72)

    static int attr_set = 0;
    if (!attr_set) {
        cudaFuncSetAttribute((const void*)k_hgemm<0>, cudaFuncAttributeMaxDynamicSharedMemorySize, HSMEM);
        cudaFuncSetAttribute((const void*)k_hgemm<1>, cudaFuncAttributeMaxDynamicSharedMemorySize, HSMEM);
        cudaFuncSetAttribute((const void*)k_hgemm<2>, cudaFuncAttributeMaxDynamicSharedMemorySize, HSMEM);
        cudaFuncSetAttribute((const void*)k_hgemm<3>, cudaFuncAttributeMaxDynamicSharedMemorySize, HSMEM);
        attr_set = 1;
    }

    // half weight copies
    __half* w_qkv_s = h_w + (size_t)0 * CC2;
    __half* w_proj_s = h_w + (size_t)3 * CC2;
    __half* w_qkv_t = h_w + (size_t)4 * CC2;
    __half* w_proj_t = h_w + (size_t)7 * CC2;
    __half* w_q_c   = h_w + (size_t)8 * CC2;
    __half* w_kv_c  = h_w + (size_t)9 * CC2;
    __half* w_proj_c = h_w + (size_t)11 * CC2;
    __half* w_fc1   = h_w + (size_t)12 * CC2;
    __half* w_fc2   = h_w + (size_t)16 * CC2;

    auto rnd = [&](const float* src, __half* dst, size_t n) {
        k_round_h<<<(int)((n + 255) / 256), 256>>>(src, dst, (int)n);
    };
    rnd(qkv_s_w, w_qkv_s, (size_t)3 * CC2);
    rnd(proj_s_w, w_proj_s, CC2);
    rnd(qkv_t_w, w_qkv_t, (size_t)3 * CC2);
    rnd(proj_t_w, w_proj_t, CC2);
    rnd(q_c_w, w_q_c, CC2);
    rnd(kv_c_w, w_kv_c, (size_t)2 * CC2);
    rnd(proj_c_w, w_proj_c, CC2);
    rnd(fc1_w, w_fc1, (size_t)4 * CC2);
    rnd(fc2_w, w_fc2, (size_t)4 * CC2);
    rnd(y, h_yr, (size_t)CB * CYL * CC);

    k_mod<<<(CB * 6 * CC + 255) / 256, 256>>>(t, sst, p_t6);

#define HG(OP, A, W, B, C, R, gi, M, Nn, K) \
    k_hgemm<OP><<<dim3((Nn) / 128, ((M) + 127) / 128), 256, HSMEM>>>(A, W, B, C, R, p_t6, gi, M, Nn, K)

    // ---- spatial attention ----
    k_ln_mod<<<NROW, 288>>>(x, p_t6, h_xm, 0, 1);
    HG(1, h_xm, w_qkv_s, qkv_s_b, p_qkv, nullptr, 0, NROW, 3 * CC, CC);   // fp32 tf32-rounded qkv
    k_scores_mma<0><<<dim3(2, 2, CB * CT * CNH), 256>>>(p_qkv, p_qkv + CC, p_sc, CNH, CS, CS,
                                                        3 * CC, 3 * CC,
                                                        (long)CS * 3 * CC, (long)CS * 3 * CC, scale);
    k_softmax<<<CB * CT * CNH * CS, 128>>>(p_sc, CS, CS, 0);
    k_av_mma<<<dim3(2, CB * CT * CNH), 256>>>(p_sc, p_qkv + 2 * CC, h_att, CNH, CS, CS,
                                              3 * CC, (long)CS * 3 * CC, CC, (long)CS * CC);
    HG(3, h_att, w_proj_s, proj_s_b, X, x, 2, NROW, CC, CC);  // X = x + gate_msa*proj

    // ---- temporal attention (causal, fused) ----
    k_xt_build<<<NROW, 288>>>(X, tpe, h_xm);
    HG(0, h_xm, w_qkv_t, qkv_t_b, h_qkv, nullptr, 0, NROW, 3 * CC, CC);   // half qkv
    k_attn_t<<<dim3(CNH, CB * CS), 128>>>(h_qkv, h_att, scale);
    HG(0, h_att, w_proj_t, proj_t_b, h_xm, nullptr, 0, NROW, CC, CC);
    k_resadd_t<<<NROW, 288>>>(X, h_xm, p_t6, 2, h_h);         // h_h = half X copy

    // ---- cross attention ----
    HG(1, h_h, w_q_c, q_c_b, p_qkv, nullptr, 0, NROW, CC, CC);            // fp32 q
    HG(1, h_yr, w_kv_c, kv_c_b, p_kv, nullptr, 0, CB * CYL, 2 * CC, CC);  // fp32 kv
    k_scores_mma<1><<<dim3(1, CN / TBM, CB * CNH), 256>>>(p_qkv, p_kv, p_sc, CNH, CN, CYL,
                                                          CC, 2 * CC,
                                                          (long)CN * CC, (long)CYL * 2 * CC, scale);
    k_av_mma<<<dim3(CN / TBM, CB * CNH), 256>>>(p_sc, p_kv + CC, h_att, CNH, CN, CYL,
                                                2 * CC, (long)CYL * 2 * CC, CC, (long)CN * CC);
    HG(3, h_att, w_proj_c, proj_c_b, X, X, -1, NROW, CC, CC); // X += proj

    // ---- MLP ----
    k_ln_mod<<<NROW, 288>>>(X, p_t6, h_xm, 3, 4);
    HG(2, h_xm, w_fc1, fc1_b, h_h, nullptr, 0, NROW, 4 * CC, CC);         // gelu, half
    HG(3, h_h, w_fc2, fc2_b, X, X, 5, NROW, CC, 4 * CC);      // X += gate_mlp*fc2
}

// round 9
// speedup vs baseline: 1.9174x; 1.0307x over previous
#include <cuda_runtime.h>
#include <cuda_fp16.h>
#include <math.h>
#include <float.h>
#include <stdint.h>

// ---------------- problem constants ----------------
#define CB   4
#define CT   16
#define CS   256
#define CN   4096
#define CC   1152
#define CNH  16
#define CHD  72
#define CYL  120
#define NROW 16384
#define CC2  (CC * CC)

// ---------------- scratch (device globals) ----------------
__device__ float g_t6[CB * 6 * CC];
__device__ float g_xm[(size_t)NROW * CC];
__device__ float g_qkv[(size_t)NROW * 3 * CC];
__device__ float g_att[(size_t)NROW * CC];
__device__ float g_h[(size_t)NROW * 4 * CC];
__device__ float g_sc[67108864UL];
__device__ float g_kv[CB * CYL * 2 * CC];
__device__ float g_w[20 * CC2];                 // half weights (aliased)
__device__ float g_yr[CB * CYL * CC];           // half y (aliased)

// ---------------- helpers ----------------
__device__ __forceinline__ float gelu_tanh(float x) {
    float x3 = x * x * x;
    return 0.5f * x * (1.f + tanhf(0.7978845608028654f * (x + 0.044715f * x3)));
}

__device__ __forceinline__ void cp_async16(void* smem, const void* gmem) {
    uint32_t s = (uint32_t)__cvta_generic_to_shared(smem);
    asm volatile("cp.async.cg.shared.global [%0], [%1], 16;\n" :: "r"(s), "l"(gmem));
}
__device__ __forceinline__ void cp_async16z(void* smem, const void* gmem, int sz) {
    uint32_t s = (uint32_t)__cvta_generic_to_shared(smem);
    asm volatile("cp.async.cg.shared.global [%0], [%1], 16, %2;\n" :: "r"(s), "l"(gmem), "r"(sz));
}
__device__ __forceinline__ void cp_commit() { asm volatile("cp.async.commit_group;\n"); }
template <int Nk>
__device__ __forceinline__ void cp_wait() { asm volatile("cp.async.wait_group %0;\n" :: "n"(Nk)); }

#define MMA_F16(acc, af, bf)                                                      \
    asm volatile(                                                                 \
        "mma.sync.aligned.m16n8k16.row.col.f32.f16.f16.f32 "                      \
        "{%0,%1,%2,%3}, {%4,%5,%6,%7}, {%8,%9}, {%0,%1,%2,%3};\n"                 \
        : "+f"(acc[0]), "+f"(acc[1]), "+f"(acc[2]), "+f"(acc[3])                  \
        : "r"(af[0]), "r"(af[1]), "r"(af[2]), "r"(af[3]), "r"(bf[0]), "r"(bf[1]))

// ---------------- elementwise: fp32 -> half ----------------
__global__ void k_round_h(const float* __restrict__ a, __half* __restrict__ o, int n) {
    int i = blockIdx.x * blockDim.x + threadIdx.x;
    if (i < n) o[i] = __float2half_rn(a[i]);
}

// ---------------- modulation ----------------
__global__ void k_mod(const float* __restrict__ t, const float* __restrict__ sst,
                      float* __restrict__ t6) {
    int i = blockIdx.x * blockDim.x + threadIdx.x;
    if (i < CB * 6 * CC) t6[i] = sst[i % (6 * CC)] + t[i];
}

// ---------------- LayerNorm + modulate (half output) ----------------
__global__ void k_ln_mod(const float* __restrict__ X, const float* __restrict__ t6,
                         __half* __restrict__ out, int shiftIdx, int scaleIdx) {
    int r = blockIdx.x;
    int b = r >> 12;
    const float* xr = X + (size_t)r * CC;
    const float* sh = t6 + (size_t)(b * 6 + shiftIdx) * CC;
    const float* scl = t6 + (size_t)(b * 6 + scaleIdx) * CC;

    float v[4];
    float s = 0.f, sq = 0.f;
#pragma unroll
    for (int i = 0; i < 4; i++) {
        int c = threadIdx.x + i * 288;
        v[i] = xr[c];
        s += v[i];
        sq += v[i] * v[i];
    }
    __shared__ float s1[9], s2[9], bc[2];
    int lane = threadIdx.x & 31, wid = threadIdx.x >> 5;
#pragma unroll
    for (int off = 16; off > 0; off >>= 1) {
        s += __shfl_xor_sync(0xffffffffu, s, off);
        sq += __shfl_xor_sync(0xffffffffu, sq, off);
    }
    if (lane == 0) { s1[wid] = s; s2[wid] = sq; }
    __syncthreads();
    if (threadIdx.x == 0) {
        float ts = 0.f, tq = 0.f;
        for (int w = 0; w < 9; w++) { ts += s1[w]; tq += s2[w]; }
        float mean = ts * (1.f / CC);
        float var = tq * (1.f / CC) - mean * mean;
        bc[0] = mean;
        bc[1] = rsqrtf(var + 1e-6f);
    }
    __syncthreads();
    float mean = bc[0], rstd = bc[1];
    __half* orow = out + (size_t)r * CC;
#pragma unroll
    for (int i = 0; i < 4; i++) {
        int c = threadIdx.x + i * 288;
        orow[c] = __float2half_rn((v[i] - mean) * rstd * (1.f + scl[c]) + sh[c]);
    }
}

// ================= fp16 dense GEMM =================
#define HTBK 32
#define HSTR 40
#define HTSZ (128 * HSTR)
#define HSTG 4
#define HSMEM (HSTG * 2 * HTSZ * 2)

template <int OP>
__global__ __launch_bounds__(256) void k_hgemm(const __half* __restrict__ A,
                                               const __half* __restrict__ W,
                                               const float* __restrict__ bias,
                                               void* __restrict__ Cout,
                                               const float* __restrict__ resid,
                                               const float* __restrict__ t6, int gi,
                                               int M, int Nn, int K) {
    extern __shared__ __half smh[];
    __half* As = smh;
    __half* Bs = smh + HSTG * HTSZ;

    const int tid = threadIdx.x;
    const int m0 = blockIdx.y * 128, n0 = blockIdx.x * 128;
    const int wid = tid >> 5, lane = tid & 31;
    const int wr = wid >> 2, wc = wid & 3;
    const int warp_m = wr * 64, warp_n = wc * 32;
    const int qr = lane >> 2, qc = lane & 3;

    float acc[4][4][4];
#pragma unroll
    for (int mi = 0; mi < 4; mi++)
#pragma unroll
        for (int ni = 0; ni < 4; ni++)
#pragma unroll
            for (int c = 0; c < 4; c++) acc[mi][ni][c] = 0.f;

    auto load_tile = [&](int stg, int kb) {
        __half* as = As + stg * HTSZ;
        __half* bs = Bs + stg * HTSZ;
#pragma unroll
        for (int i = 0; i < 2; i++) {
            int ch = tid + i * 256;
            int m = ch >> 2;
            int c8 = (ch & 3) * 8;
            int gm = m0 + m; if (gm >= M) gm = M - 1;
            cp_async16(&as[m * HSTR + c8], A + (size_t)gm * K + kb + c8);
            cp_async16(&bs[m * HSTR + c8], W + (size_t)(n0 + m) * K + kb + c8);
        }
    };

    const int KT = K >> 5;
    load_tile(0, 0); cp_commit();
    load_tile(1, 32); cp_commit();
    load_tile(2, 64); cp_commit();

    for (int kt = 0; kt < KT; ++kt) {
        cp_wait<HSTG - 2>();
        __syncthreads();
        if (kt + HSTG - 1 < KT) load_tile((kt + HSTG - 1) % HSTG, (kt + HSTG - 1) << 5);
        cp_commit();

        const __half* as = As + (kt % HSTG) * HTSZ;
        const __half* bs = Bs + (kt % HSTG) * HTSZ;
#pragma unroll
        for (int kk = 0; kk < HTBK; kk += 16) {
            uint32_t af[4][4], bf[4][2];
#pragma unroll
            for (int mi = 0; mi < 4; mi++) {
                const __half* base = &as[(warp_m + mi * 16 + qr) * HSTR + kk + 2 * qc];
                af[mi][0] = *(const uint32_t*)(base);
                af[mi][1] = *(const uint32_t*)(base + 8 * HSTR);
                af[mi][2] = *(const uint32_t*)(base + 8);
                af[mi][3] = *(const uint32_t*)(base + 8 * HSTR + 8);
            }
#pragma unroll
            for (int ni = 0; ni < 4; ni++) {
                const __half* bb = &bs[(warp_n + ni * 8 + qr) * HSTR + kk + 2 * qc];
                bf[ni][0] = *(const uint32_t*)(bb);
                bf[ni][1] = *(const uint32_t*)(bb + 8);
            }
#pragma unroll
            for (int mi = 0; mi < 4; mi++)
#pragma unroll
                for (int ni = 0; ni < 4; ni++) MMA_F16(acc[mi][ni], af[mi], bf[ni]);
        }
        __syncthreads();
    }

    const int b = m0 >> 12;
    const float* gate = (OP == 3 && gi >= 0) ? t6 + (size_t)(b * 6 + gi) * CC : nullptr;

#pragma unroll
    for (int mi = 0; mi < 4; mi++) {
        int r0 = m0 + warp_m + mi * 16 + qr;
        int r1 = r0 + 8;
#pragma unroll
        for (int ni = 0; ni < 4; ni++) {
            int c0 = n0 + warp_n + ni * 8 + qc * 2;
            float b0 = bias[c0], b1 = bias[c0 + 1];
            float v[4] = {acc[mi][ni][0] + b0, acc[mi][ni][1] + b1,
                          acc[mi][ni][2] + b0, acc[mi][ni][3] + b1};
            if (OP == 2) {
#pragma unroll
                for (int c = 0; c < 4; c++) v[c] = gelu_tanh(v[c]);
            }
            if (OP == 0 || OP == 2) {
                __half* C = (__half*)Cout;
                if (r0 < M)
                    *(__half2*)(C + (size_t)r0 * Nn + c0) =
                        __halves2half2(__float2half_rn(v[0]), __float2half_rn(v[1]));
                if (r1 < M)
                    *(__half2*)(C + (size_t)r1 * Nn + c0) =
                        __halves2half2(__float2half_rn(v[2]), __float2half_rn(v[3]));
            } else {  // OP == 3
                float* C = (float*)Cout;
                float g0 = gate ? gate[c0] : 1.f;
                float g1 = gate ? gate[c0 + 1] : 1.f;
                if (r0 < M) {
                    const float* rr = resid + (size_t)r0 * Nn;
                    float* cw = C + (size_t)r0 * Nn;
                    cw[c0] = rr[c0] + g0 * v[0];
                    cw[c0 + 1] = rr[c0 + 1] + g1 * v[1];
                }
                if (r1 < M) {
                    const float* rr = resid + (size_t)r1 * Nn;
                    float* cw = C + (size_t)r1 * Nn;
                    cw[c0] = rr[c0] + g0 * v[2];
                    cw[c0 + 1] = rr[c0 + 1] + g1 * v[3];
                }
            }
        }
    }
}

// ================= fp16 attention scores (K = 72, one-shot smem) =================
// DOSM=1: fused row softmax; requires gridDim.x == 1 and Sk <= 128.
#define SSTR 88   // halves per row (176 B, conflict-free)

template <int DOSM>
__global__ __launch_bounds__(256) void k_scores_h(const __half* __restrict__ Q,
                                                  const __half* __restrict__ Kd,
                                                  __half* __restrict__ out,
                                                  int heads, int Sq, int Sk,
                                                  int qRS, int kRS, long qBS, long kBS,
                                                  float scale) {
    __shared__ __half As[128 * SSTR];
    __shared__ __half Bs[128 * SSTR];
    __shared__ float red[128][4];

    const int tid = threadIdx.x;
    int z = blockIdx.z;
    int b = z / heads, h = z - b * heads;
    const __half* qb = Q + (long)b * qBS + h * CHD;
    const __half* kb = Kd + (long)b * kBS + h * CHD;
    const int i0 = blockIdx.y * 128, j0 = blockIdx.x * 128;
    const int wid = tid >> 5, lane = tid & 31;
    const int wr = wid >> 2, wc = wid & 3;
    const int warp_m = wr * 64, warp_n = wc * 32;
    const int qr = lane >> 2, qc = lane & 3;

    // one-shot load: 128 rows x 11 chunks of 8 halves (chunks 9,10 zero-filled)
    for (int idx = tid; idx < 128 * 11; idx += 256) {
        int m = idx / 11, c = idx - m * 11;
        int sz = (c < 9) ? 16 : 0;
        int gq = i0 + m; if (gq >= Sq) gq = Sq - 1;
        int gk = j0 + m; if (gk >= Sk) gk = Sk - 1;
        cp_async16z(&As[m * SSTR + c * 8], qb + (long)gq * qRS + c * 8, sz);
        cp_async16z(&Bs[m * SSTR + c * 8], kb + (long)gk * kRS + c * 8, sz);
    }
    cp_commit();
    cp_wait<0>();
    __syncthreads();

    float acc[4][4][4];
#pragma unroll
    for (int mi = 0; mi < 4; mi++)
#pragma unroll
        for (int ni = 0; ni < 4; ni++)
#pragma unroll
            for (int c = 0; c < 4; c++) acc[mi][ni][c] = 0.f;

#pragma unroll
    for (int kk = 0; kk < 80; kk += 16) {
        uint32_t af[4][4], bf[4][2];
#pragma unroll
        for (int mi = 0; mi < 4; mi++) {
            const __half* base = &As[(warp_m + mi * 16 + qr) * SSTR + kk + 2 * qc];
            af[mi][0] = *(const uint32_t*)(base);
            af[mi][1] = *(const uint32_t*)(base + 8 * SSTR);
            af[mi][2] = *(const uint32_t*)(base + 8);
            af[mi][3] = *(const uint32_t*)(base + 8 * SSTR + 8);
        }
#pragma unroll
        for (int ni = 0; ni < 4; ni++) {
            const __half* bb = &Bs[(warp_n + ni * 8 + qr) * SSTR + kk + 2 * qc];
            bf[ni][0] = *(const uint32_t*)(bb);
            bf[ni][1] = *(const uint32_t*)(bb + 8);
        }
#pragma unroll
        for (int mi = 0; mi < 4; mi++)
#pragma unroll
            for (int ni = 0; ni < 4; ni++) MMA_F16(acc[mi][ni], af[mi], bf[ni]);
    }

    __half* ob = out + (long)z * Sq * Sk;

    if (DOSM == 0) {
#pragma unroll
        for (int mi = 0; mi < 4; mi++) {
            int r0 = i0 + warp_m + mi * 16 + qr;
            int r1 = r0 + 8;
#pragma unroll
            for (int ni = 0; ni < 4; ni++) {
                int c0 = j0 + warp_n + ni * 8 + qc * 2;
                if (c0 + 1 < Sk || c0 < Sk) {
                    if (r0 < Sq)
                        *(__half2*)(ob + (long)r0 * Sk + c0) =
                            __halves2half2(__float2half_rn(acc[mi][ni][0] * scale),
                                           __float2half_rn(acc[mi][ni][1] * scale));
                    if (r1 < Sq)
                        *(__half2*)(ob + (long)r1 * Sk + c0) =
                            __halves2half2(__float2half_rn(acc[mi][ni][2] * scale),
                                           __float2half_rn(acc[mi][ni][3] * scale));
                }
            }
        }
        return;
    }

    // ---- fused row softmax (grid.x == 1, Sk <= 128) ----
#pragma unroll
    for (int mi = 0; mi < 4; mi++)
#pragma unroll
        for (int ni = 0; ni < 4; ni++)
#pragma unroll
            for (int c = 0; c < 4; c++) acc[mi][ni][c] *= scale;

    float mrow[4][2], srow[4][2];
#pragma unroll
    for (int mi = 0; mi < 4; mi++)
#pragma unroll
        for (int hf = 0; hf < 2; hf++) {
            float m = -FLT_MAX;
#pragma unroll
            for (int ni = 0; ni < 4; ni++) {
                int c0 = warp_n + ni * 8 + qc * 2;
                if (c0 < Sk) m = fmaxf(m, acc[mi][ni][hf * 2]);
                if (c0 + 1 < Sk) m = fmaxf(m, acc[mi][ni][hf * 2 + 1]);
            }
            m = fmaxf(m, __shfl_xor_sync(0xffffffffu, m, 1));
            m = fmaxf(m, __shfl_xor_sync(0xffffffffu, m, 2));
            if (qc == 0) red[warp_m + mi * 16 + qr + hf * 8][wc] = m;
        }
    __syncthreads();
#pragma unroll
    for (int mi = 0; mi < 4; mi++)
#pragma unroll
        for (int hf = 0; hf < 2; hf++) {
            int rl = warp_m + mi * 16 + qr + hf * 8;
            mrow[mi][hf] = fmaxf(fmaxf(red[rl][0], red[rl][1]), fmaxf(red[rl][2], red[rl][3]));
        }
    __syncthreads();
#pragma unroll
    for (int mi = 0; mi < 4; mi++)
#pragma unroll
        for (int hf = 0; hf < 2; hf++) {
            float s = 0.f;
#pragma unroll
            for (int ni = 0; ni < 4; ni++) {
                int c0 = warp_n + ni * 8 + qc * 2;
                float e0 = (c0 < Sk) ? expf(acc[mi][ni][hf * 2] - mrow[mi][hf]) : 0.f;
                float e1 = (c0 + 1 < Sk) ? expf(acc[mi][ni][hf * 2 + 1] - mrow[mi][hf]) : 0.f;
                acc[mi][ni][hf * 2] = e0;
                acc[mi][ni][hf * 2 + 1] = e1;
                s += e0 + e1;
            }
            s += __shfl_xor_sync(0xffffffffu, s, 1);
            s += __shfl_xor_sync(0xffffffffu, s, 2);
            if (qc == 0) red[warp_m + mi * 16 + qr + hf * 8][wc] = s;
        }
    __syncthreads();
#pragma unroll
    for (int mi = 0; mi < 4; mi++)
#pragma unroll
        for (int hf = 0; hf < 2; hf++) {
            int rl = warp_m + mi * 16 + qr + hf * 8;
            srow[mi][hf] = 1.f / (red[rl][0] + red[rl][1] + red[rl][2] + red[rl][3]);
        }
#pragma unroll
    for (int mi = 0; mi < 4; mi++) {
        int r0 = i0 + warp_m + mi * 16 + qr;
        int r1 = r0 + 8;
#pragma unroll
        for (int ni = 0; ni < 4; ni++) {
            int c0 = warp_n + ni * 8 + qc * 2;
            if (c0 < Sk) {
                *(__half2*)(ob + (long)r0 * Sk + c0) =
                    __halves2half2(__float2half_rn(acc[mi][ni][0] * srow[mi][0]),
                                   __float2half_rn(acc[mi][ni][1] * srow[mi][0]));
                *(__half2*)(ob + (long)r1 * Sk + c0) =
                    __halves2half2(__float2half_rn(acc[mi][ni][2] * srow[mi][1]),
                                   __float2half_rn(acc[mi][ni][3] * srow[mi][1]));
            }
        }
    }
}

// ================= fp16 attn@V =================
// O[z,i,d] = sum_j P[z,i,j] V[z,j,d]; V transposed into smem [d][key].
#define PSTR 24
__global__ __launch_bounds__(256) void k_av_h(const __half* __restrict__ P,
                                              const __half* __restrict__ V,
                                              __half* __restrict__ O,
                                              int heads, int Sq, int Sk,
                                              int vRS, long vBS, int oRS, long oBS) {
    __shared__ __half As[2][128 * PSTR];
    __shared__ __half Vs[2][72 * PSTR];

    const int tid = threadIdx.x;
    int z = blockIdx.y;
    int b = z / heads, h = z - b * heads;
    const __half* Pb = P + (long)z * Sq * Sk;
    const __half* Vb = V + (long)b * vBS + h * CHD;
    __half* Ob = O + (long)b * oBS + h * CHD;
    const int i0 = blockIdx.x * 128;
    const int wid = tid >> 5, lane = tid & 31;
    const int warp_m = wid * 16;
    const int qr = lane >> 2, qc = lane & 3;

    float acc[9][4];
#pragma unroll
    for (int nt = 0; nt < 9; nt++)
#pragma unroll
        for (int c = 0; c < 4; c++) acc[nt][c] = 0.f;

    auto load_tile = [&](int stg, int kb) {
        // P: 128 rows x 16 keys (2 chunks of 8 halves per row)
        for (int idx = tid; idx < 256; idx += 256) {
            int m = idx >> 1;
            int c = idx & 1;
            int sz = (kb + c * 8 + 8 <= Sk) ? 16 : 0;
            int gi = i0 + m; if (gi >= Sq) gi = Sq - 1;
            cp_async16z(&As[stg][m * PSTR + c * 8], Pb + (long)gi * Sk + kb + c * 8, sz);
        }
        // V transposed: 16 keys x 36 half2 -> Vs[d][key]
        for (int idx = tid; idx < 576; idx += 256) {
            int key = idx / 36, d2 = idx - key * 36;
            __half2 v = (kb + key < Sk)
                            ? *(const __half2*)(Vb + (long)(kb + key) * vRS + 2 * d2)
                            : __halves2half2(__float2half_rn(0.f), __float2half_rn(0.f));
            Vs[stg][(2 * d2) * PSTR + key] = __low2half(v);
            Vs[stg][(2 * d2 + 1) * PSTR + key] = __high2half(v);
        }
    };

    const int KT = (Sk + 15) >> 4;
    load_tile(0, 0);
    cp_commit();

    for (int kt = 0; kt < KT; ++kt) {
        int cur = kt & 1;
        if (kt + 1 < KT) {
            load_tile(1 - cur, (kt + 1) << 4);
            cp_commit();
            cp_wait<1>();
        } else {
            cp_wait<0>();
        }
        __syncthreads();

        uint32_t af[4];
        const __half* abase = &As[cur][(warp_m + qr) * PSTR + 2 * qc];
        af[0] = *(const uint32_t*)(abase);
        af[1] = *(const uint32_t*)(abase + 8 * PSTR);
        af[2] = *(const uint32_t*)(abase + 8);
        af[3] = *(const uint32_t*)(abase + 8 * PSTR + 8);
#pragma unroll
        for (int nt = 0; nt < 9; nt++) {
            uint32_t bf[2];
            const __half* bb = &Vs[cur][(nt * 8 + qr) * PSTR + 2 * qc];
            bf[0] = *(const uint32_t*)(bb);
            bf[1] = *(const uint32_t*)(bb + 8);
            MMA_F16(acc[nt], af, bf);
        }
        __syncthreads();
    }

    int r0 = i0 + warp_m + qr;
    int r1 = r0 + 8;
#pragma unroll
    for (int nt = 0; nt < 9; nt++) {
        int c0 = nt * 8 + qc * 2;
        if (r0 < Sq)
            *(__half2*)(Ob + (long)r0 * oRS + c0) =
                __halves2half2(__float2half_rn(acc[nt][0]), __float2half_rn(acc[nt][1]));
        if (r1 < Sq)
            *(__half2*)(Ob + (long)r1 * oRS + c0) =
                __halves2half2(__float2half_rn(acc[nt][2]), __float2half_rn(acc[nt][3]));
    }
}

// ---------------- spatial softmax on half (L = 256) ----------------
__global__ void k_softmax_h(__half* __restrict__ sc) {
    long row = blockIdx.x;
    __half2* p2 = (__half2*)(sc + row * 256);
    int tid = threadIdx.x;  // 128 threads, one half2 each

    float2 v = __half22float2(p2[tid]);
    __shared__ float red[4];
    float m = fmaxf(v.x, v.y);
#pragma unroll
    for (int off = 16; off > 0; off >>= 1) m = fmaxf(m, __shfl_xor_sync(0xffffffffu, m, off));
    if ((tid & 31) == 0) red[tid >> 5] = m;
    __syncthreads();
    m = fmaxf(fmaxf(red[0], red[1]), fmaxf(red[2], red[3]));
    __syncthreads();

    float e0 = expf(v.x - m), e1 = expf(v.y - m);
    float s = e0 + e1;
#pragma unroll
    for (int off = 16; off > 0; off >>= 1) s += __shfl_xor_sync(0xffffffffu, s, off);
    if ((tid & 31) == 0) red[tid >> 5] = s;
    __syncthreads();
    s = red[0] + red[1] + red[2] + red[3];
    float inv = 1.f / s;
    p2[tid] = __halves2half2(__float2half_rn(e0 * inv), __float2half_rn(e1 * inv));
}

// ---------------- fused temporal attention (T=16, causal; half in/out) -------
__global__ __launch_bounds__(128) void k_attn_t(const __half* __restrict__ qkv,
                                                __half* __restrict__ O, float scale) {
    __shared__ float q[16][72], k[16][72], v[16][72], p[16][17];
    int h = blockIdx.x;
    int bs = blockIdx.y;
    const __half* base = qkv + (size_t)bs * CT * 3 * CC + h * CHD;
    int tid = threadIdx.x;

    for (int idx = tid; idx < 16 * 72; idx += 128) {
        int t = idx / 72, d = idx - t * 72;
        const __half* row = base + (size_t)t * 3 * CC;
        q[t][d] = __half2float(row[d]);
        k[t][d] = __half2float(row[CC + d]);
        v[t][d] = __half2float(row[2 * CC + d]);
    }
    __syncthreads();

    for (int e = tid; e < 256; e += 128) {
        int i = e >> 4, j = e & 15;
        float acc = 0.f;
#pragma unroll 8
        for (int d = 0; d < 72; d++) acc += q[i][d] * k[j][d];
        p[i][j] = acc * scale;
    }
    __syncthreads();

    if (tid < 16) {
        int i = tid;
        float m = -FLT_MAX;
        for (int j = 0; j <= i; j++) m = fmaxf(m, p[i][j]);
        float s = 0.f;
        for (int j = 0; j <= i; j++) { float e = expf(p[i][j] - m); p[i][j] = e; s += e; }
        float inv = 1.f / s;
        for (int j = 0; j <= i; j++) p[i][j] *= inv;
        for (int j = i + 1; j < 16; j++) p[i][j] = 0.f;
    }
    __syncthreads();

    for (int e = tid; e < 16 * 72; e += 128) {
        int t = e / 72, d = e - t * 72;
        float acc = 0.f;
#pragma unroll
        for (int j = 0; j < 16; j++) acc += p[t][j] * v[j][d];
        O[((size_t)bs * CT + t) * CC + h * CHD + d] = __float2half_rn(acc);
    }
}

// ---------------- build temporal input (half out) ----------------
__global__ void k_xt_build(const float* __restrict__ X, const float* __restrict__ tpe,
                           __half* __restrict__ out) {
    int r = blockIdx.x;
    int t = r & 15;
    int bs = r >> 4;
    int s = bs & 255;
    int b = bs >> 8;
    const float* xr = X + ((size_t)b * CN + t * CS + s) * CC;
    const float* tp = tpe + (size_t)t * CC;
    __half* orow = out + (size_t)r * CC;
#pragma unroll
    for (int i = 0; i < 4; i++) {
        int c = threadIdx.x + i * 288;
        orow[c] = __float2half_rn(xr[c] + tp[c]);
    }
}

// ---------------- temporal residual scatter + half copy of X ----------------
__global__ void k_resadd_t(float* __restrict__ X, const __half* __restrict__ src,
                           const float* __restrict__ t6, int gi,
                           __half* __restrict__ xr_out) {
    int r = blockIdx.x;
    int b = r >> 12;
    int n = r & 4095;
    int t = n >> 8;
    int s = n & 255;
    long srow = ((long)(b * CS + s) * CT + t) * CC;
    float* xr = X + (size_t)r * CC;
    const __half* sr = src + srow;
    const float* gr = t6 + (size_t)(b * 6 + gi) * CC;
    __half* orow = xr_out + (size_t)r * CC;
#pragma unroll
    for (int i = 0; i < 4; i++) {
        int c = threadIdx.x + i * 288;
        float v = xr[c] + gr[c] * __half2float(sr[c]);
        xr[c] = v;
        orow[c] = __float2half_rn(v);
    }
}

// =======================================================================
extern "C" void kernel_launch(void* const* d_in, const int* in_sizes, int n_in,
                              void* d_out, int out_size) {
    const float* x      = (const float*)d_in[0];
    const float* y      = (const float*)d_in[1];
    const float* t      = (const float*)d_in[2];
    const float* tpe    = (const float*)d_in[3];
    const float* sst    = (const float*)d_in[4];
    const float* qkv_s_w = (const float*)d_in[5];
    const float* qkv_s_b = (const float*)d_in[6];
    const float* proj_s_w = (const float*)d_in[7];
    const float* proj_s_b = (const float*)d_in[8];
    const float* qkv_t_w = (const float*)d_in[9];
    const float* qkv_t_b = (const float*)d_in[10];
    const float* proj_t_w = (const float*)d_in[11];
    const float* proj_t_b = (const float*)d_in[12];
    const float* q_c_w  = (const float*)d_in[13];
    const float* q_c_b  = (const float*)d_in[14];
    const float* kv_c_w = (const float*)d_in[15];
    const float* kv_c_b = (const float*)d_in[16];
    const float* proj_c_w = (const float*)d_in[17];
    const float* proj_c_b = (const float*)d_in[18];
    const float* fc1_w  = (const float*)d_in[19];
    const float* fc1_b  = (const float*)d_in[20];
    const float* fc2_w  = (const float*)d_in[21];
    const float* fc2_b  = (const float*)d_in[22];
    float* X = (float*)d_out;

    float *p_t6, *p_xm, *p_qkv, *p_att, *p_h, *p_sc, *p_kv, *p_w, *p_yr;
    cudaGetSymbolAddress((void**)&p_t6, g_t6);
    cudaGetSymbolAddress((void**)&p_xm, g_xm);
    cudaGetSymbolAddress((void**)&p_qkv, g_qkv);
    cudaGetSymbolAddress((void**)&p_att, g_att);
    cudaGetSymbolAddress((void**)&p_h, g_h);
    cudaGetSymbolAddress((void**)&p_sc, g_sc);
    cudaGetSymbolAddress((void**)&p_kv, g_kv);
    cudaGetSymbolAddress((void**)&p_w, g_w);
    cudaGetSymbolAddress((void**)&p_yr, g_yr);

    // half-typed aliases
    __half* h_xm  = (__half*)p_xm;
    __half* h_qkv = (__half*)p_qkv;
    __half* h_att = (__half*)p_att;
    __half* h_h   = (__half*)p_h;
    __half* h_sc  = (__half*)p_sc;
    __half* h_kv  = (__half*)p_kv;
    __half* h_w   = (__half*)p_w;
    __half* h_yr  = (__half*)p_yr;

    const float scale = 0.11785113019775793f;  // 1/sqrt(72)

    static int attr_set = 0;
    if (!attr_set) {
        cudaFuncSetAttribute((const void*)k_hgemm<0>, cudaFuncAttributeMaxDynamicSharedMemorySize, HSMEM);
        cudaFuncSetAttribute((const void*)k_hgemm<2>, cudaFuncAttributeMaxDynamicSharedMemorySize, HSMEM);
        cudaFuncSetAttribute((const void*)k_hgemm<3>, cudaFuncAttributeMaxDynamicSharedMemorySize, HSMEM);
        attr_set = 1;
    }

    // half weight copies
    __half* w_qkv_s = h_w + (size_t)0 * CC2;
    __half* w_proj_s = h_w + (size_t)3 * CC2;
    __half* w_qkv_t = h_w + (size_t)4 * CC2;
    __half* w_proj_t = h_w + (size_t)7 * CC2;
    __half* w_q_c   = h_w + (size_t)8 * CC2;
    __half* w_kv_c  = h_w + (size_t)9 * CC2;
    __half* w_proj_c = h_w + (size_t)11 * CC2;
    __half* w_fc1   = h_w + (size_t)12 * CC2;
    __half* w_fc2   = h_w + (size_t)16 * CC2;

    auto rnd = [&](const float* src, __half* dst, size_t n) {
        k_round_h<<<(int)((n + 255) / 256), 256>>>(src, dst, (int)n);
    };
    rnd(qkv_s_w, w_qkv_s, (size_t)3 * CC2);
    rnd(proj_s_w, w_proj_s, CC2);
    rnd(qkv_t_w, w_qkv_t, (size_t)3 * CC2);
    rnd(proj_t_w, w_proj_t, CC2);
    rnd(q_c_w, w_q_c, CC2);
    rnd(kv_c_w, w_kv_c, (size_t)2 * CC2);
    rnd(proj_c_w, w_proj_c, CC2);
    rnd(fc1_w, w_fc1, (size_t)4 * CC2);
    rnd(fc2_w, w_fc2, (size_t)4 * CC2);
    rnd(y, h_yr, (size_t)CB * CYL * CC);

    k_mod<<<(CB * 6 * CC + 255) / 256, 256>>>(t, sst, p_t6);

#define HG(OP, A, W, B, C, R, gi, M, Nn, K) \
    k_hgemm<OP><<<dim3((Nn) / 128, ((M) + 127) / 128), 256, HSMEM>>>(A, W, B, C, R, p_t6, gi, M, Nn, K)

    // ---- spatial attention (all fp16) ----
    k_ln_mod<<<NROW, 288>>>(x, p_t6, h_xm, 0, 1);
    HG(0, h_xm, w_qkv_s, qkv_s_b, h_qkv, nullptr, 0, NROW, 3 * CC, CC);
    k_scores_h<0><<<dim3(2, 2, CB * CT * CNH), 256>>>(h_qkv, h_qkv + CC, h_sc, CNH, CS, CS,
                                                      3 * CC, 3 * CC,
                                                      (long)CS * 3 * CC, (long)CS * 3 * CC, scale);
    k_softmax_h<<<CB * CT * CNH * CS, 128>>>(h_sc);
    k_av_h<<<dim3(2, CB * CT * CNH), 256>>>(h_sc, h_qkv + 2 * CC, h_att, CNH, CS, CS,
                                            3 * CC, (long)CS * 3 * CC, CC, (long)CS * CC);
    HG(3, h_att, w_proj_s, proj_s_b, X, x, 2, NROW, CC, CC);  // X = x + gate_msa*proj

    // ---- temporal attention (causal, fused) ----
    k_xt_build<<<NROW, 288>>>(X, tpe, h_xm);
    HG(0, h_xm, w_qkv_t, qkv_t_b, h_qkv, nullptr, 0, NROW, 3 * CC, CC);
    k_attn_t<<<dim3(CNH, CB * CS), 128>>>(h_qkv, h_att, scale);
    HG(0, h_att, w_proj_t, proj_t_b, h_xm, nullptr, 0, NROW, CC, CC);
    k_resadd_t<<<NROW, 288>>>(X, h_xm, p_t6, 2, h_h);         // h_h = half X copy

    // ---- cross attention (fp16, fused softmax) ----
    HG(0, h_h, w_q_c, q_c_b, h_qkv, nullptr, 0, NROW, CC, CC);
    HG(0, h_yr, w_kv_c, kv_c_b, h_kv, nullptr, 0, CB * CYL, 2 * CC, CC);
    k_scores_h<1><<<dim3(1, CN / 128, CB * CNH), 256>>>(h_qkv, h_kv, h_sc, CNH, CN, CYL,
                                                        CC, 2 * CC,
                                                        (long)CN * CC, (long)CYL * 2 * CC, scale);
    k_av_h<<<dim3(CN / 128, CB * CNH), 256>>>(h_sc, h_kv + CC, h_att, CNH, CN, CYL,
                                              2 * CC, (long)CYL * 2 * CC, CC, (long)CN * CC);
    HG(3, h_att, w_proj_c, proj_c_b, X, X, -1, NROW, CC, CC); // X += proj

    // ---- MLP ----
    k_ln_mod<<<NROW, 288>>>(X, p_t6, h_xm, 3, 4);
    HG(2, h_xm, w_fc1, fc1_b, h_h, nullptr, 0, NROW, 4 * CC, CC);
    HG(3, h_h, w_fc2, fc2_b, X, X, 5, NROW, CC, 4 * CC);      // X += gate_mlp*fc2
}

// round 12
// speedup vs baseline: 2.1410x; 1.1166x over previous
#include <cuda_runtime.h>
#include <cuda_fp16.h>
#include <math.h>
#include <float.h>
#include <stdint.h>

// ---------------- problem constants ----------------
#define CB   4
#define CT   16
#define CS   256
#define CN   4096
#define CC   1152
#define CNH  16
#define CHD  72
#define CYL  120
#define NROW 16384
#define CC2  (CC * CC)

// ---------------- scratch (device globals) ----------------
__device__ float g_t6[CB * 6 * CC];
__device__ float g_xm[(size_t)NROW * CC];
__device__ float g_qkv[(size_t)NROW * 3 * CC];
__device__ float g_att[(size_t)NROW * CC];
__device__ float g_h[(size_t)NROW * 4 * CC];
__device__ float g_sc[67108864UL];
__device__ float g_kv[CB * CYL * 2 * CC];
__device__ float g_w[20 * CC2];                 // half weights (aliased)
__device__ float g_yr[CB * CYL * CC];           // half y (aliased)

// ---------------- helpers ----------------
__device__ __forceinline__ float gelu_tanh(float x) {
    float x3 = x * x * x;
    return 0.5f * x * (1.f + tanhf(0.7978845608028654f * (x + 0.044715f * x3)));
}
__device__ __forceinline__ uint32_t smem_u32(const void* p) {
    return (uint32_t)__cvta_generic_to_shared(p);
}
__device__ __forceinline__ void cp_async16u(uint32_t s, const void* g) {
    asm volatile("cp.async.cg.shared.global [%0], [%1], 16;\n" :: "r"(s), "l"(g));
}
__device__ __forceinline__ void cp_async16(void* smem, const void* gmem) {
    cp_async16u(smem_u32(smem), gmem);
}
__device__ __forceinline__ void cp_async16z(void* smem, const void* gmem, int sz) {
    uint32_t s = smem_u32(smem);
    asm volatile("cp.async.cg.shared.global [%0], [%1], 16, %2;\n" :: "r"(s), "l"(gmem), "r"(sz));
}
__device__ __forceinline__ void cp_commit() { asm volatile("cp.async.commit_group;\n"); }
template <int Nk>
__device__ __forceinline__ void cp_wait() { asm volatile("cp.async.wait_group %0;\n" :: "n"(Nk)); }

#define MMA_F16(acc, af, bf0, bf1)                                                \
    asm volatile(                                                                 \
        "mma.sync.aligned.m16n8k16.row.col.f32.f16.f16.f32 "                      \
        "{%0,%1,%2,%3}, {%4,%5,%6,%7}, {%8,%9}, {%0,%1,%2,%3};\n"                 \
        : "+f"(acc[0]), "+f"(acc[1]), "+f"(acc[2]), "+f"(acc[3])                  \
        : "r"(af[0]), "r"(af[1]), "r"(af[2]), "r"(af[3]), "r"(bf0), "r"(bf1))

#define LDSM4(r, a)                                                               \
    asm volatile("ldmatrix.sync.aligned.m8n8.x4.shared.b16 {%0,%1,%2,%3}, [%4];"  \
                 : "=r"((r)[0]), "=r"((r)[1]), "=r"((r)[2]), "=r"((r)[3])         \
                 : "r"(a))

// ---------------- elementwise: fp32 -> half ----------------
__global__ void k_round_h(const float* __restrict__ a, __half* __restrict__ o, int n) {
    int i = blockIdx.x * blockDim.x + threadIdx.x;
    if (i < n) o[i] = __float2half_rn(a[i]);
}

// ---------------- modulation ----------------
__global__ void k_mod(const float* __restrict__ t, const float* __restrict__ sst,
                      float* __restrict__ t6) {
    int i = blockIdx.x * blockDim.x + threadIdx.x;
    if (i < CB * 6 * CC) t6[i] = sst[i % (6 * CC)] + t[i];
}

// ---------------- LayerNorm + modulate (half output) ----------------
__global__ void k_ln_mod(const float* __restrict__ X, const float* __restrict__ t6,
                         __half* __restrict__ out, int shiftIdx, int scaleIdx) {
    int r = blockIdx.x;
    int b = r >> 12;
    const float* xr = X + (size_t)r * CC;
    const float* sh = t6 + (size_t)(b * 6 + shiftIdx) * CC;
    const float* scl = t6 + (size_t)(b * 6 + scaleIdx) * CC;

    float v[4];
    float s = 0.f, sq = 0.f;
#pragma unroll
    for (int i = 0; i < 4; i++) {
        int c = threadIdx.x + i * 288;
        v[i] = xr[c];
        s += v[i];
        sq += v[i] * v[i];
    }
    __shared__ float s1[9], s2[9], bc[2];
    int lane = threadIdx.x & 31, wid = threadIdx.x >> 5;
#pragma unroll
    for (int off = 16; off > 0; off >>= 1) {
        s += __shfl_xor_sync(0xffffffffu, s, off);
        sq += __shfl_xor_sync(0xffffffffu, sq, off);
    }
    if (lane == 0) { s1[wid] = s; s2[wid] = sq; }
    __syncthreads();
    if (threadIdx.x == 0) {
        float ts = 0.f, tq = 0.f;
        for (int w = 0; w < 9; w++) { ts += s1[w]; tq += s2[w]; }
        float mean = ts * (1.f / CC);
        float var = tq * (1.f / CC) - mean * mean;
        bc[0] = mean;
        bc[1] = rsqrtf(var + 1e-6f);
    }
    __syncthreads();
    float mean = bc[0], rstd = bc[1];
    __half* orow = out + (size_t)r * CC;
#pragma unroll
    for (int i = 0; i < 4; i++) {
        int c = threadIdx.x + i * 288;
        orow[c] = __float2half_rn((v[i] - mean) * rstd * (1.f + scl[c]) + sh[c]);
    }
}

// ================= fp16 dense GEMM: 256x128 tile, 512 threads, LDSM =================
// C[M,N] = A[M,K]h @ W[N,K]h^T + bias; fp32 accum.
// K-tile 64 halves, smem row stride 72 halves (conflict-free for cp.async + LDSM),
// 3-stage cp.async. 16 warps of 64x32 tiles (4 rows x 4 cols).
// OP: 0 = half store, 2 = gelu+half store, 3 = fp32 C = resid + gate*(acc+bias)
#define GSTR 72
#define GA_H (256 * GSTR)                  // halves per A stage
#define GB_H (128 * GSTR)                  // halves per B stage
#define GST_H (GA_H + GB_H)                // halves per stage
#define HSMEM (3 * GST_H * 2)              // bytes = 165888

template <int OP>
__global__ __launch_bounds__(512, 1) void k_hgemm(const __half* __restrict__ A,
                                                  const __half* __restrict__ W,
                                                  const float* __restrict__ bias,
                                                  void* __restrict__ Cout,
                                                  const float* __restrict__ resid,
                                                  const float* __restrict__ t6, int gi,
                                                  int M, int Nn, int K) {
    extern __shared__ __half smh[];
    const uint32_t sbase = smem_u32(smh);

    const int tid = threadIdx.x;
    const int m0 = blockIdx.y * 256, n0 = blockIdx.x * 128;
    const int wid = tid >> 5, lane = tid & 31;
    const int wr = wid & 3, wc = wid >> 2;          // 4 x 4 warps
    const int warp_m = wr * 64, warp_n = wc * 32;
    const int qr = lane >> 2, qc = lane & 3;
    const int lane7 = lane & 7, sel = lane >> 3;

    // LDSM source coordinates (per the m8n8 fragment mapping)
    const int a_row = warp_m + lane7 + (sel & 1) * 8;
    const int a_col = (sel >> 1) * 8;
    const int b_row = warp_n + lane7 + (sel >> 1) * 8;
    const int b_col = (sel & 1) * 8;

    float acc[4][4][4];
#pragma unroll
    for (int mi = 0; mi < 4; mi++)
#pragma unroll
        for (int ni = 0; ni < 4; ni++)
#pragma unroll
            for (int c = 0; c < 4; c++) acc[mi][ni][c] = 0.f;

    auto load_tile = [&](int stg, int kb) {
        uint32_t as = sbase + (uint32_t)(stg * GST_H) * 2u;
        uint32_t bs = as + GA_H * 2u;
#pragma unroll
        for (int i = 0; i < 4; i++) {                 // A: 256 rows x 8 chunks
            int idx = tid + i * 512;
            int m = idx >> 3, c8 = (idx & 7) * 8;
            int gm = m0 + m; if (gm >= M) gm = M - 1;
            cp_async16u(as + (uint32_t)(m * GSTR + c8) * 2u, A + (size_t)gm * K + kb + c8);
        }
#pragma unroll
        for (int i = 0; i < 2; i++) {                 // B: 128 rows x 8 chunks
            int idx = tid + i * 512;
            int m = idx >> 3, c8 = (idx & 7) * 8;
            cp_async16u(bs + (uint32_t)(m * GSTR + c8) * 2u, W + (size_t)(n0 + m) * K + kb + c8);
        }
    };

    const int KT = K >> 6;
    load_tile(0, 0); cp_commit();
    load_tile(1, 64); cp_commit();

    for (int t = 0; t < KT; ++t) {
        if (t + 1 < KT) cp_wait<1>(); else cp_wait<0>();
        __syncthreads();
        if (t + 2 < KT) { load_tile((t + 2) % 3, (t + 2) << 6); }
        cp_commit();

        uint32_t as = sbase + (uint32_t)((t % 3) * GST_H) * 2u;
        uint32_t bs = as + GA_H * 2u;
        uint32_t aaddr = as + (uint32_t)(a_row * GSTR + a_col) * 2u;
        uint32_t baddr = bs + (uint32_t)(b_row * GSTR + b_col) * 2u;

#pragma unroll
        for (int kk = 0; kk < 64; kk += 16) {
            uint32_t af[4][4], bq[2][4];
#pragma unroll
            for (int mi = 0; mi < 4; mi++)
                LDSM4(af[mi], aaddr + (uint32_t)(mi * 16 * GSTR + kk) * 2u);
#pragma unroll
            for (int nip = 0; nip < 2; nip++)
                LDSM4(bq[nip], baddr + (uint32_t)(nip * 16 * GSTR + kk) * 2u);
#pragma unroll
            for (int mi = 0; mi < 4; mi++)
#pragma unroll
                for (int ni = 0; ni < 4; ni++)
                    MMA_F16(acc[mi][ni], af[mi], bq[ni >> 1][(ni & 1) * 2],
                            bq[ni >> 1][(ni & 1) * 2 + 1]);
        }
        __syncthreads();
    }

    const int b = m0 >> 12;
    const float* gate = (OP == 3 && gi >= 0) ? t6 + (size_t)(b * 6 + gi) * CC : nullptr;

#pragma unroll
    for (int mi = 0; mi < 4; mi++) {
        int r0 = m0 + warp_m + mi * 16 + qr;
        int r1 = r0 + 8;
#pragma unroll
        for (int ni = 0; ni < 4; ni++) {
            int c0 = n0 + warp_n + ni * 8 + qc * 2;
            float b0 = bias[c0], b1 = bias[c0 + 1];
            float v[4] = {acc[mi][ni][0] + b0, acc[mi][ni][1] + b1,
                          acc[mi][ni][2] + b0, acc[mi][ni][3] + b1};
            if (OP == 2) {
#pragma unroll
                for (int c = 0; c < 4; c++) v[c] = gelu_tanh(v[c]);
            }
            if (OP == 0 || OP == 2) {
                __half* C = (__half*)Cout;
                if (r0 < M)
                    *(__half2*)(C + (size_t)r0 * Nn + c0) =
                        __halves2half2(__float2half_rn(v[0]), __float2half_rn(v[1]));
                if (r1 < M)
                    *(__half2*)(C + (size_t)r1 * Nn + c0) =
                        __halves2half2(__float2half_rn(v[2]), __float2half_rn(v[3]));
            } else {  // OP == 3
                float* C = (float*)Cout;
                float g0 = gate ? gate[c0] : 1.f;
                float g1 = gate ? gate[c0 + 1] : 1.f;
                if (r0 < M) {
                    const float* rr = resid + (size_t)r0 * Nn;
                    float* cw = C + (size_t)r0 * Nn;
                    cw[c0] = rr[c0] + g0 * v[0];
                    cw[c0 + 1] = rr[c0 + 1] + g1 * v[1];
                }
                if (r1 < M) {
                    const float* rr = resid + (size_t)r1 * Nn;
                    float* cw = C + (size_t)r1 * Nn;
                    cw[c0] = rr[c0] + g0 * v[2];
                    cw[c0 + 1] = rr[c0 + 1] + g1 * v[3];
                }
            }
        }
    }
}

// ================= fp16 attention scores (K = 72, one-shot smem) =================
#define SSTR 88

#define MMA_F16B(acc, af, bf)                                                     \
    asm volatile(                                                                 \
        "mma.sync.aligned.m16n8k16.row.col.f32.f16.f16.f32 "                      \
        "{%0,%1,%2,%3}, {%4,%5,%6,%7}, {%8,%9}, {%0,%1,%2,%3};\n"                 \
        : "+f"(acc[0]), "+f"(acc[1]), "+f"(acc[2]), "+f"(acc[3])                  \
        : "r"(af[0]), "r"(af[1]), "r"(af[2]), "r"(af[3]), "r"(bf[0]), "r"(bf[1]))

template <int DOSM>
__global__ __launch_bounds__(256) void k_scores_h(const __half* __restrict__ Q,
                                                  const __half* __restrict__ Kd,
                                                  __half* __restrict__ out,
                                                  int heads, int Sq, int Sk,
                                                  int qRS, int kRS, long qBS, long kBS,
                                                  float scale) {
    __shared__ __half As[128 * SSTR];
    __shared__ __half Bs[128 * SSTR];
    __shared__ float red[128][4];

    const int tid = threadIdx.x;
    int z = blockIdx.z;
    int b = z / heads, h = z - b * heads;
    const __half* qb = Q + (long)b * qBS + h * CHD;
    const __half* kb = Kd + (long)b * kBS + h * CHD;
    const int i0 = blockIdx.y * 128, j0 = blockIdx.x * 128;
    const int wid = tid >> 5, lane = tid & 31;
    const int wr = wid >> 2, wc = wid & 3;
    const int warp_m = wr * 64, warp_n = wc * 32;
    const int qr = lane >> 2, qc = lane & 3;

    for (int idx = tid; idx < 128 * 11; idx += 256) {
        int m = idx / 11, c = idx - m * 11;
        int sz = (c < 9) ? 16 : 0;
        int gq = i0 + m; if (gq >= Sq) gq = Sq - 1;
        int gk = j0 + m; if (gk >= Sk) gk = Sk - 1;
        cp_async16z(&As[m * SSTR + c * 8], qb + (long)gq * qRS + c * 8, sz);
        cp_async16z(&Bs[m * SSTR + c * 8], kb + (long)gk * kRS + c * 8, sz);
    }
    cp_commit();
    cp_wait<0>();
    __syncthreads();

    float acc[4][4][4];
#pragma unroll
    for (int mi = 0; mi < 4; mi++)
#pragma unroll
        for (int ni = 0; ni < 4; ni++)
#pragma unroll
            for (int c = 0; c < 4; c++) acc[mi][ni][c] = 0.f;

#pragma unroll
    for (int kk = 0; kk < 80; kk += 16) {
        uint32_t af[4][4], bf[4][2];
#pragma unroll
        for (int mi = 0; mi < 4; mi++) {
            const __half* base = &As[(warp_m + mi * 16 + qr) * SSTR + kk + 2 * qc];
            af[mi][0] = *(const uint32_t*)(base);
            af[mi][1] = *(const uint32_t*)(base + 8 * SSTR);
            af[mi][2] = *(const uint32_t*)(base + 8);
            af[mi][3] = *(const uint32_t*)(base + 8 * SSTR + 8);
        }
#pragma unroll
        for (int ni = 0; ni < 4; ni++) {
            const __half* bb = &Bs[(warp_n + ni * 8 + qr) * SSTR + kk + 2 * qc];
            bf[ni][0] = *(const uint32_t*)(bb);
            bf[ni][1] = *(const uint32_t*)(bb + 8);
        }
#pragma unroll
        for (int mi = 0; mi < 4; mi++)
#pragma unroll
            for (int ni = 0; ni < 4; ni++) MMA_F16B(acc[mi][ni], af[mi], bf[ni]);
    }

    __half* ob = out + (long)z * Sq * Sk;

    if (DOSM == 0) {
#pragma unroll
        for (int mi = 0; mi < 4; mi++) {
            int r0 = i0 + warp_m + mi * 16 + qr;
            int r1 = r0 + 8;
#pragma unroll
            for (int ni = 0; ni < 4; ni++) {
                int c0 = j0 + warp_n + ni * 8 + qc * 2;
                if (c0 < Sk) {
                    if (r0 < Sq)
                        *(__half2*)(ob + (long)r0 * Sk + c0) =
                            __halves2half2(__float2half_rn(acc[mi][ni][0] * scale),
                                           __float2half_rn(acc[mi][ni][1] * scale));
                    if (r1 < Sq)
                        *(__half2*)(ob + (long)r1 * Sk + c0) =
                            __halves2half2(__float2half_rn(acc[mi][ni][2] * scale),
                                           __float2half_rn(acc[mi][ni][3] * scale));
                }
            }
        }
        return;
    }

#pragma unroll
    for (int mi = 0; mi < 4; mi++)
#pragma unroll
        for (int ni = 0; ni < 4; ni++)
#pragma unroll
            for (int c = 0; c < 4; c++) acc[mi][ni][c] *= scale;

    float mrow[4][2], srow[4][2];
#pragma unroll
    for (int mi = 0; mi < 4; mi++)
#pragma unroll
        for (int hf = 0; hf < 2; hf++) {
            float m = -FLT_MAX;
#pragma unroll
            for (int ni = 0; ni < 4; ni++) {
                int c0 = warp_n + ni * 8 + qc * 2;
                if (c0 < Sk) m = fmaxf(m, acc[mi][ni][hf * 2]);
                if (c0 + 1 < Sk) m = fmaxf(m, acc[mi][ni][hf * 2 + 1]);
            }
            m = fmaxf(m, __shfl_xor_sync(0xffffffffu, m, 1));
            m = fmaxf(m, __shfl_xor_sync(0xffffffffu, m, 2));
            if (qc == 0) red[warp_m + mi * 16 + qr + hf * 8][wc] = m;
        }
    __syncthreads();
#pragma unroll
    for (int mi = 0; mi < 4; mi++)
#pragma unroll
        for (int hf = 0; hf < 2; hf++) {
            int rl = warp_m + mi * 16 + qr + hf * 8;
            mrow[mi][hf] = fmaxf(fmaxf(red[rl][0], red[rl][1]), fmaxf(red[rl][2], red[rl][3]));
        }
    __syncthreads();
#pragma unroll
    for (int mi = 0; mi < 4; mi++)
#pragma unroll
        for (int hf = 0; hf < 2; hf++) {
            float s = 0.f;
#pragma unroll
            for (int ni = 0; ni < 4; ni++) {
                int c0 = warp_n + ni * 8 + qc * 2;
                float e0 = (c0 < Sk) ? expf(acc[mi][ni][hf * 2] - mrow[mi][hf]) : 0.f;
                float e1 = (c0 + 1 < Sk) ? expf(acc[mi][ni][hf * 2 + 1] - mrow[mi][hf]) : 0.f;
                acc[mi][ni][hf * 2] = e0;
                acc[mi][ni][hf * 2 + 1] = e1;
                s += e0 + e1;
            }
            s += __shfl_xor_sync(0xffffffffu, s, 1);
            s += __shfl_xor_sync(0xffffffffu, s, 2);
            if (qc == 0) red[warp_m + mi * 16 + qr + hf * 8][wc] = s;
        }
    __syncthreads();
#pragma unroll
    for (int mi = 0; mi < 4; mi++)
#pragma unroll
        for (int hf = 0; hf < 2; hf++) {
            int rl = warp_m + mi * 16 + qr + hf * 8;
            srow[mi][hf] = 1.f / (red[rl][0] + red[rl][1] + red[rl][2] + red[rl][3]);
        }
#pragma unroll
    for (int mi = 0; mi < 4; mi++) {
        int r0 = i0 + warp_m + mi * 16 + qr;
        int r1 = r0 + 8;
#pragma unroll
        for (int ni = 0; ni < 4; ni++) {
            int c0 = warp_n + ni * 8 + qc * 2;
            if (c0 < Sk) {
                *(__half2*)(ob + (long)r0 * Sk + c0) =
                    __halves2half2(__float2half_rn(acc[mi][ni][0] * srow[mi][0]),
                                   __float2half_rn(acc[mi][ni][1] * srow[mi][0]));
                *(__half2*)(ob + (long)r1 * Sk + c0) =
                    __halves2half2(__float2half_rn(acc[mi][ni][2] * srow[mi][1]),
                                   __float2half_rn(acc[mi][ni][3] * srow[mi][1]));
            }
        }
    }
}

// ================= fp16 attn@V =================
#define PSTR 24
__global__ __launch_bounds__(256) void k_av_h(const __half* __restrict__ P,
                                              const __half* __restrict__ V,
                                              __half* __restrict__ O,
                                              int heads, int Sq, int Sk,
                                              int vRS, long vBS, int oRS, long oBS) {
    __shared__ __half As[2][128 * PSTR];
    __shared__ __half Vs[2][72 * PSTR];

    const int tid = threadIdx.x;
    int z = blockIdx.y;
    int b = z / heads, h = z - b * heads;
    const __half* Pb = P + (long)z * Sq * Sk;
    const __half* Vb = V + (long)b * vBS + h * CHD;
    __half* Ob = O + (long)b * oBS + h * CHD;
    const int i0 = blockIdx.x * 128;
    const int wid = tid >> 5, lane = tid & 31;
    const int warp_m = wid * 16;
    const int qr = lane >> 2, qc = lane & 3;

    float acc[9][4];
#pragma unroll
    for (int nt = 0; nt < 9; nt++)
#pragma unroll
        for (int c = 0; c < 4; c++) acc[nt][c] = 0.f;

    auto load_tile = [&](int stg, int kb) {
        for (int idx = tid; idx < 256; idx += 256) {
            int m = idx >> 1;
            int c = idx & 1;
            int sz = (kb + c * 8 + 8 <= Sk) ? 16 : 0;
            int gi = i0 + m; if (gi >= Sq) gi = Sq - 1;
            cp_async16z(&As[stg][m * PSTR + c * 8], Pb + (long)gi * Sk + kb + c * 8, sz);
        }
        for (int idx = tid; idx < 576; idx += 256) {
            int key = idx / 36, d2 = idx - key * 36;
            __half2 v = (kb + key < Sk)
                            ? *(const __half2*)(Vb + (long)(kb + key) * vRS + 2 * d2)
                            : __halves2half2(__float2half_rn(0.f), __float2half_rn(0.f));
            Vs[stg][(2 * d2) * PSTR + key] = __low2half(v);
            Vs[stg][(2 * d2 + 1) * PSTR + key] = __high2half(v);
        }
    };

    const int KT = (Sk + 15) >> 4;
    load_tile(0, 0);
    cp_commit();

    for (int kt = 0; kt < KT; ++kt) {
        int cur = kt & 1;
        if (kt + 1 < KT) {
            load_tile(1 - cur, (kt + 1) << 4);
            cp_commit();
            cp_wait<1>();
        } else {
            cp_wait<0>();
        }
        __syncthreads();

        uint32_t af[4];
        const __half* abase = &As[cur][(warp_m + qr) * PSTR + 2 * qc];
        af[0] = *(const uint32_t*)(abase);
        af[1] = *(const uint32_t*)(abase + 8 * PSTR);
        af[2] = *(const uint32_t*)(abase + 8);
        af[3] = *(const uint32_t*)(abase + 8 * PSTR + 8);
#pragma unroll
        for (int nt = 0; nt < 9; nt++) {
            uint32_t bf[2];
            const __half* bb = &Vs[cur][(nt * 8 + qr) * PSTR + 2 * qc];
            bf[0] = *(const uint32_t*)(bb);
            bf[1] = *(const uint32_t*)(bb + 8);
            MMA_F16B(acc[nt], af, bf);
        }
        __syncthreads();
    }

    int r0 = i0 + warp_m + qr;
    int r1 = r0 + 8;
#pragma unroll
    for (int nt = 0; nt < 9; nt++) {
        int c0 = nt * 8 + qc * 2;
        if (r0 < Sq)
            *(__half2*)(Ob + (long)r0 * oRS + c0) =
                __halves2half2(__float2half_rn(acc[nt][0]), __float2half_rn(acc[nt][1]));
        if (r1 < Sq)
            *(__half2*)(Ob + (long)r1 * oRS + c0) =
                __halves2half2(__float2half_rn(acc[nt][2]), __float2half_rn(acc[nt][3]));
    }
}

// ---------------- spatial softmax on half (L = 256) ----------------
__global__ void k_softmax_h(__half* __restrict__ sc) {
    long row = blockIdx.x;
    __half2* p2 = (__half2*)(sc + row * 256);
    int tid = threadIdx.x;

    float2 v = __half22float2(p2[tid]);
    __shared__ float red[4];
    float m = fmaxf(v.x, v.y);
#pragma unroll
    for (int off = 16; off > 0; off >>= 1) m = fmaxf(m, __shfl_xor_sync(0xffffffffu, m, off));
    if ((tid & 31) == 0) red[tid >> 5] = m;
    __syncthreads();
    m = fmaxf(fmaxf(red[0], red[1]), fmaxf(red[2], red[3]));
    __syncthreads();

    float e0 = expf(v.x - m), e1 = expf(v.y - m);
    float s = e0 + e1;
#pragma unroll
    for (int off = 16; off > 0; off >>= 1) s += __shfl_xor_sync(0xffffffffu, s, off);
    if ((tid & 31) == 0) red[tid >> 5] = s;
    __syncthreads();
    s = red[0] + red[1] + red[2] + red[3];
    float inv = 1.f / s;
    p2[tid] = __halves2half2(__float2half_rn(e0 * inv), __float2half_rn(e1 * inv));
}

// ---------------- fused temporal attention (T=16, causal; half in/out) -------
__global__ __launch_bounds__(128) void k_attn_t(const __half* __restrict__ qkv,
                                                __half* __restrict__ O, float scale) {
    __shared__ float q[16][72], k[16][72], v[16][72], p[16][17];
    int h = blockIdx.x;
    int bs = blockIdx.y;
    const __half* base = qkv + (size_t)bs * CT * 3 * CC + h * CHD;
    int tid = threadIdx.x;

    for (int idx = tid; idx < 16 * 72; idx += 128) {
        int t = idx / 72, d = idx - t * 72;
        const __half* row = base + (size_t)t * 3 * CC;
        q[t][d] = __half2float(row[d]);
        k[t][d] = __half2float(row[CC + d]);
        v[t][d] = __half2float(row[2 * CC + d]);
    }
    __syncthreads();

    for (int e = tid; e < 256; e += 128) {
        int i = e >> 4, j = e & 15;
        float acc = 0.f;
#pragma unroll 8
        for (int d = 0; d < 72; d++) acc += q[i][d] * k[j][d];
        p[i][j] = acc * scale;
    }
    __syncthreads();

    if (tid < 16) {
        int i = tid;
        float m = -FLT_MAX;
        for (int j = 0; j <= i; j++) m = fmaxf(m, p[i][j]);
        float s = 0.f;
        for (int j = 0; j <= i; j++) { float e = expf(p[i][j] - m); p[i][j] = e; s += e; }
        float inv = 1.f / s;
        for (int j = 0; j <= i; j++) p[i][j] *= inv;
        for (int j = i + 1; j < 16; j++) p[i][j] = 0.f;
    }
    __syncthreads();

    for (int e = tid; e < 16 * 72; e += 128) {
        int t = e / 72, d = e - t * 72;
        float acc = 0.f;
#pragma unroll
        for (int j = 0; j < 16; j++) acc += p[t][j] * v[j][d];
        O[((size_t)bs * CT + t) * CC + h * CHD + d] = __float2half_rn(acc);
    }
}

// ---------------- build temporal input (half out) ----------------
__global__ void k_xt_build(const float* __restrict__ X, const float* __restrict__ tpe,
                           __half* __restrict__ out) {
    int r = blockIdx.x;
    int t = r & 15;
    int bs = r >> 4;
    int s = bs & 255;
    int b = bs >> 8;
    const float* xr = X + ((size_t)b * CN + t * CS + s) * CC;
    const float* tp = tpe + (size_t)t * CC;
    __half* orow = out + (size_t)r * CC;
#pragma unroll
    for (int i = 0; i < 4; i++) {
        int c = threadIdx.x + i * 288;
        orow[c] = __float2half_rn(xr[c] + tp[c]);
    }
}

// ---------------- temporal residual scatter + half copy of X ----------------
__global__ void k_resadd_t(float* __restrict__ X, const __half* __restrict__ src,
                           const float* __restrict__ t6, int gi,
                           __half* __restrict__ xr_out) {
    int r = blockIdx.x;
    int b = r >> 12;
    int n = r & 4095;
    int t = n >> 8;
    int s = n & 255;
    long srow = ((long)(b * CS + s) * CT + t) * CC;
    float* xr = X + (size_t)r * CC;
    const __half* sr = src + srow;
    const float* gr = t6 + (size_t)(b * 6 + gi) * CC;
    __half* orow = xr_out + (size_t)r * CC;
#pragma unroll
    for (int i = 0; i < 4; i++) {
        int c = threadIdx.x + i * 288;
        float v = xr[c] + gr[c] * __half2float(sr[c]);
        xr[c] = v;
        orow[c] = __float2half_rn(v);
    }
}

// =======================================================================
extern "C" void kernel_launch(void* const* d_in, const int* in_sizes, int n_in,
                              void* d_out, int out_size) {
    const float* x      = (const float*)d_in[0];
    const float* y      = (const float*)d_in[1];
    const float* t      = (const float*)d_in[2];
    const float* tpe    = (const float*)d_in[3];
    const float* sst    = (const float*)d_in[4];
    const float* qkv_s_w = (const float*)d_in[5];
    const float* qkv_s_b = (const float*)d_in[6];
    const float* proj_s_w = (const float*)d_in[7];
    const float* proj_s_b = (const float*)d_in[8];
    const float* qkv_t_w = (const float*)d_in[9];
    const float* qkv_t_b = (const float*)d_in[10];
    const float* proj_t_w = (const float*)d_in[11];
    const float* proj_t_b = (const float*)d_in[12];
    const float* q_c_w  = (const float*)d_in[13];
    const float* q_c_b  = (const float*)d_in[14];
    const float* kv_c_w = (const float*)d_in[15];
    const float* kv_c_b = (const float*)d_in[16];
    const float* proj_c_w = (const float*)d_in[17];
    const float* proj_c_b = (const float*)d_in[18];
    const float* fc1_w  = (const float*)d_in[19];
    const float* fc1_b  = (const float*)d_in[20];
    const float* fc2_w  = (const float*)d_in[21];
    const float* fc2_b  = (const float*)d_in[22];
    float* X = (float*)d_out;

    float *p_t6, *p_xm, *p_qkv, *p_att, *p_h, *p_sc, *p_kv, *p_w, *p_yr;
    cudaGetSymbolAddress((void**)&p_t6, g_t6);
    cudaGetSymbolAddress((void**)&p_xm, g_xm);
    cudaGetSymbolAddress((void**)&p_qkv, g_qkv);
    cudaGetSymbolAddress((void**)&p_att, g_att);
    cudaGetSymbolAddress((void**)&p_h, g_h);
    cudaGetSymbolAddress((void**)&p_sc, g_sc);
    cudaGetSymbolAddress((void**)&p_kv, g_kv);
    cudaGetSymbolAddress((void**)&p_w, g_w);
    cudaGetSymbolAddress((void**)&p_yr, g_yr);

    // half-typed aliases
    __half* h_xm  = (__half*)p_xm;
    __half* h_qkv = (__half*)p_qkv;
    __half* h_att = (__half*)p_att;
    __half* h_h   = (__half*)p_h;
    __half* h_sc  = (__half*)p_sc;
    __half* h_kv  = (__half*)p_kv;
    __half* h_w   = (__half*)p_w;
    __half* h_yr  = (__half*)p_yr;

    const float scale = 0.11785113019775793f;  // 1/sqrt(72)

    static int attr_set = 0;
    if (!attr_set) {
        cudaFuncSetAttribute((const void*)k_hgemm<0>, cudaFuncAttributeMaxDynamicSharedMemorySize, HSMEM);
        cudaFuncSetAttribute((const void*)k_hgemm<2>, cudaFuncAttributeMaxDynamicSharedMemorySize, HSMEM);
        cudaFuncSetAttribute((const void*)k_hgemm<3>, cudaFuncAttributeMaxDynamicSharedMemorySize, HSMEM);
        attr_set = 1;
    }

    // half weight copies
    __half* w_qkv_s = h_w + (size_t)0 * CC2;
    __half* w_proj_s = h_w + (size_t)3 * CC2;
    __half* w_qkv_t = h_w + (size_t)4 * CC2;
    __half* w_proj_t = h_w + (size_t)7 * CC2;
    __half* w_q_c   = h_w + (size_t)8 * CC2;
    __half* w_kv_c  = h_w + (size_t)9 * CC2;
    __half* w_proj_c = h_w + (size_t)11 * CC2;
    __half* w_fc1   = h_w + (size_t)12 * CC2;
    __half* w_fc2   = h_w + (size_t)16 * CC2;

    auto rnd = [&](const float* src, __half* dst, size_t n) {
        k_round_h<<<(int)((n + 255) / 256), 256>>>(src, dst, (int)n);
    };
    rnd(qkv_s_w, w_qkv_s, (size_t)3 * CC2);
    rnd(proj_s_w, w_proj_s, CC2);
    rnd(qkv_t_w, w_qkv_t, (size_t)3 * CC2);
    rnd(proj_t_w, w_proj_t, CC2);
    rnd(q_c_w, w_q_c, CC2);
    rnd(kv_c_w, w_kv_c, (size_t)2 * CC2);
    rnd(proj_c_w, w_proj_c, CC2);
    rnd(fc1_w, w_fc1, (size_t)4 * CC2);
    rnd(fc2_w, w_fc2, (size_t)4 * CC2);
    rnd(y, h_yr, (size_t)CB * CYL * CC);

    k_mod<<<(CB * 6 * CC + 255) / 256, 256>>>(t, sst, p_t6);

#define HG(OP, A, W, B, C, R, gi, M, Nn, K) \
    k_hgemm<OP><<<dim3((Nn) / 128, ((M) + 255) / 256), 512, HSMEM>>>(A, W, B, C, R, p_t6, gi, M, Nn, K)

    // ---- spatial attention (all fp16) ----
    k_ln_mod<<<NROW, 288>>>(x, p_t6, h_xm, 0, 1);
    HG(0, h_xm, w_qkv_s, qkv_s_b, h_qkv, nullptr, 0, NROW, 3 * CC, CC);
    k_scores_h<0><<<dim3(2, 2, CB * CT * CNH), 256>>>(h_qkv, h_qkv + CC, h_sc, CNH, CS, CS,
                                                      3 * CC, 3 * CC,
                                                      (long)CS * 3 * CC, (long)CS * 3 * CC, scale);
    k_softmax_h<<<CB * CT * CNH * CS, 128>>>(h_sc);
    k_av_h<<<dim3(2, CB * CT * CNH), 256>>>(h_sc, h_qkv + 2 * CC, h_att, CNH, CS, CS,
                                            3 * CC, (long)CS * 3 * CC, CC, (long)CS * CC);
    HG(3, h_att, w_proj_s, proj_s_b, X, x, 2, NROW, CC, CC);  // X = x + gate_msa*proj

    // ---- temporal attention (causal, fused) ----
    k_xt_build<<<NROW, 288>>>(X, tpe, h_xm);
    HG(0, h_xm, w_qkv_t, qkv_t_b, h_qkv, nullptr, 0, NROW, 3 * CC, CC);
    k_attn_t<<<dim3(CNH, CB * CS), 128>>>(h_qkv, h_att, scale);
    HG(0, h_att, w_proj_t, proj_t_b, h_xm, nullptr, 0, NROW, CC, CC);
    k_resadd_t<<<NROW, 288>>>(X, h_xm, p_t6, 2, h_h);         // h_h = half X copy

    // ---- cross attention (fp16, fused softmax) ----
    HG(0, h_h, w_q_c, q_c_b, h_qkv, nullptr, 0, NROW, CC, CC);
    HG(0, h_yr, w_kv_c, kv_c_b, h_kv, nullptr, 0, CB * CYL, 2 * CC, CC);
    k_scores_h<1><<<dim3(1, CN / 128, CB * CNH), 256>>>(h_qkv, h_kv, h_sc, CNH, CN, CYL,
                                                        CC, 2 * CC,
                                                        (long)CN * CC, (long)CYL * 2 * CC, scale);
    k_av_h<<<dim3(CN / 128, CB * CNH), 256>>>(h_sc, h_kv + CC, h_att, CNH, CN, CYL,
                                              2 * CC, (long)CYL * 2 * CC, CC, (long)CN * CC);
    HG(3, h_att, w_proj_c, proj_c_b, X, X, -1, NROW, CC, CC); // X += proj

    // ---- MLP ----
    k_ln_mod<<<NROW, 288>>>(X, p_t6, h_xm, 3, 4);
    HG(2, h_xm, w_fc1, fc1_b, h_h, nullptr, 0, NROW, 4 * CC, CC);
    HG(3, h_h, w_fc2, fc2_b, X, X, 5, NROW, CC, 4 * CC);      // X += gate_mlp*fc2
}

// round 16
// speedup vs baseline: 2.1968x; 1.0260x over previous
#include <cuda_runtime.h>
#include <cuda_fp16.h>
#include <math.h>
#include <float.h>
#include <stdint.h>

// ---------------- problem constants ----------------
#define CB   4
#define CT   16
#define CS   256
#define CN   4096
#define CC   1152
#define CNH  16
#define CHD  72
#define CYL  120
#define NROW 16384
#define CC2  (CC * CC)

// ---------------- scratch (device globals) ----------------
__device__ float g_t6[CB * 6 * CC];
__device__ float g_xm[(size_t)NROW * CC];
__device__ float g_qkv[(size_t)NROW * 3 * CC];
__device__ float g_att[(size_t)NROW * CC];
__device__ float g_h[(size_t)NROW * 4 * CC];
__device__ float g_sc[67108864UL];
__device__ float g_kv[CB * CYL * 2 * CC];
__device__ float g_w[20 * CC2];                 // half weights (aliased)
__device__ float g_yr[CB * CYL * CC];           // half y (aliased)

// ---------------- helpers ----------------
__device__ __forceinline__ float gelu_tanh(float x) {
    float x3 = x * x * x;
    return 0.5f * x * (1.f + tanhf(0.7978845608028654f * (x + 0.044715f * x3)));
}
__device__ __forceinline__ uint32_t smem_u32(const void* p) {
    return (uint32_t)__cvta_generic_to_shared(p);
}
__device__ __forceinline__ void cp_async16u(uint32_t s, const void* g) {
    asm volatile("cp.async.cg.shared.global [%0], [%1], 16;\n" :: "r"(s), "l"(g));
}
__device__ __forceinline__ void cp_async16(void* smem, const void* gmem) {
    cp_async16u(smem_u32(smem), gmem);
}
__device__ __forceinline__ void cp_async16z(void* smem, const void* gmem, int sz) {
    uint32_t s = smem_u32(smem);
    asm volatile("cp.async.cg.shared.global [%0], [%1], 16, %2;\n" :: "r"(s), "l"(gmem), "r"(sz));
}
__device__ __forceinline__ void cp_commit() { asm volatile("cp.async.commit_group;\n"); }
template <int Nk>
__device__ __forceinline__ void cp_wait() { asm volatile("cp.async.wait_group %0;\n" :: "n"(Nk)); }

#define MMA_F16(acc, af, bf0, bf1)                                                \
    asm volatile(                                                                 \
        "mma.sync.aligned.m16n8k16.row.col.f32.f16.f16.f32 "                      \
        "{%0,%1,%2,%3}, {%4,%5,%6,%7}, {%8,%9}, {%0,%1,%2,%3};\n"                 \
        : "+f"(acc[0]), "+f"(acc[1]), "+f"(acc[2]), "+f"(acc[3])                  \
        : "r"(af[0]), "r"(af[1]), "r"(af[2]), "r"(af[3]), "r"(bf0), "r"(bf1))

#define MMA_F16B(acc, af, bf)                                                     \
    asm volatile(                                                                 \
        "mma.sync.aligned.m16n8k16.row.col.f32.f16.f16.f32 "                      \
        "{%0,%1,%2,%3}, {%4,%5,%6,%7}, {%8,%9}, {%0,%1,%2,%3};\n"                 \
        : "+f"(acc[0]), "+f"(acc[1]), "+f"(acc[2]), "+f"(acc[3])                  \
        : "r"(af[0]), "r"(af[1]), "r"(af[2]), "r"(af[3]), "r"(bf[0]), "r"(bf[1]))

#define LDSM4(r, a)                                                               \
    asm volatile("ldmatrix.sync.aligned.m8n8.x4.shared.b16 {%0,%1,%2,%3}, [%4];"  \
                 : "=r"((r)[0]), "=r"((r)[1]), "=r"((r)[2]), "=r"((r)[3])         \
                 : "r"(a))

// ---------------- elementwise: fp32 -> half ----------------
__global__ void k_round_h(const float* __restrict__ a, __half* __restrict__ o, int n) {
    int i = blockIdx.x * blockDim.x + threadIdx.x;
    if (i < n) o[i] = __float2half_rn(a[i]);
}

// ---------------- modulation ----------------
__global__ void k_mod(const float* __restrict__ t, const float* __restrict__ sst,
                      float* __restrict__ t6) {
    int i = blockIdx.x * blockDim.x + threadIdx.x;
    if (i < CB * 6 * CC) t6[i] = sst[i % (6 * CC)] + t[i];
}

// ---------------- LayerNorm + modulate (half output) ----------------
__global__ void k_ln_mod(const float* __restrict__ X, const float* __restrict__ t6,
                         __half* __restrict__ out, int shiftIdx, int scaleIdx) {
    int r = blockIdx.x;
    int b = r >> 12;
    const float* xr = X + (size_t)r * CC;
    const float* sh = t6 + (size_t)(b * 6 + shiftIdx) * CC;
    const float* scl = t6 + (size_t)(b * 6 + scaleIdx) * CC;

    float v[4];
    float s = 0.f, sq = 0.f;
#pragma unroll
    for (int i = 0; i < 4; i++) {
        int c = threadIdx.x + i * 288;
        v[i] = xr[c];
        s += v[i];
        sq += v[i] * v[i];
    }
    __shared__ float s1[9], s2[9], bc[2];
    int lane = threadIdx.x & 31, wid = threadIdx.x >> 5;
#pragma unroll
    for (int off = 16; off > 0; off >>= 1) {
        s += __shfl_xor_sync(0xffffffffu, s, off);
        sq += __shfl_xor_sync(0xffffffffu, sq, off);
    }
    if (lane == 0) { s1[wid] = s; s2[wid] = sq; }
    __syncthreads();
    if (threadIdx.x == 0) {
        float ts = 0.f, tq = 0.f;
        for (int w = 0; w < 9; w++) { ts += s1[w]; tq += s2[w]; }
        float mean = ts * (1.f / CC);
        float var = tq * (1.f / CC) - mean * mean;
        bc[0] = mean;
        bc[1] = rsqrtf(var + 1e-6f);
    }
    __syncthreads();
    float mean = bc[0], rstd = bc[1];
    __half* orow = out + (size_t)r * CC;
#pragma unroll
    for (int i = 0; i < 4; i++) {
        int c = threadIdx.x + i * 288;
        orow[c] = __float2half_rn((v[i] - mean) * rstd * (1.f + scl[c]) + sh[c]);
    }
}

// ================= fp16 dense GEMM: 256x128 tile, 512 threads, LDSM =================
// OP: 0 = half store, 2 = gelu+half store, 3 = fp32 C = resid + gate*(acc+bias),
//     4 = temporal residual scatter: X[perm(r)] += gate*(acc+bias), + half copy
#define GSTR 72
#define GA_H (256 * GSTR)
#define GB_H (128 * GSTR)
#define GST_H (GA_H + GB_H)
#define HSMEM (3 * GST_H * 2)

template <int OP>
__global__ __launch_bounds__(512, 1) void k_hgemm(const __half* __restrict__ A,
                                                  const __half* __restrict__ W,
                                                  const float* __restrict__ bias,
                                                  void* __restrict__ Cout,
                                                  const float* __restrict__ resid,
                                                  const float* __restrict__ t6, int gi,
                                                  __half* __restrict__ xcopy,
                                                  int M, int Nn, int K) {
    extern __shared__ __half smh[];
    const uint32_t sbase = smem_u32(smh);

    const int tid = threadIdx.x;
    const int m0 = blockIdx.y * 256, n0 = blockIdx.x * 128;
    const int wid = tid >> 5, lane = tid & 31;
    const int wr = wid & 3, wc = wid >> 2;
    const int warp_m = wr * 64, warp_n = wc * 32;
    const int qr = lane >> 2, qc = lane & 3;
    const int lane7 = lane & 7, sel = lane >> 3;

    const int a_row = warp_m + lane7 + (sel & 1) * 8;
    const int a_col = (sel >> 1) * 8;
    const int b_row = warp_n + lane7 + (sel >> 1) * 8;
    const int b_col = (sel & 1) * 8;

    float acc[4][4][4];
#pragma unroll
    for (int mi = 0; mi < 4; mi++)
#pragma unroll
        for (int ni = 0; ni < 4; ni++)
#pragma unroll
            for (int c = 0; c < 4; c++) acc[mi][ni][c] = 0.f;

    auto load_tile = [&](int stg, int kb) {
        uint32_t as = sbase + (uint32_t)(stg * GST_H) * 2u;
        uint32_t bs = as + GA_H * 2u;
#pragma unroll
        for (int i = 0; i < 4; i++) {
            int idx = tid + i * 512;
            int m = idx >> 3, c8 = (idx & 7) * 8;
            int gm = m0 + m; if (gm >= M) gm = M - 1;
            cp_async16u(as + (uint32_t)(m * GSTR + c8) * 2u, A + (size_t)gm * K + kb + c8);
        }
#pragma unroll
        for (int i = 0; i < 2; i++) {
            int idx = tid + i * 512;
            int m = idx >> 3, c8 = (idx & 7) * 8;
            cp_async16u(bs + (uint32_t)(m * GSTR + c8) * 2u, W + (size_t)(n0 + m) * K + kb + c8);
        }
    };

    const int KT = K >> 6;
    load_tile(0, 0); cp_commit();
    load_tile(1, 64); cp_commit();

    for (int t = 0; t < KT; ++t) {
        if (t + 1 < KT) cp_wait<1>(); else cp_wait<0>();
        __syncthreads();
        if (t + 2 < KT) { load_tile((t + 2) % 3, (t + 2) << 6); }
        cp_commit();

        uint32_t as = sbase + (uint32_t)((t % 3) * GST_H) * 2u;
        uint32_t bs = as + GA_H * 2u;
        uint32_t aaddr = as + (uint32_t)(a_row * GSTR + a_col) * 2u;
        uint32_t baddr = bs + (uint32_t)(b_row * GSTR + b_col) * 2u;

#pragma unroll
        for (int kk = 0; kk < 64; kk += 16) {
            uint32_t af[4][4], bq[2][4];
#pragma unroll
            for (int mi = 0; mi < 4; mi++)
                LDSM4(af[mi], aaddr + (uint32_t)(mi * 16 * GSTR + kk) * 2u);
#pragma unroll
            for (int nip = 0; nip < 2; nip++)
                LDSM4(bq[nip], baddr + (uint32_t)(nip * 16 * GSTR + kk) * 2u);
#pragma unroll
            for (int mi = 0; mi < 4; mi++)
#pragma unroll
                for (int ni = 0; ni < 4; ni++)
                    MMA_F16(acc[mi][ni], af[mi], bq[ni >> 1][(ni & 1) * 2],
                            bq[ni >> 1][(ni & 1) * 2 + 1]);
        }
        __syncthreads();
    }

    const int b = m0 >> 12;
    const float* gate = ((OP == 3 || OP == 4) && gi >= 0)
                            ? t6 + (size_t)(b * 6 + gi) * CC : nullptr;

#pragma unroll
    for (int mi = 0; mi < 4; mi++) {
        int r0 = m0 + warp_m + mi * 16 + qr;
        int r1 = r0 + 8;
#pragma unroll
        for (int ni = 0; ni < 4; ni++) {
            int c0 = n0 + warp_n + ni * 8 + qc * 2;
            float b0 = bias[c0], b1 = bias[c0 + 1];
            float v[4] = {acc[mi][ni][0] + b0, acc[mi][ni][1] + b1,
                          acc[mi][ni][2] + b0, acc[mi][ni][3] + b1};
            if (OP == 2) {
#pragma unroll
                for (int c = 0; c < 4; c++) v[c] = gelu_tanh(v[c]);
            }
            if (OP == 0 || OP == 2) {
                __half* C = (__half*)Cout;
                if (r0 < M)
                    *(__half2*)(C + (size_t)r0 * Nn + c0) =
                        __halves2half2(__float2half_rn(v[0]), __float2half_rn(v[1]));
                if (r1 < M)
                    *(__half2*)(C + (size_t)r1 * Nn + c0) =
                        __halves2half2(__float2half_rn(v[2]), __float2half_rn(v[3]));
            } else if (OP == 3) {
                float* C = (float*)Cout;
                float g0 = gate ? gate[c0] : 1.f;
                float g1 = gate ? gate[c0 + 1] : 1.f;
                if (r0 < M) {
                    const float* rr = resid + (size_t)r0 * Nn;
                    float* cw = C + (size_t)r0 * Nn;
                    cw[c0] = rr[c0] + g0 * v[0];
                    cw[c0 + 1] = rr[c0 + 1] + g1 * v[1];
                }
                if (r1 < M) {
                    const float* rr = resid + (size_t)r1 * Nn;
                    float* cw = C + (size_t)r1 * Nn;
                    cw[c0] = rr[c0] + g0 * v[2];
                    cw[c0 + 1] = rr[c0 + 1] + g1 * v[3];
                }
            } else {  // OP == 4: temporal scatter + half copy
                float* C = (float*)Cout;
                float g0 = gate[c0], g1 = gate[c0 + 1];
#pragma unroll
                for (int hf = 0; hf < 2; hf++) {
                    int r = hf ? r1 : r0;
                    int rem = r & 4095;
                    int s = rem >> 4, tt = rem & 15;
                    size_t xr = ((size_t)(r >> 12) * 4096 + tt * 256 + s) * Nn;
                    float nv0 = C[xr + c0] + g0 * v[hf * 2];
                    float nv1 = C[xr + c0 + 1] + g1 * v[hf * 2 + 1];
                    C[xr + c0] = nv0;
                    C[xr + c0 + 1] = nv1;
                    *(__half2*)(xcopy + xr + c0) =
                        __halves2half2(__float2half_rn(nv0), __float2half_rn(nv1));
                }
            }
        }
    }
}

// ================= fp16 attention scores (K = 72, one-shot smem) =================
#define SSTR 88

template <int DOSM>
__global__ __launch_bounds__(256) void k_scores_h(const __half* __restrict__ Q,
                                                  const __half* __restrict__ Kd,
                                                  __half* __restrict__ out,
                                                  int heads, int Sq, int Sk,
                                                  int qRS, int kRS, long qBS, long kBS,
                                                  float scale) {
    __shared__ __half As[128 * SSTR];
    __shared__ __half Bs[128 * SSTR];
    __shared__ float red[128][4];

    const int tid = threadIdx.x;
    int z = blockIdx.z;
    int b = z / heads, h = z - b * heads;
    const __half* qb = Q + (long)b * qBS + h * CHD;
    const __half* kb = Kd + (long)b * kBS + h * CHD;
    const int i0 = blockIdx.y * 128, j0 = blockIdx.x * 128;
    const int wid = tid >> 5, lane = tid & 31;
    const int wr = wid >> 2, wc = wid & 3;
    const int warp_m = wr * 64, warp_n = wc * 32;
    const int qr = lane >> 2, qc = lane & 3;

    for (int idx = tid; idx < 128 * 11; idx += 256) {
        int m = idx / 11, c = idx - m * 11;
        int sz = (c < 9) ? 16 : 0;
        int gq = i0 + m; if (gq >= Sq) gq = Sq - 1;
        int gk = j0 + m; if (gk >= Sk) gk = Sk - 1;
        cp_async16z(&As[m * SSTR + c * 8], qb + (long)gq * qRS + c * 8, sz);
        cp_async16z(&Bs[m * SSTR + c * 8], kb + (long)gk * kRS + c * 8, sz);
    }
    cp_commit();
    cp_wait<0>();
    __syncthreads();

    float acc[4][4][4];
#pragma unroll
    for (int mi = 0; mi < 4; mi++)
#pragma unroll
        for (int ni = 0; ni < 4; ni++)
#pragma unroll
            for (int c = 0; c < 4; c++) acc[mi][ni][c] = 0.f;

#pragma unroll
    for (int kk = 0; kk < 80; kk += 16) {
        uint32_t af[4][4], bf[4][2];
#pragma unroll
        for (int mi = 0; mi < 4; mi++) {
            const __half* base = &As[(warp_m + mi * 16 + qr) * SSTR + kk + 2 * qc];
            af[mi][0] = *(const uint32_t*)(base);
            af[mi][1] = *(const uint32_t*)(base + 8 * SSTR);
            af[mi][2] = *(const uint32_t*)(base + 8);
            af[mi][3] = *(const uint32_t*)(base + 8 * SSTR + 8);
        }
#pragma unroll
        for (int ni = 0; ni < 4; ni++) {
            const __half* bb = &Bs[(warp_n + ni * 8 + qr) * SSTR + kk + 2 * qc];
            bf[ni][0] = *(const uint32_t*)(bb);
            bf[ni][1] = *(const uint32_t*)(bb + 8);
        }
#pragma unroll
        for (int mi = 0; mi < 4; mi++)
#pragma unroll
            for (int ni = 0; ni < 4; ni++) MMA_F16B(acc[mi][ni], af[mi], bf[ni]);
    }

    __half* ob = out + (long)z * Sq * Sk;

    if (DOSM == 0) {
#pragma unroll
        for (int mi = 0; mi < 4; mi++) {
            int r0 = i0 + warp_m + mi * 16 + qr;
            int r1 = r0 + 8;
#pragma unroll
            for (int ni = 0; ni < 4; ni++) {
                int c0 = j0 + warp_n + ni * 8 + qc * 2;
                if (c0 < Sk) {
                    if (r0 < Sq)
                        *(__half2*)(ob + (long)r0 * Sk + c0) =
                            __halves2half2(__float2half_rn(acc[mi][ni][0] * scale),
                                           __float2half_rn(acc[mi][ni][1] * scale));
                    if (r1 < Sq)
                        *(__half2*)(ob + (long)r1 * Sk + c0) =
                            __halves2half2(__float2half_rn(acc[mi][ni][2] * scale),
                                           __float2half_rn(acc[mi][ni][3] * scale));
                }
            }
        }
        return;
    }

#pragma unroll
    for (int mi = 0; mi < 4; mi++)
#pragma unroll
        for (int ni = 0; ni < 4; ni++)
#pragma unroll
            for (int c = 0; c < 4; c++) acc[mi][ni][c] *= scale;

    float mrow[4][2], srow[4][2];
#pragma unroll
    for (int mi = 0; mi < 4; mi++)
#pragma unroll
        for (int hf = 0; hf < 2; hf++) {
            float m = -FLT_MAX;
#pragma unroll
            for (int ni = 0; ni < 4; ni++) {
                int c0 = warp_n + ni * 8 + qc * 2;
                if (c0 < Sk) m = fmaxf(m, acc[mi][ni][hf * 2]);
                if (c0 + 1 < Sk) m = fmaxf(m, acc[mi][ni][hf * 2 + 1]);
            }
            m = fmaxf(m, __shfl_xor_sync(0xffffffffu, m, 1));
            m = fmaxf(m, __shfl_xor_sync(0xffffffffu, m, 2));
            if (qc == 0) red[warp_m + mi * 16 + qr + hf * 8][wc] = m;
        }
    __syncthreads();
#pragma unroll
    for (int mi = 0; mi < 4; mi++)
#pragma unroll
        for (int hf = 0; hf < 2; hf++) {
            int rl = warp_m + mi * 16 + qr + hf * 8;
            mrow[mi][hf] = fmaxf(fmaxf(red[rl][0], red[rl][1]), fmaxf(red[rl][2], red[rl][3]));
        }
    __syncthreads();
#pragma unroll
    for (int mi = 0; mi < 4; mi++)
#pragma unroll
        for (int hf = 0; hf < 2; hf++) {
            float s = 0.f;
#pragma unroll
            for (int ni = 0; ni < 4; ni++) {
                int c0 = warp_n + ni * 8 + qc * 2;
                float e0 = (c0 < Sk) ? expf(acc[mi][ni][hf * 2] - mrow[mi][hf]) : 0.f;
                float e1 = (c0 + 1 < Sk) ? expf(acc[mi][ni][hf * 2 + 1] - mrow[mi][hf]) : 0.f;
                acc[mi][ni][hf * 2] = e0;
                acc[mi][ni][hf * 2 + 1] = e1;
                s += e0 + e1;
            }
            s += __shfl_xor_sync(0xffffffffu, s, 1);
            s += __shfl_xor_sync(0xffffffffu, s, 2);
            if (qc == 0) red[warp_m + mi * 16 + qr + hf * 8][wc] = s;
        }
    __syncthreads();
#pragma unroll
    for (int mi = 0; mi < 4; mi++)
#pragma unroll
        for (int hf = 0; hf < 2; hf++) {
            int rl = warp_m + mi * 16 + qr + hf * 8;
            srow[mi][hf] = 1.f / (red[rl][0] + red[rl][1] + red[rl][2] + red[rl][3]);
        }
#pragma unroll
    for (int mi = 0; mi < 4; mi++) {
        int r0 = i0 + warp_m + mi * 16 + qr;
        int r1 = r0 + 8;
#pragma unroll
        for (int ni = 0; ni < 4; ni++) {
            int c0 = warp_n + ni * 8 + qc * 2;
            if (c0 < Sk) {
                *(__half2*)(ob + (long)r0 * Sk + c0) =
                    __halves2half2(__float2half_rn(acc[mi][ni][0] * srow[mi][0]),
                                   __float2half_rn(acc[mi][ni][1] * srow[mi][0]));
                *(__half2*)(ob + (long)r1 * Sk + c0) =
                    __halves2half2(__float2half_rn(acc[mi][ni][2] * srow[mi][1]),
                                   __float2half_rn(acc[mi][ni][3] * srow[mi][1]));
            }
        }
    }
}

// ================= spatial scores + fused softmax (Sq tile 128, Sk = 256) =======
// 8 warps: wr = wid&1 (2 x 64 rows), wc = wid>>1 (4 x 64 cols). Dynamic smem.
#define SMSM (128 * SSTR * 2 + 256 * SSTR * 2)   // 67584 bytes

__global__ __launch_bounds__(256) void k_scores_sm(const __half* __restrict__ Q,
                                                   const __half* __restrict__ Kd,
                                                   __half* __restrict__ out,
                                                   int heads, float scale) {
    extern __shared__ __half ssm[];
    __half* As = ssm;                 // 128 x 88
    __half* Bs = ssm + 128 * SSTR;    // 256 x 88
    __shared__ float red[128][4];

    const int tid = threadIdx.x;
    int z = blockIdx.z;
    int b = z / heads, h = z - b * heads;
    const __half* qb = Q + (long)b * (CS * 3L * CC) + h * CHD;
    const __half* kb = Kd + (long)b * (CS * 3L * CC) + h * CHD;
    const int i0 = blockIdx.y * 128;
    const int wid = tid >> 5, lane = tid & 31;
    const int wr = wid & 1, wc = wid >> 1;
    const int warp_m = wr * 64, warp_n = wc * 64;
    const int qr = lane >> 2, qc = lane & 3;

    for (int idx = tid; idx < 128 * 11; idx += 256) {
        int m = idx / 11, c = idx - m * 11;
        int sz = (c < 9) ? 16 : 0;
        cp_async16z(&As[m * SSTR + c * 8], qb + (long)(i0 + m) * (3 * CC) + c * 8, sz);
    }
    for (int idx = tid; idx < 256 * 11; idx += 256) {
        int m = idx / 11, c = idx - m * 11;
        int sz = (c < 9) ? 16 : 0;
        cp_async16z(&Bs[m * SSTR + c * 8], kb + (long)m * (3 * CC) + c * 8, sz);
    }
    cp_commit();
    cp_wait<0>();
    __syncthreads();

    float acc[4][8][4];
#pragma unroll
    for (int mi = 0; mi < 4; mi++)
#pragma unroll
        for (int ni = 0; ni < 8; ni++)
#pragma unroll
            for (int c = 0; c < 4; c++) acc[mi][ni][c] = 0.f;

#pragma unroll
    for (int kk = 0; kk < 80; kk += 16) {
        uint32_t af[4][4], bf[8][2];
#pragma unroll
        for (int mi = 0; mi < 4; mi++) {
            const __half* base = &As[(warp_m + mi * 16 + qr) * SSTR + kk + 2 * qc];
            af[mi][0] = *(const uint32_t*)(base);
            af[mi][1] = *(const uint32_t*)(base + 8 * SSTR);
            af[mi][2] = *(const uint32_t*)(base + 8);
            af[mi][3] = *(const uint32_t*)(base + 8 * SSTR + 8);
        }
#pragma unroll
        for (int ni = 0; ni < 8; ni++) {
            const __half* bb = &Bs[(warp_n + ni * 8 + qr) * SSTR + kk + 2 * qc];
            bf[ni][0] = *(const uint32_t*)(bb);
            bf[ni][1] = *(const uint32_t*)(bb + 8);
        }
#pragma unroll
        for (int mi = 0; mi < 4; mi++)
#pragma unroll
            for (int ni = 0; ni < 8; ni++) MMA_F16B(acc[mi][ni], af[mi], bf[ni]);
    }

    // fused softmax over full Sk = 256 (scale then normalize)
#pragma unroll
    for (int mi = 0; mi < 4; mi++)
#pragma unroll
        for (int ni = 0; ni < 8; ni++)
#pragma unroll
            for (int c = 0; c < 4; c++) acc[mi][ni][c] *= scale;

    float mrow[4][2], srow[4][2];
#pragma unroll
    for (int mi = 0; mi < 4; mi++)
#pragma unroll
        for (int hf = 0; hf < 2; hf++) {
            float m = -FLT_MAX;
#pragma unroll
            for (int ni = 0; ni < 8; ni++) {
                m = fmaxf(m, acc[mi][ni][hf * 2]);
                m = fmaxf(m, acc[mi][ni][hf * 2 + 1]);
            }
            m = fmaxf(m, __shfl_xor_sync(0xffffffffu, m, 1));
            m = fmaxf(m, __shfl_xor_sync(0xffffffffu, m, 2));
            if (qc == 0) red[warp_m + mi * 16 + qr + hf * 8][wc] = m;
        }
    __syncthreads();
#pragma unroll
    for (int mi = 0; mi < 4; mi++)
#pragma unroll
        for (int hf = 0; hf < 2; hf++) {
            int rl = warp_m + mi * 16 + qr + hf * 8;
            mrow[mi][hf] = fmaxf(fmaxf(red[rl][0], red[rl][1]), fmaxf(red[rl][2], red[rl][3]));
        }
    __syncthreads();
#pragma unroll
    for (int mi = 0; mi < 4; mi++)
#pragma unroll
        for (int hf = 0; hf < 2; hf++) {
            float s = 0.f;
#pragma unroll
            for (int ni = 0; ni < 8; ni++) {
                float e0 = expf(acc[mi][ni][hf * 2] - mrow[mi][hf]);
                float e1 = expf(acc[mi][ni][hf * 2 + 1] - mrow[mi][hf]);
                acc[mi][ni][hf * 2] = e0;
                acc[mi][ni][hf * 2 + 1] = e1;
                s += e0 + e1;
            }
            s += __shfl_xor_sync(0xffffffffu, s, 1);
            s += __shfl_xor_sync(0xffffffffu, s, 2);
            if (qc == 0) red[warp_m + mi * 16 + qr + hf * 8][wc] = s;
        }
    __syncthreads();
#pragma unroll
    for (int mi = 0; mi < 4; mi++)
#pragma unroll
        for (int hf = 0; hf < 2; hf++) {
            int rl = warp_m + mi * 16 + qr + hf * 8;
            srow[mi][hf] = 1.f / (red[rl][0] + red[rl][1] + red[rl][2] + red[rl][3]);
        }

    __half* ob = out + (long)z * CS * CS;
#pragma unroll
    for (int mi = 0; mi < 4; mi++) {
        int r0 = i0 + warp_m + mi * 16 + qr;
        int r1 = r0 + 8;
#pragma unroll
        for (int ni = 0; ni < 8; ni++) {
            int c0 = warp_n + ni * 8 + qc * 2;
            *(__half2*)(ob + (long)r0 * CS + c0) =
                __halves2half2(__float2half_rn(acc[mi][ni][0] * srow[mi][0]),
                               __float2half_rn(acc[mi][ni][1] * srow[mi][0]));
            *(__half2*)(ob + (long)r1 * CS + c0) =
                __halves2half2(__float2half_rn(acc[mi][ni][2] * srow[mi][1]),
                               __float2half_rn(acc[mi][ni][3] * srow[mi][1]));
        }
    }
}

// ================= fp16 attn@V =================
#define PSTR 24
__global__ __launch_bounds__(256) void k_av_h(const __half* __restrict__ P,
                                              const __half* __restrict__ V,
                                              __half* __restrict__ O,
                                              int heads, int Sq, int Sk,
                                              int vRS, long vBS, int oRS, long oBS) {
    __shared__ __half As[2][128 * PSTR];
    __shared__ __half Vs[2][72 * PSTR];

    const int tid = threadIdx.x;
    int z = blockIdx.y;
    int b = z / heads, h = z - b * heads;
    const __half* Pb = P + (long)z * Sq * Sk;
    const __half* Vb = V + (long)b * vBS + h * CHD;
    __half* Ob = O + (long)b * oBS + h * CHD;
    const int i0 = blockIdx.x * 128;
    const int wid = tid >> 5, lane = tid & 31;
    const int warp_m = wid * 16;
    const int qr = lane >> 2, qc = lane & 3;

    float acc[9][4];
#pragma unroll
    for (int nt = 0; nt < 9; nt++)
#pragma unroll
        for (int c = 0; c < 4; c++) acc[nt][c] = 0.f;

    auto load_tile = [&](int stg, int kb) {
        for (int idx = tid; idx < 256; idx += 256) {
            int m = idx >> 1;
            int c = idx & 1;
            int sz = (kb + c * 8 + 8 <= Sk) ? 16 : 0;
            int gi = i0 + m; if (gi >= Sq) gi = Sq - 1;
            cp_async16z(&As[stg][m * PSTR + c * 8], Pb + (long)gi * Sk + kb + c * 8, sz);
        }
        for (int idx = tid; idx < 576; idx += 256) {
            int key = idx / 36, d2 = idx - key * 36;
            __half2 v = (kb + key < Sk)
                            ? *(const __half2*)(Vb + (long)(kb + key) * vRS + 2 * d2)
                            : __halves2half2(__float2half_rn(0.f), __float2half_rn(0.f));
            Vs[stg][(2 * d2) * PSTR + key] = __low2half(v);
            Vs[stg][(2 * d2 + 1) * PSTR + key] = __high2half(v);
        }
    };

    const int KT = (Sk + 15) >> 4;
    load_tile(0, 0);
    cp_commit();

    for (int kt = 0; kt < KT; ++kt) {
        int cur = kt & 1;
        if (kt + 1 < KT) {
            load_tile(1 - cur, (kt + 1) << 4);
            cp_commit();
            cp_wait<1>();
        } else {
            cp_wait<0>();
        }
        __syncthreads();

        uint32_t af[4];
        const __half* abase = &As[cur][(warp_m + qr) * PSTR + 2 * qc];
        af[0] = *(const uint32_t*)(abase);
        af[1] = *(const uint32_t*)(abase + 8 * PSTR);
        af[2] = *(const uint32_t*)(abase + 8);
        af[3] = *(const uint32_t*)(abase + 8 * PSTR + 8);
#pragma unroll
        for (int nt = 0; nt < 9; nt++) {
            uint32_t bf[2];
            const __half* bb = &Vs[cur][(nt * 8 + qr) * PSTR + 2 * qc];
            bf[0] = *(const uint32_t*)(bb);
            bf[1] = *(const uint32_t*)(bb + 8);
            MMA_F16B(acc[nt], af, bf);
        }
        __syncthreads();
    }

    int r0 = i0 + warp_m + qr;
    int r1 = r0 + 8;
#pragma unroll
    for (int nt = 0; nt < 9; nt++) {
        int c0 = nt * 8 + qc * 2;
        if (r0 < Sq)
            *(__half2*)(Ob + (long)r0 * oRS + c0) =
                __halves2half2(__float2half_rn(acc[nt][0]), __float2half_rn(acc[nt][1]));
        if (r1 < Sq)
            *(__half2*)(Ob + (long)r1 * oRS + c0) =
                __halves2half2(__float2half_rn(acc[nt][2]), __float2half_rn(acc[nt][3]));
    }
}

// ---------------- fused temporal attention (T=16, causal; half in/out) -------
__global__ __launch_bounds__(128) void k_attn_t(const __half* __restrict__ qkv,
                                                __half* __restrict__ O, float scale) {
    __shared__ float q[16][72], k[16][72], v[16][72], p[16][17];
    int h = blockIdx.x;
    int bs = blockIdx.y;
    const __half* base = qkv + (size_t)bs * CT * 3 * CC + h * CHD;
    int tid = threadIdx.x;

    for (int idx = tid; idx < 16 * 72; idx += 128) {
        int t = idx / 72, d = idx - t * 72;
        const __half* row = base + (size_t)t * 3 * CC;
        q[t][d] = __half2float(row[d]);
        k[t][d] = __half2float(row[CC + d]);
        v[t][d] = __half2float(row[2 * CC + d]);
    }
    __syncthreads();

    for (int e = tid; e < 256; e += 128) {
        int i = e >> 4, j = e & 15;
        float acc = 0.f;
#pragma unroll 8
        for (int d = 0; d < 72; d++) acc += q[i][d] * k[j][d];
        p[i][j] = acc * scale;
    }
    __syncthreads();

    if (tid < 16) {
        int i = tid;
        float m = -FLT_MAX;
        for (int j = 0; j <= i; j++) m = fmaxf(m, p[i][j]);
        float s = 0.f;
        for (int j = 0; j <= i; j++) { float e = expf(p[i][j] - m); p[i][j] = e; s += e; }
        float inv = 1.f / s;
        for (int j = 0; j <= i; j++) p[i][j] *= inv;
        for (int j = i + 1; j < 16; j++) p[i][j] = 0.f;
    }
    __syncthreads();

    for (int e = tid; e < 16 * 72; e += 128) {
        int t = e / 72, d = e - t * 72;
        float acc = 0.f;
#pragma unroll
        for (int j = 0; j < 16; j++) acc += p[t][j] * v[j][d];
        O[((size_t)bs * CT + t) * CC + h * CHD + d] = __float2half_rn(acc);
    }
}

// ---------------- build temporal input (half out) ----------------
__global__ void k_xt_build(const float* __restrict__ X, const float* __restrict__ tpe,
                           __half* __restrict__ out) {
    int r = blockIdx.x;
    int t = r & 15;
    int bs = r >> 4;
    int s = bs & 255;
    int b = bs >> 8;
    const float* xr = X + ((size_t)b * CN + t * CS + s) * CC;
    const float* tp = tpe + (size_t)t * CC;
    __half* orow = out + (size_t)r * CC;
#pragma unroll
    for (int i = 0; i < 4; i++) {
        int c = threadIdx.x + i * 288;
        orow[c] = __float2half_rn(xr[c] + tp[c]);
    }
}

// =======================================================================
extern "C" void kernel_launch(void* const* d_in, const int* in_sizes, int n_in,
                              void* d_out, int out_size) {
    const float* x      = (const float*)d_in[0];
    const float* y      = (const float*)d_in[1];
    const float* t      = (const float*)d_in[2];
    const float* tpe    = (const float*)d_in[3];
    const float* sst    = (const float*)d_in[4];
    const float* qkv_s_w = (const float*)d_in[5];
    const float* qkv_s_b = (const float*)d_in[6];
    const float* proj_s_w = (const float*)d_in[7];
    const float* proj_s_b = (const float*)d_in[8];
    const float* qkv_t_w = (const float*)d_in[9];
    const float* qkv_t_b = (const float*)d_in[10];
    const float* proj_t_w = (const float*)d_in[11];
    const float* proj_t_b = (const float*)d_in[12];
    const float* q_c_w  = (const float*)d_in[13];
    const float* q_c_b  = (const float*)d_in[14];
    const float* kv_c_w = (const float*)d_in[15];
    const float* kv_c_b = (const float*)d_in[16];
    const float* proj_c_w = (const float*)d_in[17];
    const float* proj_c_b = (const float*)d_in[18];
    const float* fc1_w  = (const float*)d_in[19];
    const float* fc1_b  = (const float*)d_in[20];
    const float* fc2_w  = (const float*)d_in[21];
    const float* fc2_b  = (const float*)d_in[22];
    float* X = (float*)d_out;

    float *p_t6, *p_xm, *p_qkv, *p_att, *p_h, *p_sc, *p_kv, *p_w, *p_yr;
    cudaGetSymbolAddress((void**)&p_t6, g_t6);
    cudaGetSymbolAddress((void**)&p_xm, g_xm);
    cudaGetSymbolAddress((void**)&p_qkv, g_qkv);
    cudaGetSymbolAddress((void**)&p_att, g_att);
    cudaGetSymbolAddress((void**)&p_h, g_h);
    cudaGetSymbolAddress((void**)&p_sc, g_sc);
    cudaGetSymbolAddress((void**)&p_kv, g_kv);
    cudaGetSymbolAddress((void**)&p_w, g_w);
    cudaGetSymbolAddress((void**)&p_yr, g_yr);

    // half-typed aliases
    __half* h_xm  = (__half*)p_xm;
    __half* h_qkv = (__half*)p_qkv;
    __half* h_att = (__half*)p_att;
    __half* h_h   = (__half*)p_h;
    __half* h_sc  = (__half*)p_sc;
    __half* h_kv  = (__half*)p_kv;
    __half* h_w   = (__half*)p_w;
    __half* h_yr  = (__half*)p_yr;

    const float scale = 0.11785113019775793f;  // 1/sqrt(72)

    static int attr_set = 0;
    if (!attr_set) {
        cudaFuncSetAttribute((const void*)k_hgemm<0>, cudaFuncAttributeMaxDynamicSharedMemorySize, HSMEM);
        cudaFuncSetAttribute((const void*)k_hgemm<2>, cudaFuncAttributeMaxDynamicSharedMemorySize, HSMEM);
        cudaFuncSetAttribute((const void*)k_hgemm<3>, cudaFuncAttributeMaxDynamicSharedMemorySize, HSMEM);
        cudaFuncSetAttribute((const void*)k_hgemm<4>, cudaFuncAttributeMaxDynamicSharedMemorySize, HSMEM);
        cudaFuncSetAttribute((const void*)k_scores_sm, cudaFuncAttributeMaxDynamicSharedMemorySize, SMSM);
        attr_set = 1;
    }

    // half weight copies
    __half* w_qkv_s = h_w + (size_t)0 * CC2;
    __half* w_proj_s = h_w + (size_t)3 * CC2;
    __half* w_qkv_t = h_w + (size_t)4 * CC2;
    __half* w_proj_t = h_w + (size_t)7 * CC2;
    __half* w_q_c   = h_w + (size_t)8 * CC2;
    __half* w_kv_c  = h_w + (size_t)9 * CC2;
    __half* w_proj_c = h_w + (size_t)11 * CC2;
    __half* w_fc1   = h_w + (size_t)12 * CC2;
    __half* w_fc2   = h_w + (size_t)16 * CC2;

    auto rnd = [&](const float* src, __half* dst, size_t n) {
        k_round_h<<<(int)((n + 255) / 256), 256>>>(src, dst, (int)n);
    };
    rnd(qkv_s_w, w_qkv_s, (size_t)3 * CC2);
    rnd(proj_s_w, w_proj_s, CC2);
    rnd(qkv_t_w, w_qkv_t, (size_t)3 * CC2);
    rnd(proj_t_w, w_proj_t, CC2);
    rnd(q_c_w, w_q_c, CC2);
    rnd(kv_c_w, w_kv_c, (size_t)2 * CC2);
    rnd(proj_c_w, w_proj_c, CC2);
    rnd(fc1_w, w_fc1, (size_t)4 * CC2);
    rnd(fc2_w, w_fc2, (size_t)4 * CC2);
    rnd(y, h_yr, (size_t)CB * CYL * CC);

    k_mod<<<(CB * 6 * CC + 255) / 256, 256>>>(t, sst, p_t6);

#define HG(OP, A, W, B, C, R, gi, XC, M, Nn, K) \
    k_hgemm<OP><<<dim3((Nn) / 128, ((M) + 255) / 256), 512, HSMEM>>>(A, W, B, C, R, p_t6, gi, XC, M, Nn, K)

    // ---- spatial attention (all fp16, softmax fused into scores) ----
    k_ln_mod<<<NROW, 288>>>(x, p_t6, h_xm, 0, 1);
    HG(0, h_xm, w_qkv_s, qkv_s_b, h_qkv, nullptr, 0, (__half*)nullptr, NROW, 3 * CC, CC);
    k_scores_sm<<<dim3(1, 2, CB * CT * CNH), 256, SMSM>>>(h_qkv, h_qkv + CC, h_sc, CNH, scale);
    k_av_h<<<dim3(2, CB * CT * CNH), 256>>>(h_sc, h_qkv + 2 * CC, h_att, CNH, CS, CS,
                                            3 * CC, (long)CS * 3 * CC, CC, (long)CS * CC);
    HG(3, h_att, w_proj_s, proj_s_b, X, x, 2, (__half*)nullptr, NROW, CC, CC);  // X = x + g*proj

    // ---- temporal attention (causal, fused; scatter fused into proj_t) ----
    k_xt_build<<<NROW, 288>>>(X, tpe, h_xm);
    HG(0, h_xm, w_qkv_t, qkv_t_b, h_qkv, nullptr, 0, (__half*)nullptr, NROW, 3 * CC, CC);
    k_attn_t<<<dim3(CNH, CB * CS), 128>>>(h_qkv, h_att, scale);
    HG(4, h_att, w_proj_t, proj_t_b, X, nullptr, 2, h_h, NROW, CC, CC);  // X[perm] += g*proj; h_h copy

    // ---- cross attention (fp16, fused softmax) ----
    HG(0, h_h, w_q_c, q_c_b, h_qkv, nullptr, 0, (__half*)nullptr, NROW, CC, CC);
    HG(0, h_yr, w_kv_c, kv_c_b, h_kv, nullptr, 0, (__half*)nullptr, CB * CYL, 2 * CC, CC);
    k_scores_h<1><<<dim3(1, CN / 128, CB * CNH), 256>>>(h_qkv, h_kv, h_sc, CNH, CN, CYL,
                                                        CC, 2 * CC,
                                                        (long)CN * CC, (long)CYL * 2 * CC, scale);
    k_av_h<<<dim3(CN / 128, CB * CNH), 256>>>(h_sc, h_kv + CC, h_att, CNH, CN, CYL,
                                              2 * CC, (long)CYL * 2 * CC, CC, (long)CN * CC);
    HG(3, h_att, w_proj_c, proj_c_b, X, X, -1, (__half*)nullptr, NROW, CC, CC); // X += proj

    // ---- MLP ----
    k_ln_mod<<<NROW, 288>>>(X, p_t6, h_xm, 3, 4);
    HG(2, h_xm, w_fc1, fc1_b, h_h, nullptr, 0, (__half*)nullptr, NROW, 4 * CC, CC);
    HG(3, h_h, w_fc2, fc2_b, X, X, 5, (__half*)nullptr, NROW, CC, 4 * CC);      // X += g*fc2
}

// round 17
// speedup vs baseline: 2.2048x; 1.0036x over previous
#include <cuda_runtime.h>
#include <cuda_fp16.h>
#include <math.h>
#include <float.h>
#include <stdint.h>

// ---------------- problem constants ----------------
#define CB   4
#define CT   16
#define CS   256
#define CN   4096
#define CC   1152
#define CNH  16
#define CHD  72
#define CYL  120
#define NROW 16384
#define CC2  (CC * CC)

// ---------------- scratch (device globals) ----------------
__device__ float g_t6[CB * 6 * CC];
__device__ float g_xm[(size_t)NROW * CC];
__device__ float g_qkv[(size_t)NROW * 3 * CC];
__device__ float g_att[(size_t)NROW * CC];
__device__ float g_h[(size_t)NROW * 4 * CC];
__device__ float g_sc[67108864UL];
__device__ float g_kv[CB * CYL * 2 * CC];
__device__ float g_w[20 * CC2];                 // half weights (aliased)
__device__ float g_yr[CB * CYL * CC];           // half y (aliased)

// ---------------- helpers ----------------
__device__ __forceinline__ float gelu_tanh(float x) {
    float x3 = x * x * x;
    return 0.5f * x * (1.f + tanhf(0.7978845608028654f * (x + 0.044715f * x3)));
}
__device__ __forceinline__ uint32_t smem_u32(const void* p) {
    return (uint32_t)__cvta_generic_to_shared(p);
}
__device__ __forceinline__ void cp_async16u(uint32_t s, const void* g) {
    asm volatile("cp.async.cg.shared.global [%0], [%1], 16;\n" :: "r"(s), "l"(g));
}
__device__ __forceinline__ void cp_async16(void* smem, const void* gmem) {
    cp_async16u(smem_u32(smem), gmem);
}
__device__ __forceinline__ void cp_async16z(void* smem, const void* gmem, int sz) {
    uint32_t s = smem_u32(smem);
    asm volatile("cp.async.cg.shared.global [%0], [%1], 16, %2;\n" :: "r"(s), "l"(gmem), "r"(sz));
}
__device__ __forceinline__ void cp_commit() { asm volatile("cp.async.commit_group;\n"); }
template <int Nk>
__device__ __forceinline__ void cp_wait() { asm volatile("cp.async.wait_group %0;\n" :: "n"(Nk)); }

#define MMA_F16(acc, af, bf0, bf1)                                                \
    asm volatile(                                                                 \
        "mma.sync.aligned.m16n8k16.row.col.f32.f16.f16.f32 "                      \
        "{%0,%1,%2,%3}, {%4,%5,%6,%7}, {%8,%9}, {%0,%1,%2,%3};\n"                 \
        : "+f"(acc[0]), "+f"(acc[1]), "+f"(acc[2]), "+f"(acc[3])                  \
        : "r"(af[0]), "r"(af[1]), "r"(af[2]), "r"(af[3]), "r"(bf0), "r"(bf1))

#define MMA_F16B(acc, af, bf)                                                     \
    asm volatile(                                                                 \
        "mma.sync.aligned.m16n8k16.row.col.f32.f16.f16.f32 "                      \
        "{%0,%1,%2,%3}, {%4,%5,%6,%7}, {%8,%9}, {%0,%1,%2,%3};\n"                 \
        : "+f"(acc[0]), "+f"(acc[1]), "+f"(acc[2]), "+f"(acc[3])                  \
        : "r"(af[0]), "r"(af[1]), "r"(af[2]), "r"(af[3]), "r"(bf[0]), "r"(bf[1]))

#define LDSM4(r, a)                                                               \
    asm volatile("ldmatrix.sync.aligned.m8n8.x4.shared.b16 {%0,%1,%2,%3}, [%4];"  \
                 : "=r"((r)[0]), "=r"((r)[1]), "=r"((r)[2]), "=r"((r)[3])         \
                 : "r"(a))

// ---------------- elementwise: fp32 -> half ----------------
__global__ void k_round_h(const float* __restrict__ a, __half* __restrict__ o, int n) {
    int i = blockIdx.x * blockDim.x + threadIdx.x;
    if (i < n) o[i] = __float2half_rn(a[i]);
}

// ---------------- modulation ----------------
__global__ void k_mod(const float* __restrict__ t, const float* __restrict__ sst,
                      float* __restrict__ t6) {
    int i = blockIdx.x * blockDim.x + threadIdx.x;
    if (i < CB * 6 * CC) t6[i] = sst[i % (6 * CC)] + t[i];
}

// ---------------- LayerNorm + modulate (half output) ----------------
__global__ void k_ln_mod(const float* __restrict__ X, const float* __restrict__ t6,
                         __half* __restrict__ out, int shiftIdx, int scaleIdx) {
    int r = blockIdx.x;
    int b = r >> 12;
    const float* xr = X + (size_t)r * CC;
    const float* sh = t6 + (size_t)(b * 6 + shiftIdx) * CC;
    const float* scl = t6 + (size_t)(b * 6 + scaleIdx) * CC;

    float v[4];
    float s = 0.f, sq = 0.f;
#pragma unroll
    for (int i = 0; i < 4; i++) {
        int c = threadIdx.x + i * 288;
        v[i] = xr[c];
        s += v[i];
        sq += v[i] * v[i];
    }
    __shared__ float s1[9], s2[9], bc[2];
    int lane = threadIdx.x & 31, wid = threadIdx.x >> 5;
#pragma unroll
    for (int off = 16; off > 0; off >>= 1) {
        s += __shfl_xor_sync(0xffffffffu, s, off);
        sq += __shfl_xor_sync(0xffffffffu, sq, off);
    }
    if (lane == 0) { s1[wid] = s; s2[wid] = sq; }
    __syncthreads();
    if (threadIdx.x == 0) {
        float ts = 0.f, tq = 0.f;
        for (int w = 0; w < 9; w++) { ts += s1[w]; tq += s2[w]; }
        float mean = ts * (1.f / CC);
        float var = tq * (1.f / CC) - mean * mean;
        bc[0] = mean;
        bc[1] = rsqrtf(var + 1e-6f);
    }
    __syncthreads();
    float mean = bc[0], rstd = bc[1];
    __half* orow = out + (size_t)r * CC;
#pragma unroll
    for (int i = 0; i < 4; i++) {
        int c = threadIdx.x + i * 288;
        orow[c] = __float2half_rn((v[i] - mean) * rstd * (1.f + scl[c]) + sh[c]);
    }
}

// ================= fp16 dense GEMM: 256x128 tile, 512 threads, LDSM =================
// OP: 0 = half store, 2 = gelu+half store, 3 = fp32 C = resid + gate*(acc+bias),
//     4 = temporal residual scatter: X[perm(r)] += gate*(acc+bias), + half copy
//     5 = OP3 + xt emit: X = resid + gate*(acc+bias); xt[perm(r)] = half(X + tpe[t])
#define GSTR 72
#define GA_H (256 * GSTR)
#define GB_H (128 * GSTR)
#define GST_H (GA_H + GB_H)
#define HSMEM (3 * GST_H * 2)

template <int OP>
__global__ __launch_bounds__(512, 1) void k_hgemm(const __half* __restrict__ A,
                                                  const __half* __restrict__ W,
                                                  const float* __restrict__ bias,
                                                  void* __restrict__ Cout,
                                                  const float* __restrict__ resid,
                                                  const float* __restrict__ t6, int gi,
                                                  __half* __restrict__ xcopy,
                                                  const float* __restrict__ aux,
                                                  int M, int Nn, int K) {
    extern __shared__ __half smh[];
    const uint32_t sbase = smem_u32(smh);

    const int tid = threadIdx.x;
    const int m0 = blockIdx.y * 256, n0 = blockIdx.x * 128;
    const int wid = tid >> 5, lane = tid & 31;
    const int wr = wid & 3, wc = wid >> 2;
    const int warp_m = wr * 64, warp_n = wc * 32;
    const int qr = lane >> 2, qc = lane & 3;
    const int lane7 = lane & 7, sel = lane >> 3;

    const int a_row = warp_m + lane7 + (sel & 1) * 8;
    const int a_col = (sel >> 1) * 8;
    const int b_row = warp_n + lane7 + (sel >> 1) * 8;
    const int b_col = (sel & 1) * 8;

    float acc[4][4][4];
#pragma unroll
    for (int mi = 0; mi < 4; mi++)
#pragma unroll
        for (int ni = 0; ni < 4; ni++)
#pragma unroll
            for (int c = 0; c < 4; c++) acc[mi][ni][c] = 0.f;

    auto load_tile = [&](int stg, int kb) {
        uint32_t as = sbase + (uint32_t)(stg * GST_H) * 2u;
        uint32_t bs = as + GA_H * 2u;
#pragma unroll
        for (int i = 0; i < 4; i++) {
            int idx = tid + i * 512;
            int m = idx >> 3, c8 = (idx & 7) * 8;
            int gm = m0 + m; if (gm >= M) gm = M - 1;
            cp_async16u(as + (uint32_t)(m * GSTR + c8) * 2u, A + (size_t)gm * K + kb + c8);
        }
#pragma unroll
        for (int i = 0; i < 2; i++) {
            int idx = tid + i * 512;
            int m = idx >> 3, c8 = (idx & 7) * 8;
            cp_async16u(bs + (uint32_t)(m * GSTR + c8) * 2u, W + (size_t)(n0 + m) * K + kb + c8);
        }
    };

    const int KT = K >> 6;
    load_tile(0, 0); cp_commit();
    load_tile(1, 64); cp_commit();

    for (int t = 0; t < KT; ++t) {
        if (t + 1 < KT) cp_wait<1>(); else cp_wait<0>();
        __syncthreads();
        if (t + 2 < KT) { load_tile((t + 2) % 3, (t + 2) << 6); }
        cp_commit();

        uint32_t as = sbase + (uint32_t)((t % 3) * GST_H) * 2u;
        uint32_t bs = as + GA_H * 2u;
        uint32_t aaddr = as + (uint32_t)(a_row * GSTR + a_col) * 2u;
        uint32_t baddr = bs + (uint32_t)(b_row * GSTR + b_col) * 2u;

#pragma unroll
        for (int kk = 0; kk < 64; kk += 16) {
            uint32_t af[4][4], bq[2][4];
#pragma unroll
            for (int mi = 0; mi < 4; mi++)
                LDSM4(af[mi], aaddr + (uint32_t)(mi * 16 * GSTR + kk) * 2u);
#pragma unroll
            for (int nip = 0; nip < 2; nip++)
                LDSM4(bq[nip], baddr + (uint32_t)(nip * 16 * GSTR + kk) * 2u);
#pragma unroll
            for (int mi = 0; mi < 4; mi++)
#pragma unroll
                for (int ni = 0; ni < 4; ni++)
                    MMA_F16(acc[mi][ni], af[mi], bq[ni >> 1][(ni & 1) * 2],
                            bq[ni >> 1][(ni & 1) * 2 + 1]);
        }
        __syncthreads();
    }

    const int b = m0 >> 12;
    const float* gate = ((OP >= 3) && gi >= 0) ? t6 + (size_t)(b * 6 + gi) * CC : nullptr;

#pragma unroll
    for (int mi = 0; mi < 4; mi++) {
        int r0 = m0 + warp_m + mi * 16 + qr;
        int r1 = r0 + 8;
#pragma unroll
        for (int ni = 0; ni < 4; ni++) {
            int c0 = n0 + warp_n + ni * 8 + qc * 2;
            float b0 = bias[c0], b1 = bias[c0 + 1];
            float v[4] = {acc[mi][ni][0] + b0, acc[mi][ni][1] + b1,
                          acc[mi][ni][2] + b0, acc[mi][ni][3] + b1};
            if (OP == 2) {
#pragma unroll
                for (int c = 0; c < 4; c++) v[c] = gelu_tanh(v[c]);
            }
            if (OP == 0 || OP == 2) {
                __half* C = (__half*)Cout;
                if (r0 < M)
                    *(__half2*)(C + (size_t)r0 * Nn + c0) =
                        __halves2half2(__float2half_rn(v[0]), __float2half_rn(v[1]));
                if (r1 < M)
                    *(__half2*)(C + (size_t)r1 * Nn + c0) =
                        __halves2half2(__float2half_rn(v[2]), __float2half_rn(v[3]));
            } else if (OP == 3) {
                float* C = (float*)Cout;
                float g0 = gate ? gate[c0] : 1.f;
                float g1 = gate ? gate[c0 + 1] : 1.f;
                if (r0 < M) {
                    const float* rr = resid + (size_t)r0 * Nn;
                    float* cw = C + (size_t)r0 * Nn;
                    cw[c0] = rr[c0] + g0 * v[0];
                    cw[c0 + 1] = rr[c0 + 1] + g1 * v[1];
                }
                if (r1 < M) {
                    const float* rr = resid + (size_t)r1 * Nn;
                    float* cw = C + (size_t)r1 * Nn;
                    cw[c0] = rr[c0] + g0 * v[2];
                    cw[c0 + 1] = rr[c0 + 1] + g1 * v[3];
                }
            } else if (OP == 4) {  // temporal scatter + half copy
                float* C = (float*)Cout;
                float g0 = gate[c0], g1 = gate[c0 + 1];
#pragma unroll
                for (int hf = 0; hf < 2; hf++) {
                    int r = hf ? r1 : r0;
                    int rem = r & 4095;
                    int s = rem >> 4, tt = rem & 15;
                    size_t xr = ((size_t)(r >> 12) * 4096 + tt * 256 + s) * Nn;
                    float nv0 = C[xr + c0] + g0 * v[hf * 2];
                    float nv1 = C[xr + c0 + 1] + g1 * v[hf * 2 + 1];
                    C[xr + c0] = nv0;
                    C[xr + c0 + 1] = nv1;
                    *(__half2*)(xcopy + xr + c0) =
                        __halves2half2(__float2half_rn(nv0), __float2half_rn(nv1));
                }
            } else {  // OP == 5: X = resid + gate*v ; xt[perm] = half(X + tpe)
                float* C = (float*)Cout;
                float g0 = gate[c0], g1 = gate[c0 + 1];
#pragma unroll
                for (int hf = 0; hf < 2; hf++) {
                    int r = hf ? r1 : r0;
                    const float* rr = resid + (size_t)r * Nn;
                    float nv0 = rr[c0] + g0 * v[hf * 2];
                    float nv1 = rr[c0 + 1] + g1 * v[hf * 2 + 1];
                    float* cw = C + (size_t)r * Nn;
                    cw[c0] = nv0;
                    cw[c0 + 1] = nv1;
                    int rem = r & 4095;
                    int tt = rem >> 8, s = rem & 255;
                    size_t xtr = (((size_t)(r >> 12) * 256 + s) * 16 + tt) * Nn;
                    float tp0 = aux[(size_t)tt * Nn + c0];
                    float tp1 = aux[(size_t)tt * Nn + c0 + 1];
                    *(__half2*)(xcopy + xtr + c0) =
                        __halves2half2(__float2half_rn(nv0 + tp0), __float2half_rn(nv1 + tp1));
                }
            }
        }
    }
}

// ================= fp16 attention scores (K = 72, one-shot smem) =================
#define SSTR 88

template <int DOSM>
__global__ __launch_bounds__(256) void k_scores_h(const __half* __restrict__ Q,
                                                  const __half* __restrict__ Kd,
                                                  __half* __restrict__ out,
                                                  int heads, int Sq, int Sk,
                                                  int qRS, int kRS, long qBS, long kBS,
                                                  float scale) {
    __shared__ __half As[128 * SSTR];
    __shared__ __half Bs[128 * SSTR];
    __shared__ float red[128][4];

    const int tid = threadIdx.x;
    int z = blockIdx.z;
    int b = z / heads, h = z - b * heads;
    const __half* qb = Q + (long)b * qBS + h * CHD;
    const __half* kb = Kd + (long)b * kBS + h * CHD;
    const int i0 = blockIdx.y * 128, j0 = blockIdx.x * 128;
    const int wid = tid >> 5, lane = tid & 31;
    const int wr = wid >> 2, wc = wid & 3;
    const int warp_m = wr * 64, warp_n = wc * 32;
    const int qr = lane >> 2, qc = lane & 3;

    for (int idx = tid; idx < 128 * 11; idx += 256) {
        int m = idx / 11, c = idx - m * 11;
        int sz = (c < 9) ? 16 : 0;
        int gq = i0 + m; if (gq >= Sq) gq = Sq - 1;
        int gk = j0 + m; if (gk >= Sk) gk = Sk - 1;
        cp_async16z(&As[m * SSTR + c * 8], qb + (long)gq * qRS + c * 8, sz);
        cp_async16z(&Bs[m * SSTR + c * 8], kb + (long)gk * kRS + c * 8, sz);
    }
    cp_commit();
    cp_wait<0>();
    __syncthreads();

    float acc[4][4][4];
#pragma unroll
    for (int mi = 0; mi < 4; mi++)
#pragma unroll
        for (int ni = 0; ni < 4; ni++)
#pragma unroll
            for (int c = 0; c < 4; c++) acc[mi][ni][c] = 0.f;

#pragma unroll
    for (int kk = 0; kk < 80; kk += 16) {
        uint32_t af[4][4], bf[4][2];
#pragma unroll
        for (int mi = 0; mi < 4; mi++) {
            const __half* base = &As[(warp_m + mi * 16 + qr) * SSTR + kk + 2 * qc];
            af[mi][0] = *(const uint32_t*)(base);
            af[mi][1] = *(const uint32_t*)(base + 8 * SSTR);
            af[mi][2] = *(const uint32_t*)(base + 8);
            af[mi][3] = *(const uint32_t*)(base + 8 * SSTR + 8);
        }
#pragma unroll
        for (int ni = 0; ni < 4; ni++) {
            const __half* bb = &Bs[(warp_n + ni * 8 + qr) * SSTR + kk + 2 * qc];
            bf[ni][0] = *(const uint32_t*)(bb);
            bf[ni][1] = *(const uint32_t*)(bb + 8);
        }
#pragma unroll
        for (int mi = 0; mi < 4; mi++)
#pragma unroll
            for (int ni = 0; ni < 4; ni++) MMA_F16B(acc[mi][ni], af[mi], bf[ni]);
    }

    __half* ob = out + (long)z * Sq * Sk;

    if (DOSM == 0) {
#pragma unroll
        for (int mi = 0; mi < 4; mi++) {
            int r0 = i0 + warp_m + mi * 16 + qr;
            int r1 = r0 + 8;
#pragma unroll
            for (int ni = 0; ni < 4; ni++) {
                int c0 = j0 + warp_n + ni * 8 + qc * 2;
                if (c0 < Sk) {
                    if (r0 < Sq)
                        *(__half2*)(ob + (long)r0 * Sk + c0) =
                            __halves2half2(__float2half_rn(acc[mi][ni][0] * scale),
                                           __float2half_rn(acc[mi][ni][1] * scale));
                    if (r1 < Sq)
                        *(__half2*)(ob + (long)r1 * Sk + c0) =
                            __halves2half2(__float2half_rn(acc[mi][ni][2] * scale),
                                           __float2half_rn(acc[mi][ni][3] * scale));
                }
            }
        }
        return;
    }

#pragma unroll
    for (int mi = 0; mi < 4; mi++)
#pragma unroll
        for (int ni = 0; ni < 4; ni++)
#pragma unroll
            for (int c = 0; c < 4; c++) acc[mi][ni][c] *= scale;

    float mrow[4][2], srow[4][2];
#pragma unroll
    for (int mi = 0; mi < 4; mi++)
#pragma unroll
        for (int hf = 0; hf < 2; hf++) {
            float m = -FLT_MAX;
#pragma unroll
            for (int ni = 0; ni < 4; ni++) {
                int c0 = warp_n + ni * 8 + qc * 2;
                if (c0 < Sk) m = fmaxf(m, acc[mi][ni][hf * 2]);
                if (c0 + 1 < Sk) m = fmaxf(m, acc[mi][ni][hf * 2 + 1]);
            }
            m = fmaxf(m, __shfl_xor_sync(0xffffffffu, m, 1));
            m = fmaxf(m, __shfl_xor_sync(0xffffffffu, m, 2));
            if (qc == 0) red[warp_m + mi * 16 + qr + hf * 8][wc] = m;
        }
    __syncthreads();
#pragma unroll
    for (int mi = 0; mi < 4; mi++)
#pragma unroll
        for (int hf = 0; hf < 2; hf++) {
            int rl = warp_m + mi * 16 + qr + hf * 8;
            mrow[mi][hf] = fmaxf(fmaxf(red[rl][0], red[rl][1]), fmaxf(red[rl][2], red[rl][3]));
        }
    __syncthreads();
#pragma unroll
    for (int mi = 0; mi < 4; mi++)
#pragma unroll
        for (int hf = 0; hf < 2; hf++) {
            float s = 0.f;
#pragma unroll
            for (int ni = 0; ni < 4; ni++) {
                int c0 = warp_n + ni * 8 + qc * 2;
                float e0 = (c0 < Sk) ? expf(acc[mi][ni][hf * 2] - mrow[mi][hf]) : 0.f;
                float e1 = (c0 + 1 < Sk) ? expf(acc[mi][ni][hf * 2 + 1] - mrow[mi][hf]) : 0.f;
                acc[mi][ni][hf * 2] = e0;
                acc[mi][ni][hf * 2 + 1] = e1;
                s += e0 + e1;
            }
            s += __shfl_xor_sync(0xffffffffu, s, 1);
            s += __shfl_xor_sync(0xffffffffu, s, 2);
            if (qc == 0) red[warp_m + mi * 16 + qr + hf * 8][wc] = s;
        }
    __syncthreads();
#pragma unroll
    for (int mi = 0; mi < 4; mi++)
#pragma unroll
        for (int hf = 0; hf < 2; hf++) {
            int rl = warp_m + mi * 16 + qr + hf * 8;
            srow[mi][hf] = 1.f / (red[rl][0] + red[rl][1] + red[rl][2] + red[rl][3]);
        }
#pragma unroll
    for (int mi = 0; mi < 4; mi++) {
        int r0 = i0 + warp_m + mi * 16 + qr;
        int r1 = r0 + 8;
#pragma unroll
        for (int ni = 0; ni < 4; ni++) {
            int c0 = warp_n + ni * 8 + qc * 2;
            if (c0 < Sk) {
                *(__half2*)(ob + (long)r0 * Sk + c0) =
                    __halves2half2(__float2half_rn(acc[mi][ni][0] * srow[mi][0]),
                                   __float2half_rn(acc[mi][ni][1] * srow[mi][0]));
                *(__half2*)(ob + (long)r1 * Sk + c0) =
                    __halves2half2(__float2half_rn(acc[mi][ni][2] * srow[mi][1]),
                                   __float2half_rn(acc[mi][ni][3] * srow[mi][1]));
            }
        }
    }
}

// ================= spatial scores + fused softmax (Sq tile 128, Sk = 256) =======
#define SMSM (128 * SSTR * 2 + 256 * SSTR * 2)   // 67584 bytes

__global__ __launch_bounds__(256) void k_scores_sm(const __half* __restrict__ Q,
                                                   const __half* __restrict__ Kd,
                                                   __half* __restrict__ out,
                                                   int heads, float scale) {
    extern __shared__ __half ssm[];
    __half* As = ssm;
    __half* Bs = ssm + 128 * SSTR;
    __shared__ float red[128][4];

    const int tid = threadIdx.x;
    int z = blockIdx.z;
    int b = z / heads, h = z - b * heads;
    const __half* qb = Q + (long)b * (CS * 3L * CC) + h * CHD;
    const __half* kb = Kd + (long)b * (CS * 3L * CC) + h * CHD;
    const int i0 = blockIdx.y * 128;
    const int wid = tid >> 5, lane = tid & 31;
    const int wr = wid & 1, wc = wid >> 1;
    const int warp_m = wr * 64, warp_n = wc * 64;
    const int qr = lane >> 2, qc = lane & 3;

    for (int idx = tid; idx < 128 * 11; idx += 256) {
        int m = idx / 11, c = idx - m * 11;
        int sz = (c < 9) ? 16 : 0;
        cp_async16z(&As[m * SSTR + c * 8], qb + (long)(i0 + m) * (3 * CC) + c * 8, sz);
    }
    for (int idx = tid; idx < 256 * 11; idx += 256) {
        int m = idx / 11, c = idx - m * 11;
        int sz = (c < 9) ? 16 : 0;
        cp_async16z(&Bs[m * SSTR + c * 8], kb + (long)m * (3 * CC) + c * 8, sz);
    }
    cp_commit();
    cp_wait<0>();
    __syncthreads();

    float acc[4][8][4];
#pragma unroll
    for (int mi = 0; mi < 4; mi++)
#pragma unroll
        for (int ni = 0; ni < 8; ni++)
#pragma unroll
            for (int c = 0; c < 4; c++) acc[mi][ni][c] = 0.f;

#pragma unroll
    for (int kk = 0; kk < 80; kk += 16) {
        uint32_t af[4][4], bf[8][2];
#pragma unroll
        for (int mi = 0; mi < 4; mi++) {
            const __half* base = &As[(warp_m + mi * 16 + qr) * SSTR + kk + 2 * qc];
            af[mi][0] = *(const uint32_t*)(base);
            af[mi][1] = *(const uint32_t*)(base + 8 * SSTR);
            af[mi][2] = *(const uint32_t*)(base + 8);
            af[mi][3] = *(const uint32_t*)(base + 8 * SSTR + 8);
        }
#pragma unroll
        for (int ni = 0; ni < 8; ni++) {
            const __half* bb = &Bs[(warp_n + ni * 8 + qr) * SSTR + kk + 2 * qc];
            bf[ni][0] = *(const uint32_t*)(bb);
            bf[ni][1] = *(const uint32_t*)(bb + 8);
        }
#pragma unroll
        for (int mi = 0; mi < 4; mi++)
#pragma unroll
            for (int ni = 0; ni < 8; ni++) MMA_F16B(acc[mi][ni], af[mi], bf[ni]);
    }

#pragma unroll
    for (int mi = 0; mi < 4; mi++)
#pragma unroll
        for (int ni = 0; ni < 8; ni++)
#pragma unroll
            for (int c = 0; c < 4; c++) acc[mi][ni][c] *= scale;

    float mrow[4][2], srow[4][2];
#pragma unroll
    for (int mi = 0; mi < 4; mi++)
#pragma unroll
        for (int hf = 0; hf < 2; hf++) {
            float m = -FLT_MAX;
#pragma unroll
            for (int ni = 0; ni < 8; ni++) {
                m = fmaxf(m, acc[mi][ni][hf * 2]);
                m = fmaxf(m, acc[mi][ni][hf * 2 + 1]);
            }
            m = fmaxf(m, __shfl_xor_sync(0xffffffffu, m, 1));
            m = fmaxf(m, __shfl_xor_sync(0xffffffffu, m, 2));
            if (qc == 0) red[warp_m + mi * 16 + qr + hf * 8][wc] = m;
        }
    __syncthreads();
#pragma unroll
    for (int mi = 0; mi < 4; mi++)
#pragma unroll
        for (int hf = 0; hf < 2; hf++) {
            int rl = warp_m + mi * 16 + qr + hf * 8;
            mrow[mi][hf] = fmaxf(fmaxf(red[rl][0], red[rl][1]), fmaxf(red[rl][2], red[rl][3]));
        }
    __syncthreads();
#pragma unroll
    for (int mi = 0; mi < 4; mi++)
#pragma unroll
        for (int hf = 0; hf < 2; hf++) {
            float s = 0.f;
#pragma unroll
            for (int ni = 0; ni < 8; ni++) {
                float e0 = expf(acc[mi][ni][hf * 2] - mrow[mi][hf]);
                float e1 = expf(acc[mi][ni][hf * 2 + 1] - mrow[mi][hf]);
                acc[mi][ni][hf * 2] = e0;
                acc[mi][ni][hf * 2 + 1] = e1;
                s += e0 + e1;
            }
            s += __shfl_xor_sync(0xffffffffu, s, 1);
            s += __shfl_xor_sync(0xffffffffu, s, 2);
            if (qc == 0) red[warp_m + mi * 16 + qr + hf * 8][wc] = s;
        }
    __syncthreads();
#pragma unroll
    for (int mi = 0; mi < 4; mi++)
#pragma unroll
        for (int hf = 0; hf < 2; hf++) {
            int rl = warp_m + mi * 16 + qr + hf * 8;
            srow[mi][hf] = 1.f / (red[rl][0] + red[rl][1] + red[rl][2] + red[rl][3]);
        }

    __half* ob = out + (long)z * CS * CS;
#pragma unroll
    for (int mi = 0; mi < 4; mi++) {
        int r0 = i0 + warp_m + mi * 16 + qr;
        int r1 = r0 + 8;
#pragma unroll
        for (int ni = 0; ni < 8; ni++) {
            int c0 = warp_n + ni * 8 + qc * 2;
            *(__half2*)(ob + (long)r0 * CS + c0) =
                __halves2half2(__float2half_rn(acc[mi][ni][0] * srow[mi][0]),
                               __float2half_rn(acc[mi][ni][1] * srow[mi][0]));
            *(__half2*)(ob + (long)r1 * CS + c0) =
                __halves2half2(__float2half_rn(acc[mi][ni][2] * srow[mi][1]),
                               __float2half_rn(acc[mi][ni][3] * srow[mi][1]));
        }
    }
}

// ================= fp16 attn@V (32-key K-chunks) =================
#define PSTR 40
__global__ __launch_bounds__(256) void k_av_h(const __half* __restrict__ P,
                                              const __half* __restrict__ V,
                                              __half* __restrict__ O,
                                              int heads, int Sq, int Sk,
                                              int vRS, long vBS, int oRS, long oBS) {
    __shared__ __half As[2][128 * PSTR];
    __shared__ __half Vs[2][72 * PSTR];

    const int tid = threadIdx.x;
    int z = blockIdx.y;
    int b = z / heads, h = z - b * heads;
    const __half* Pb = P + (long)z * Sq * Sk;
    const __half* Vb = V + (long)b * vBS + h * CHD;
    __half* Ob = O + (long)b * oBS + h * CHD;
    const int i0 = blockIdx.x * 128;
    const int wid = tid >> 5, lane = tid & 31;
    const int warp_m = wid * 16;
    const int qr = lane >> 2, qc = lane & 3;

    float acc[9][4];
#pragma unroll
    for (int nt = 0; nt < 9; nt++)
#pragma unroll
        for (int c = 0; c < 4; c++) acc[nt][c] = 0.f;

    auto load_tile = [&](int stg, int kb) {
        // P: 128 rows x 32 keys (4 chunks of 8 halves per row)
#pragma unroll
        for (int i = 0; i < 2; i++) {
            int idx = tid + i * 256;
            int m = idx >> 2;
            int c = idx & 3;
            int sz = (kb + c * 8 + 8 <= Sk) ? 16 : 0;
            int gi = i0 + m; if (gi >= Sq) gi = Sq - 1;
            cp_async16z(&As[stg][m * PSTR + c * 8], Pb + (long)gi * Sk + kb + c * 8, sz);
        }
        // V transposed: 32 keys x 36 half2 -> Vs[d][key]
        for (int idx = tid; idx < 1152; idx += 256) {
            int key = idx / 36, d2 = idx - key * 36;
            __half2 v = (kb + key < Sk)
                            ? *(const __half2*)(Vb + (long)(kb + key) * vRS + 2 * d2)
                            : __halves2half2(__float2half_rn(0.f), __float2half_rn(0.f));
            Vs[stg][(2 * d2) * PSTR + key] = __low2half(v);
            Vs[stg][(2 * d2 + 1) * PSTR + key] = __high2half(v);
        }
    };

    const int KT = (Sk + 31) >> 5;
    load_tile(0, 0);
    cp_commit();

    for (int kt = 0; kt < KT; ++kt) {
        int cur = kt & 1;
        if (kt + 1 < KT) {
            load_tile(1 - cur, (kt + 1) << 5);
            cp_commit();
            cp_wait<1>();
        } else {
            cp_wait<0>();
        }
        __syncthreads();

#pragma unroll
        for (int hk = 0; hk < 2; hk++) {
            uint32_t af[4];
            const __half* abase = &As[cur][(warp_m + qr) * PSTR + hk * 16 + 2 * qc];
            af[0] = *(const uint32_t*)(abase);
            af[1] = *(const uint32_t*)(abase + 8 * PSTR);
            af[2] = *(const uint32_t*)(abase + 8);
            af[3] = *(const uint32_t*)(abase + 8 * PSTR + 8);
#pragma unroll
            for (int nt = 0; nt < 9; nt++) {
                uint32_t bf[2];
                const __half* bb = &Vs[cur][(nt * 8 + qr) * PSTR + hk * 16 + 2 * qc];
                bf[0] = *(const uint32_t*)(bb);
                bf[1] = *(const uint32_t*)(bb + 8);
                MMA_F16B(acc[nt], af, bf);
            }
        }
        __syncthreads();
    }

    int r0 = i0 + warp_m + qr;
    int r1 = r0 + 8;
#pragma unroll
    for (int nt = 0; nt < 9; nt++) {
        int c0 = nt * 8 + qc * 2;
        if (r0 < Sq)
            *(__half2*)(Ob + (long)r0 * oRS + c0) =
                __halves2half2(__float2half_rn(acc[nt][0]), __float2half_rn(acc[nt][1]));
        if (r1 < Sq)
            *(__half2*)(Ob + (long)r1 * oRS + c0) =
                __halves2half2(__float2half_rn(acc[nt][2]), __float2half_rn(acc[nt][3]));
    }
}

// ---------------- fused temporal attention (T=16, causal; half in/out) -------
__global__ __launch_bounds__(128) void k_attn_t(const __half* __restrict__ qkv,
                                                __half* __restrict__ O, float scale) {
    __shared__ float q[16][72], k[16][72], v[16][72], p[16][17];
    int h = blockIdx.x;
    int bs = blockIdx.y;
    const __half* base = qkv + (size_t)bs * CT * 3 * CC + h * CHD;
    int tid = threadIdx.x;

    for (int idx = tid; idx < 16 * 72; idx += 128) {
        int t = idx / 72, d = idx - t * 72;
        const __half* row = base + (size_t)t * 3 * CC;
        q[t][d] = __half2float(row[d]);
        k[t][d] = __half2float(row[CC + d]);
        v[t][d] = __half2float(row[2 * CC + d]);
    }
    __syncthreads();

    for (int e = tid; e < 256; e += 128) {
        int i = e >> 4, j = e & 15;
        float acc = 0.f;
#pragma unroll 8
        for (int d = 0; d < 72; d++) acc += q[i][d] * k[j][d];
        p[i][j] = acc * scale;
    }
    __syncthreads();

    if (tid < 16) {
        int i = tid;
        float m = -FLT_MAX;
        for (int j = 0; j <= i; j++) m = fmaxf(m, p[i][j]);
        float s = 0.f;
        for (int j = 0; j <= i; j++) { float e = expf(p[i][j] - m); p[i][j] = e; s += e; }
        float inv = 1.f / s;
        for (int j = 0; j <= i; j++) p[i][j] *= inv;
        for (int j = i + 1; j < 16; j++) p[i][j] = 0.f;
    }
    __syncthreads();

    for (int e = tid; e < 16 * 72; e += 128) {
        int t = e / 72, d = e - t * 72;
        float acc = 0.f;
#pragma unroll
        for (int j = 0; j < 16; j++) acc += p[t][j] * v[j][d];
        O[((size_t)bs * CT + t) * CC + h * CHD + d] = __float2half_rn(acc);
    }
}

// =======================================================================
extern "C" void kernel_launch(void* const* d_in, const int* in_sizes, int n_in,
                              void* d_out, int out_size) {
    const float* x      = (const float*)d_in[0];
    const float* y      = (const float*)d_in[1];
    const float* t      = (const float*)d_in[2];
    const float* tpe    = (const float*)d_in[3];
    const float* sst    = (const float*)d_in[4];
    const float* qkv_s_w = (const float*)d_in[5];
    const float* qkv_s_b = (const float*)d_in[6];
    const float* proj_s_w = (const float*)d_in[7];
    const float* proj_s_b = (const float*)d_in[8];
    const float* qkv_t_w = (const float*)d_in[9];
    const float* qkv_t_b = (const float*)d_in[10];
    const float* proj_t_w = (const float*)d_in[11];
    const float* proj_t_b = (const float*)d_in[12];
    const float* q_c_w  = (const float*)d_in[13];
    const float* q_c_b  = (const float*)d_in[14];
    const float* kv_c_w = (const float*)d_in[15];
    const float* kv_c_b = (const float*)d_in[16];
    const float* proj_c_w = (const float*)d_in[17];
    const float* proj_c_b = (const float*)d_in[18];
    const float* fc1_w  = (const float*)d_in[19];
    const float* fc1_b  = (const float*)d_in[20];
    const float* fc2_w  = (const float*)d_in[21];
    const float* fc2_b  = (const float*)d_in[22];
    float* X = (float*)d_out;

    float *p_t6, *p_xm, *p_qkv, *p_att, *p_h, *p_sc, *p_kv, *p_w, *p_yr;
    cudaGetSymbolAddress((void**)&p_t6, g_t6);
    cudaGetSymbolAddress((void**)&p_xm, g_xm);
    cudaGetSymbolAddress((void**)&p_qkv, g_qkv);
    cudaGetSymbolAddress((void**)&p_att, g_att);
    cudaGetSymbolAddress((void**)&p_h, g_h);
    cudaGetSymbolAddress((void**)&p_sc, g_sc);
    cudaGetSymbolAddress((void**)&p_kv, g_kv);
    cudaGetSymbolAddress((void**)&p_w, g_w);
    cudaGetSymbolAddress((void**)&p_yr, g_yr);

    // half-typed aliases
    __half* h_xm  = (__half*)p_xm;
    __half* h_qkv = (__half*)p_qkv;
    __half* h_att = (__half*)p_att;
    __half* h_h   = (__half*)p_h;
    __half* h_sc  = (__half*)p_sc;
    __half* h_kv  = (__half*)p_kv;
    __half* h_w   = (__half*)p_w;
    __half* h_yr  = (__half*)p_yr;

    const float scale = 0.11785113019775793f;  // 1/sqrt(72)

    static int attr_set = 0;
    if (!attr_set) {
        cudaFuncSetAttribute((const void*)k_hgemm<0>, cudaFuncAttributeMaxDynamicSharedMemorySize, HSMEM);
        cudaFuncSetAttribute((const void*)k_hgemm<2>, cudaFuncAttributeMaxDynamicSharedMemorySize, HSMEM);
        cudaFuncSetAttribute((const void*)k_hgemm<3>, cudaFuncAttributeMaxDynamicSharedMemorySize, HSMEM);
        cudaFuncSetAttribute((const void*)k_hgemm<4>, cudaFuncAttributeMaxDynamicSharedMemorySize, HSMEM);
        cudaFuncSetAttribute((const void*)k_hgemm<5>, cudaFuncAttributeMaxDynamicSharedMemorySize, HSMEM);
        cudaFuncSetAttribute((const void*)k_scores_sm, cudaFuncAttributeMaxDynamicSharedMemorySize, SMSM);
        attr_set = 1;
    }

    // half weight copies
    __half* w_qkv_s = h_w + (size_t)0 * CC2;
    __half* w_proj_s = h_w + (size_t)3 * CC2;
    __half* w_qkv_t = h_w + (size_t)4 * CC2;
    __half* w_proj_t = h_w + (size_t)7 * CC2;
    __half* w_q_c   = h_w + (size_t)8 * CC2;
    __half* w_kv_c  = h_w + (size_t)9 * CC2;
    __half* w_proj_c = h_w + (size_t)11 * CC2;
    __half* w_fc1   = h_w + (size_t)12 * CC2;
    __half* w_fc2   = h_w + (size_t)16 * CC2;

    auto rnd = [&](const float* src, __half* dst, size_t n) {
        k_round_h<<<(int)((n + 255) / 256), 256>>>(src, dst, (int)n);
    };
    rnd(qkv_s_w, w_qkv_s, (size_t)3 * CC2);
    rnd(proj_s_w, w_proj_s, CC2);
    rnd(qkv_t_w, w_qkv_t, (size_t)3 * CC2);
    rnd(proj_t_w, w_proj_t, CC2);
    rnd(q_c_w, w_q_c, CC2);
    rnd(kv_c_w, w_kv_c, (size_t)2 * CC2);
    rnd(proj_c_w, w_proj_c, CC2);
    rnd(fc1_w, w_fc1, (size_t)4 * CC2);
    rnd(fc2_w, w_fc2, (size_t)4 * CC2);
    rnd(y, h_yr, (size_t)CB * CYL * CC);

    k_mod<<<(CB * 6 * CC + 255) / 256, 256>>>(t, sst, p_t6);

#define HG(OP, A, W, B, C, R, gi, XC, AUX, M, Nn, K) \
    k_hgemm<OP><<<dim3((Nn) / 128, ((M) + 255) / 256), 512, HSMEM>>>(A, W, B, C, R, p_t6, gi, XC, AUX, M, Nn, K)

    // ---- spatial attention (fp16, softmax fused; xt_build fused into proj_s) ----
    k_ln_mod<<<NROW, 288>>>(x, p_t6, h_xm, 0, 1);
    HG(0, h_xm, w_qkv_s, qkv_s_b, h_qkv, nullptr, 0, (__half*)nullptr, (const float*)nullptr,
       NROW, 3 * CC, CC);
    k_scores_sm<<<dim3(1, 2, CB * CT * CNH), 256, SMSM>>>(h_qkv, h_qkv + CC, h_sc, CNH, scale);
    k_av_h<<<dim3(2, CB * CT * CNH), 256>>>(h_sc, h_qkv + 2 * CC, h_att, CNH, CS, CS,
                                            3 * CC, (long)CS * 3 * CC, CC, (long)CS * CC);
    // X = x + gate_msa*proj; h_xm[perm] = half(X + tpe)
    HG(5, h_att, w_proj_s, proj_s_b, X, x, 2, h_xm, tpe, NROW, CC, CC);

    // ---- temporal attention (causal, fused; scatter fused into proj_t) ----
    HG(0, h_xm, w_qkv_t, qkv_t_b, h_qkv, nullptr, 0, (__half*)nullptr, (const float*)nullptr,
       NROW, 3 * CC, CC);
    k_attn_t<<<dim3(CNH, CB * CS), 128>>>(h_qkv, h_att, scale);
    HG(4, h_att, w_proj_t, proj_t_b, X, nullptr, 2, h_h, (const float*)nullptr,
       NROW, CC, CC);  // X[perm] += g*proj; h_h copy

    // ---- cross attention (fp16, fused softmax) ----
    HG(0, h_h, w_q_c, q_c_b, h_qkv, nullptr, 0, (__half*)nullptr, (const float*)nullptr,
       NROW, CC, CC);
    HG(0, h_yr, w_kv_c, kv_c_b, h_kv, nullptr, 0, (__half*)nullptr, (const float*)nullptr,
       CB * CYL, 2 * CC, CC);
    k_scores_h<1><<<dim3(1, CN / 128, CB * CNH), 256>>>(h_qkv, h_kv, h_sc, CNH, CN, CYL,
                                                        CC, 2 * CC,
                                                        (long)CN * CC, (long)CYL * 2 * CC, scale);
    k_av_h<<<dim3(CN / 128, CB * CNH), 256>>>(h_sc, h_kv + CC, h_att, CNH, CN, CYL,
                                              2 * CC, (long)CYL * 2 * CC, CC, (long)CN * CC);
    HG(3, h_att, w_proj_c, proj_c_b, X, X, -1, (__half*)nullptr, (const float*)nullptr,
       NROW, CC, CC);  // X += proj

    // ---- MLP ----
    k_ln_mod<<<NROW, 288>>>(X, p_t6, h_xm, 3, 4);
    HG(2, h_xm, w_fc1, fc1_b, h_h, nullptr, 0, (__half*)nullptr, (const float*)nullptr,
       NROW, 4 * CC, CC);
    HG(3, h_h, w_fc2, fc2_b, X, X, 5, (__half*)nullptr, (const float*)nullptr,
       NROW, CC, 4 * CC);  // X += g*fc2
}